// round 11
// baseline (speedup 1.0000x reference)
#include <cuda_runtime.h>
#include <cstdint>
#include <stdint.h>
#include <math.h>

#define BQ 8
#define SQ 2048
#define HQ 512
#define LQ 8
#define MQ 32
#define KBQ 256

// ---------------- scratch (device globals, allocation-free) ----------------
__device__ float  g_h [BQ*SQ*HQ];           // hidden state [B,S,H]
__device__ float  g_y [BQ*SQ*HQ];           // GEMM scratch
__device__ float2 g_tab[MQ*SQ];             // (cos, sin) of 2*pi*m*s/S
__device__ float  g_Xc[128*BQ*HQ];          // fwd DFT out [128 rows][B*H cols]; rows 0-31 Xr, 32-63 Xi
__device__ float  g_Yr[BQ*MQ*HQ];
__device__ float  g_Yi[BQ*MQ*HQ];
__device__ float  g_o2[BQ*SQ*(HQ/4)];
__device__ float  g_gf[BQ*HQ];
__device__ float  g_k1[BQ*HQ];
__device__ float  g_mred[16*BQ*HQ];         // mean partials

// bf16 hi/lo packed operands (2 bf16 per word)
#define WTOT (LQ*HQ*HQ + (HQ/2)*HQ + (HQ/4)*(HQ/2))
__device__ unsigned int g_A0[BQ*SQ*HQ/2];   // h pairs along H (conv/op1 GEMM A)
__device__ unsigned int g_A1[BQ*SQ*HQ/2];
__device__ unsigned int g_W0[WTOT/2];
__device__ unsigned int g_W1[WTOT/2];
__device__ unsigned int g_o10[BQ*SQ*(HQ/2)/2];
__device__ unsigned int g_o11[BQ*SQ*(HQ/2)/2];
__device__ unsigned int g_T0[128*SQ/2];     // fwd twiddle matrix bf16 hi/lo, 128 rows x 1024 words
__device__ unsigned int g_T1[128*SQ/2];
__device__ unsigned int g_hT0[BQ*HQ*SQ/2];  // h^T[(b*H+c), s] pairs along s
__device__ unsigned int g_hT1[BQ*HQ*SQ/2];

__device__ __forceinline__ float gelu_exact(float x) {
    return 0.5f * x * (1.0f + erff(x * 0.70710678118654752440f));
}

// ---------------- bf16 helpers ----------------
__device__ __forceinline__ unsigned int bfpack(float x0, float x1) {
    unsigned int rr;
    asm("cvt.rn.bf16x2.f32 %0, %1, %2;" : "=r"(rr) : "f"(x1), "f"(x0));
    return rr;
}

__device__ __forceinline__ void bfsplit2(float x0, float x1,
                                         unsigned int& whi, unsigned int& wlo) {
    unsigned int hic = bfpack(x0, x1);
    float res0 = x0 - __uint_as_float(hic << 16);
    float res1 = x1 - __uint_as_float(hic & 0xffff0000u);
    whi = hic;
    wlo = bfpack(res0, res1);
}

__device__ __forceinline__ void ldsm4(unsigned int& ra, unsigned int& rb,
                                      unsigned int& rc, unsigned int& rd,
                                      unsigned int addr) {
    asm volatile("ldmatrix.sync.aligned.m8n8.x4.shared.b16 {%0,%1,%2,%3}, [%4];"
                 : "=r"(ra), "=r"(rb), "=r"(rc), "=r"(rd) : "r"(addr));
}

__device__ __forceinline__ void mma_bf16(float* dacc, const unsigned int* amat,
                                         const unsigned int* bmat) {
    asm volatile(
        "mma.sync.aligned.m16n8k16.row.col.f32.bf16.bf16.f32 "
        "{%0,%1,%2,%3}, {%4,%5,%6,%7}, {%8,%9}, {%0,%1,%2,%3};"
        : "+f"(dacc[0]), "+f"(dacc[1]), "+f"(dacc[2]), "+f"(dacc[3])
        : "r"(amat[0]), "r"(amat[1]), "r"(amat[2]), "r"(amat[3]),
          "r"(bmat[0]), "r"(bmat[1]));
}

#define CPASYNC16(dstaddr, srcptr) \
    asm volatile("cp.async.cg.shared.global [%0], [%1], 16;" \
                 :: "r"(dstaddr), "l"(srcptr))
#define CPCOMMIT() asm volatile("cp.async.commit_group;")
#define CPWAIT(nn) asm volatile("cp.async.wait_group %0;" :: "n"(nn))

// ---------------- fwd twiddle matrix T (bf16 split, pairs along s) ----------------
// rows 0-31: cos(2*pi*m*s/S) ; rows 32-63: -sin ; rows 64-127: zero pad
__global__ void k_tabT() {
    int i = blockIdx.x * 256 + threadIdx.x;      // (row, s-pair)
    if (i < 128 * SQ / 2) {
        int sp  = i & (SQ / 2 - 1);
        int row = i >> 10;
        float v0 = 0.f, v1 = 0.f;
        if (row < 32) {
            float a0 = (float)(row * (2 * sp))     * (1.0f / 1024.0f);
            float a1 = (float)(row * (2 * sp + 1)) * (1.0f / 1024.0f);
            v0 = cospif(a0); v1 = cospif(a1);
        } else if (row < 64) {
            int m = row - 32;
            float a0 = (float)(m * (2 * sp))     * (1.0f / 1024.0f);
            float a1 = (float)(m * (2 * sp + 1)) * (1.0f / 1024.0f);
            v0 = -sinpif(a0); v1 = -sinpif(a1);
        }
        bfsplit2(v0, v1, g_T0[i], g_T1[i]);
    }
}

// ---------------- inverse twiddle tables (float, for idftln) ----------------
__global__ void k_tab() {
    int i = blockIdx.x * blockDim.x + threadIdx.x;
    if (i < MQ * SQ) {
        int m = i / SQ, s = i % SQ;
        float a = (float)(m * s) * (1.0f / 1024.0f);
        g_tab[i] = make_float2(cospif(a), sinpif(a));
    }
}

// ---------------- h^T init: pairs along s ----------------
__global__ void k_initT(const float* __restrict__ x, const float* __restrict__ in_w,
                        const float* __restrict__ in_b) {
    int i = blockIdx.x * 256 + threadIdx.x;      // word = ((b*H + c), s-pair)
    if (i < BQ * HQ * SQ / 2) {
        int sp = i & (SQ / 2 - 1);
        int bc = i >> 10;
        int c  = bc & (HQ - 1);
        int b  = bc >> 9;
        float wv = in_w[c], bv = in_b[c];
        float v0 = x[b * SQ + 2 * sp] * wv + bv;
        float v1 = x[b * SQ + 2 * sp + 1] * wv + bv;
        bfsplit2(v0, v1, g_hT0[i], g_hT1[i]);
    }
}

// ---------------- input projection (h + bf16 split along H) ----------------
__global__ void k_init(const float* __restrict__ x, const float* __restrict__ in_w,
                       const float* __restrict__ in_b) {
    int i = blockIdx.x * 256 + threadIdx.x;      // pair index along H
    if (i < BQ * SQ * HQ / 2) {
        int e0 = 2 * i;
        int c0 = e0 & (HQ - 1);
        int bs = e0 >> 9;
        float xv = x[bs];
        float v0 = xv * in_w[c0] + in_b[c0];
        float v1 = xv * in_w[c0 + 1] + in_b[c0 + 1];
        g_h[e0] = v0;
        g_h[e0 + 1] = v1;
        bfsplit2(v0, v1, g_A0[i], g_A1[i]);
    }
}

// ---------------- fp32 -> bf16 hi/lo split (weights) ----------------
__global__ void k_cvt(const float* __restrict__ src, unsigned int* __restrict__ dsthi,
                      unsigned int* __restrict__ dstlo, int npairs) {
    int i = blockIdx.x * 256 + threadIdx.x;
    if (i < npairs) {
        bfsplit2(src[2 * i], src[2 * i + 1], dsthi[i], dstlo[i]);
    }
}

// ---------------- per-mode complex GEMM ----------------
__global__ void k_spec(const float* __restrict__ Wr, const float* __restrict__ Wi) {
    int m = blockIdx.x, tid = threadIdx.x;
    __shared__ float sXr[BQ][HQ];
    __shared__ float sXi[BQ][HQ];
    for (int i = tid; i < BQ * HQ; i += 128) {
        int b = i >> 9, hh = i & 511;
        sXr[b][hh] = g_Xc[(size_t)m * (BQ * HQ) + i];
        sXi[b][hh] = g_Xc[(size_t)(32 + m) * (BQ * HQ) + i];
    }
    __syncthreads();
    int k = blockIdx.y * 128 + tid;
    float yr[BQ], yi[BQ];
#pragma unroll
    for (int b = 0; b < BQ; b++) { yr[b] = 0.f; yi[b] = 0.f; }
#pragma unroll 4
    for (int h = 0; h < HQ; h++) {
        float wr = Wr[(m * HQ + h) * HQ + k];
        float wi = Wi[(m * HQ + h) * HQ + k];
#pragma unroll
        for (int b = 0; b < BQ; b++) {
            float xr = sXr[b][h], xi = sXi[b][h];
            yr[b] = fmaf(xr, wr, fmaf(-xi, wi, yr[b]));
            yi[b] = fmaf(xr, wi, fmaf( xi, wr, yi[b]));
        }
    }
#pragma unroll
    for (int b = 0; b < BQ; b++) {
        g_Yr[(b * MQ + m) * HQ + k] = yr[b];
        g_Yi[(b * MQ + m) * HQ + k] = yi[b];
    }
}

// ===== fused inverse DFT + conv-bias + LayerNorm + residual + bf16 splits =====
// grid (SQ/64, BQ), block 512 (one thread per channel c)
__global__ void __launch_bounds__(512, 1)
k_idftln(const float* __restrict__ cb, const float* __restrict__ gg,
         const float* __restrict__ bb) {
    int b  = blockIdx.y;
    int s0 = blockIdx.x * 64;
    int tid = threadIdx.x;           // = channel c
    int lane = tid & 31, wrp = tid >> 5;

    float yr[MQ], yi[MQ];
#pragma unroll
    for (int m = 0; m < MQ; m++) {
        yr[m] = g_Yr[(b * MQ + m) * HQ + tid];
        yi[m] = g_Yi[(b * MQ + m) * HQ + tid];
    }
    __shared__ float2 tb[MQ * 64];
    __shared__ float red[32];
    for (int i = tid; i < MQ * 64; i += 512) {
        int m = i >> 6, ss = i & 63;
        tb[i] = g_tab[m * SQ + s0 + ss];
    }
    float gval = gg[tid], bval = bb[tid], cbv = cb[tid];
    float hvPrev = 0.f;
    __syncthreads();

    for (int ss = 0; ss < 64; ss++) {
        float acc = 0.f;
#pragma unroll
        for (int m = 1; m < MQ; m++) {
            float2 t = tb[m * 64 + ss];
            acc = fmaf(yr[m],  t.x, acc);
            acc = fmaf(-yi[m], t.y, acc);
        }
        float xfv = (yr[0] + 2.f * acc) * (1.0f / (float)SQ);
        size_t idx = (size_t)(b * SQ + s0 + ss) * HQ + tid;
        float tv = g_y[idx] + xfv + cbv;

        float s1 = tv, s2 = tv * tv;
#pragma unroll
        for (int o = 16; o; o >>= 1) {
            s1 += __shfl_xor_sync(0xffffffffu, s1, o);
            s2 += __shfl_xor_sync(0xffffffffu, s2, o);
        }
        if (lane == 0) { red[wrp] = s1; red[16 + wrp] = s2; }
        __syncthreads();
        float ts = 0.f, ts2 = 0.f;
#pragma unroll
        for (int q = 0; q < 16; q++) { ts += red[q]; ts2 += red[16 + q]; }
        float mu  = ts * (1.f / HQ);
        float var = ts2 * (1.f / HQ) - mu * mu;
        float rinv = rsqrtf(var + 1e-5f);

        float hv = (tv - mu) * rinv * gval + bval + g_h[idx];
        g_h[idx] = hv;
        // pairs along H for conv GEMM A operand
        float hOther = __shfl_xor_sync(0xffffffffu, hv, 1);
        if ((tid & 1) == 0) {
            unsigned int w0v, w1v;
            bfsplit2(hv, hOther, w0v, w1v);
            size_t widx = idx >> 1;
            g_A0[widx] = w0v;
            g_A1[widx] = w1v;
        }
        // pairs along s for fwd-DFT B operand (h^T)
        if (ss & 1) {
            unsigned int t0v, t1v;
            bfsplit2(hvPrev, hv, t0v, t1v);
            size_t tidx = ((size_t)(b * HQ + tid) << 10) + (size_t)((s0 + ss) >> 1);
            g_hT0[tidx] = t0v;
            g_hT1[tidx] = t1v;
        }
        hvPrev = hv;
        __syncthreads();
    }
}

// ============ 3xBF16 tensor-core GEMM (hi/lo compensated) — R9-proven ============
#define STG_WORDS 12288

__device__ __forceinline__ void issue_slab(
    unsigned int smemBase, int stageSel,
    const unsigned int* __restrict__ Amat0, const unsigned int* __restrict__ Amat1,
    const unsigned int* __restrict__ Bmat0, const unsigned int* __restrict__ Bmat1,
    int rowBase, int colBase, int Kw, int kw, int tid)
{
#pragma unroll
    for (int it = 0; it < 4; it++) {
        int idx = tid + it * 256;
        int row = idx >> 3, chk = idx & 7;
        unsigned int woff = (unsigned int)(stageSel * STG_WORDS + row * 32 +
                                           ((chk ^ (row & 7)) << 2));
        size_t gsrc = (size_t)(rowBase + row) * Kw + kw + chk * 4;
        CPASYNC16(smemBase + woff * 4, Amat0 + gsrc);
        CPASYNC16(smemBase + (woff + 4096) * 4, Amat1 + gsrc);
    }
#pragma unroll
    for (int it = 0; it < 2; it++) {
        int idx = tid + it * 256;
        int row = idx >> 3, chk = idx & 7;
        unsigned int woff = (unsigned int)(stageSel * STG_WORDS + 8192 + row * 32 +
                                           ((chk ^ (row & 7)) << 2));
        size_t gsrc = (size_t)(colBase + row) * Kw + kw + chk * 4;
        CPASYNC16(smemBase + woff * 4, Bmat0 + gsrc);
        CPASYNC16(smemBase + (woff + 2048) * 4, Bmat1 + gsrc);
    }
}

__global__ void __launch_bounds__(256, 2)
k_gemm_tc2(const unsigned int* __restrict__ Amat0, const unsigned int* __restrict__ Amat1,
           const unsigned int* __restrict__ Bmat0, const unsigned int* __restrict__ Bmat1,
           float* __restrict__ Cmat, int Mdim, int Ndim, int Kdim,
           const float* __restrict__ biasPtr, int gmode,
           unsigned int* __restrict__ Cout0, unsigned int* __restrict__ Cout1) {
    extern __shared__ unsigned int shMem[];
    const int tid  = threadIdx.x;
    const int lane = tid & 31;
    const int warpIdx = tid >> 5;
    const int wmoff = (warpIdx & 3) * 32;
    const int wnoff = (warpIdx >> 2) * 32;
    const int rowBase = blockIdx.x * 128;
    const int colBase = blockIdx.y * 64;
    const int Kw = Kdim >> 1;

    const unsigned int smemBase = (unsigned int)__cvta_generic_to_shared(shMem);

    const int arowA = wmoff + (lane & 15);
    const int achA  = lane >> 4;
    const int browB = wnoff + ((lane >> 4) << 3) + (lane & 7);
    const int bchB  = (lane >> 3) & 1;

    float acc[2][4][4];
#pragma unroll
    for (int fi = 0; fi < 2; fi++)
#pragma unroll
        for (int ji = 0; ji < 4; ji++)
#pragma unroll
            for (int ci = 0; ci < 4; ci++) acc[fi][ji][ci] = 0.0f;

    const int nSlab = Kw >> 5;
    issue_slab(smemBase, 0, Amat0, Amat1, Bmat0, Bmat1, rowBase, colBase, Kw, 0, tid);
    CPCOMMIT();

    for (int is = 0; is < nSlab; is++) {
        const int stagec = is & 1;
        if (is + 1 < nSlab) {
            issue_slab(smemBase, (is + 1) & 1, Amat0, Amat1, Bmat0, Bmat1,
                       rowBase, colBase, Kw, (is + 1) << 5, tid);
            CPCOMMIT();
            CPWAIT(1);
        } else {
            CPWAIT(0);
        }
        __syncthreads();

        const unsigned int stW = (unsigned int)(stagec * STG_WORDS);
#pragma unroll
        for (int gi = 0; gi < 4; gi++) {
            unsigned int fragA0[2][4];
            unsigned int fragA1[2][4];
            unsigned int fragB0[4][2];
            unsigned int fragB1[4][2];
#pragma unroll
            for (int fi = 0; fi < 2; fi++) {
                int rr = arowA + fi * 16;
                int chq = 2 * gi + achA;
                unsigned int byoff = (stW + rr * 32 + ((chq ^ (rr & 7)) << 2)) << 2;
                ldsm4(fragA0[fi][0], fragA0[fi][1], fragA0[fi][2], fragA0[fi][3],
                      smemBase + byoff);
                ldsm4(fragA1[fi][0], fragA1[fi][1], fragA1[fi][2], fragA1[fi][3],
                      smemBase + byoff + 4096 * 4);
            }
#pragma unroll
            for (int pj = 0; pj < 2; pj++) {
                int rr = browB + pj * 16;
                int chq = 2 * gi + bchB;
                unsigned int byoff = (stW + 8192 + rr * 32 + ((chq ^ (rr & 7)) << 2)) << 2;
                unsigned int tqa[4];
                ldsm4(tqa[0], tqa[1], tqa[2], tqa[3], smemBase + byoff);
                fragB0[2 * pj + 0][0] = tqa[0];
                fragB0[2 * pj + 0][1] = tqa[1];
                fragB0[2 * pj + 1][0] = tqa[2];
                fragB0[2 * pj + 1][1] = tqa[3];
                unsigned int tqb[4];
                ldsm4(tqb[0], tqb[1], tqb[2], tqb[3], smemBase + byoff + 2048 * 4);
                fragB1[2 * pj + 0][0] = tqb[0];
                fragB1[2 * pj + 0][1] = tqb[1];
                fragB1[2 * pj + 1][0] = tqb[2];
                fragB1[2 * pj + 1][1] = tqb[3];
            }
#pragma unroll
            for (int fi = 0; fi < 2; fi++) {
#pragma unroll
                for (int ji = 0; ji < 4; ji++) {
                    mma_bf16(acc[fi][ji], fragA0[fi], fragB0[ji]);
                    mma_bf16(acc[fi][ji], fragA1[fi], fragB0[ji]);
                    mma_bf16(acc[fi][ji], fragA0[fi], fragB1[ji]);
                }
            }
        }
        __syncthreads();
    }

    const int Ndw = Ndim >> 1;
#pragma unroll
    for (int fi = 0; fi < 2; fi++) {
#pragma unroll
        for (int ji = 0; ji < 4; ji++) {
            int orow = rowBase + wmoff + fi * 16 + (lane >> 2);
            int ocol = colBase + wnoff + ji * 8 + (lane & 3) * 2;
            float outA = acc[fi][ji][0];
            float outB = acc[fi][ji][1];
            float outC = acc[fi][ji][2];
            float outD = acc[fi][ji][3];
            if (gmode != 0) {
                float biasLo = biasPtr[ocol];
                float biasHi = biasPtr[ocol + 1];
                outA = gelu_exact(outA + biasLo);
                outB = gelu_exact(outB + biasHi);
                outC = gelu_exact(outC + biasLo);
                outD = gelu_exact(outD + biasHi);
            }
            if (gmode == 3) {
                size_t widx0 = (size_t)orow * Ndw + (ocol >> 1);
                size_t widx1 = (size_t)(orow + 8) * Ndw + (ocol >> 1);
                bfsplit2(outA, outB, Cout0[widx0], Cout1[widx0]);
                bfsplit2(outC, outD, Cout0[widx1], Cout1[widx1]);
            } else {
                *(float2*)&Cmat[(size_t)orow * Ndim + ocol] = make_float2(outA, outB);
                *(float2*)&Cmat[(size_t)(orow + 8) * Ndim + ocol] = make_float2(outC, outD);
            }
        }
    }
}

// ---------------- final projection to scalar ----------------
__global__ void k_op3(const float* __restrict__ w, const float* __restrict__ b3,
                      float* __restrict__ out) {
    int tid = threadIdx.x;
    int row = blockIdx.x * 4 + (tid >> 5);
    int lane = tid & 31;
    float s = 0.f;
#pragma unroll
    for (int i = 0; i < 4; i++) {
        int j = lane + i * 32;
        s += g_o2[(size_t)row * 128 + j] * w[j];
    }
#pragma unroll
    for (int o = 16; o; o >>= 1) s += __shfl_xor_sync(0xffffffffu, s, o);
    if (lane == 0) out[row] = s + b3[0];
}

// ---------------- mean over s (two-stage) ----------------
__global__ void k_mean1() {
    int part = blockIdx.y;
    int b = blockIdx.x >> 2;
    int c = (blockIdx.x & 3) * 128 + threadIdx.x;
    float s = 0.f;
    int sbeg = part * (SQ / 16);
    for (int ss = sbeg; ss < sbeg + (SQ / 16); ss++)
        s += g_h[(size_t)(b * SQ + ss) * HQ + c];
    g_mred[part * (BQ * HQ) + b * HQ + c] = s;
}

__global__ void k_mean2() {
    int i = blockIdx.x * 256 + threadIdx.x;
    if (i < BQ * HQ) {
        float s = 0.f;
#pragma unroll
        for (int part = 0; part < 16; part++) s += g_mred[part * (BQ * HQ) + i];
        g_gf[i] = s * (1.f / SQ);
    }
}

// ---------------- head: k1 = gelu(gf @ h1_w^T + h1_b) ----------------
__global__ void k_head1(const float* __restrict__ w, const float* __restrict__ bias) {
    int b = blockIdx.x, tid = threadIdx.x;
    int j = blockIdx.y * 128 + tid;
    __shared__ float sg[HQ];
    for (int i = tid; i < HQ; i += 128) sg[i] = g_gf[b * HQ + i];
    __syncthreads();
    const float4* w4 = (const float4*)(w + (size_t)j * HQ);
    float acc = 0.f;
    for (int c = 0; c < HQ / 4; c++) {
        float4 wv = w4[c];
        float4 gv = *(const float4*)&sg[c * 4];
        acc = fmaf(wv.x, gv.x, acc); acc = fmaf(wv.y, gv.y, acc);
        acc = fmaf(wv.z, gv.z, acc); acc = fmaf(wv.w, gv.w, acc);
    }
    g_k1[b * HQ + j] = gelu_exact(acc + bias[j]);
}

// ---------------- head: key_pred = sigmoid(k1 @ h2_w^T + h2_b) ----------------
__global__ void k_head2(const float* __restrict__ w, const float* __restrict__ bias,
                        float* __restrict__ out) {
    int b = blockIdx.x, tid = threadIdx.x;
    int j = blockIdx.y * 128 + tid;
    __shared__ float sk[HQ];
    for (int i = tid; i < HQ; i += 128) sk[i] = g_k1[b * HQ + i];
    __syncthreads();
    const float4* w4 = (const float4*)(w + (size_t)j * HQ);
    float acc = 0.f;
    for (int c = 0; c < HQ / 4; c++) {
        float4 wv = w4[c];
        float4 kv = *(const float4*)&sk[c * 4];
        acc = fmaf(wv.x, kv.x, acc); acc = fmaf(wv.y, kv.y, acc);
        acc = fmaf(wv.z, kv.z, acc); acc = fmaf(wv.w, kv.w, acc);
    }
    float t = acc + bias[j];
    out[BQ * SQ + b * KBQ + j] = 1.f / (1.f + expf(-t));
}

// ---------------- launch ----------------
extern "C" void kernel_launch(void* const* d_in, const int* in_sizes, int n_in,
                              void* d_out, int out_size) {
    const float* x      = (const float*)d_in[0];
    const float* in_w   = (const float*)d_in[1];
    const float* in_b   = (const float*)d_in[2];
    const float* fw_r   = (const float*)d_in[3];
    const float* fw_i   = (const float*)d_in[4];
    const float* conv_w = (const float*)d_in[5];
    const float* conv_b = (const float*)d_in[6];
    const float* ln_g   = (const float*)d_in[7];
    const float* ln_b   = (const float*)d_in[8];
    const float* op1_w  = (const float*)d_in[9];
    const float* op1_b  = (const float*)d_in[10];
    const float* op2_w  = (const float*)d_in[11];
    const float* op2_b  = (const float*)d_in[12];
    const float* op3_w  = (const float*)d_in[13];
    const float* op3_b  = (const float*)d_in[14];
    const float* h1_w   = (const float*)d_in[15];
    const float* h1_b   = (const float*)d_in[16];
    const float* h2_w   = (const float*)d_in[17];
    const float* h2_b   = (const float*)d_in[18];
    float* out = (float*)d_out;

    float *yp, *o2p, *xcp;
    unsigned int *a0p, *a1p, *w0p, *w1p, *o10p, *o11p, *t0p, *t1p, *ht0p, *ht1p;
    cudaGetSymbolAddress((void**)&yp,  g_y);
    cudaGetSymbolAddress((void**)&o2p, g_o2);
    cudaGetSymbolAddress((void**)&xcp, g_Xc);
    cudaGetSymbolAddress((void**)&a0p, g_A0);
    cudaGetSymbolAddress((void**)&a1p, g_A1);
    cudaGetSymbolAddress((void**)&w0p, g_W0);
    cudaGetSymbolAddress((void**)&w1p, g_W1);
    cudaGetSymbolAddress((void**)&o10p, g_o10);
    cudaGetSymbolAddress((void**)&o11p, g_o11);
    cudaGetSymbolAddress((void**)&t0p, g_T0);
    cudaGetSymbolAddress((void**)&t1p, g_T1);
    cudaGetSymbolAddress((void**)&ht0p, g_hT0);
    cudaGetSymbolAddress((void**)&ht1p, g_hT1);

    static int smemSet = 0;
    if (!smemSet) {
        cudaFuncSetAttribute(k_gemm_tc2, cudaFuncAttributeMaxDynamicSharedMemorySize,
                             2 * STG_WORDS * 4);
        smemSet = 1;
    }
    const int dynSmem = 2 * STG_WORDS * 4;

    const int convWPairs = LQ * HQ * HQ / 2;
    const int op1WOff    = convWPairs;
    const int op1WPairs  = (HQ / 2) * HQ / 2;
    const int op2WOff    = convWPairs + op1WPairs;
    const int op2WPairs  = (HQ / 4) * (HQ / 2) / 2;
    const int hPairs     = BQ * SQ * HQ / 2;
    const int htWords    = BQ * HQ * SQ / 2;

    // launch #4 = fwd DFT GEMM (ncu capture slot): C[128, B*H] = T @ hT^T
    k_tabT<<<(128 * SQ / 2 + 255) / 256, 256>>>();
    k_initT<<<(htWords + 255) / 256, 256>>>(x, in_w, in_b);
    k_tab<<<(MQ * SQ + 255) / 256, 256>>>();
    k_gemm_tc2<<<dim3(1, BQ * HQ / 64), 256, dynSmem>>>(
        t0p, t1p, ht0p, ht1p, xcp, 128, BQ * HQ, SQ,
        (const float*)0, 0, (unsigned int*)0, (unsigned int*)0);
    k_init<<<(hPairs + 255) / 256, 256>>>(x, in_w, in_b);
    k_cvt<<<(convWPairs + 255) / 256, 256>>>(conv_w, w0p, w1p, convWPairs);
    k_cvt<<<(op1WPairs + 255) / 256, 256>>>(op1_w, w0p + op1WOff, w1p + op1WOff, op1WPairs);
    k_cvt<<<(op2WPairs + 255) / 256, 256>>>(op2_w, w0p + op2WOff, w1p + op2WOff, op2WPairs);
    k_spec<<<dim3(MQ, HQ / 128), 128>>>(fw_r, fw_i);
    k_gemm_tc2<<<dim3(BQ * SQ / 128, HQ / 64), 256, dynSmem>>>(
        a0p, a1p, w0p, w1p, yp, BQ * SQ, HQ, HQ,
        (const float*)0, 0, (unsigned int*)0, (unsigned int*)0);
    k_idftln<<<dim3(SQ / 64, BQ), 512>>>(conv_b, ln_g, ln_b);

    for (int l = 1; l < LQ; l++) {
        k_gemm_tc2<<<dim3(1, BQ * HQ / 64), 256, dynSmem>>>(
            t0p, t1p, ht0p, ht1p, xcp, 128, BQ * HQ, SQ,
            (const float*)0, 0, (unsigned int*)0, (unsigned int*)0);
        k_spec<<<dim3(MQ, HQ / 128), 128>>>(fw_r + (size_t)l * MQ * HQ * HQ,
                                            fw_i + (size_t)l * MQ * HQ * HQ);
        k_gemm_tc2<<<dim3(BQ * SQ / 128, HQ / 64), 256, dynSmem>>>(
            a0p, a1p, w0p + (size_t)l * HQ * HQ / 2, w1p + (size_t)l * HQ * HQ / 2,
            yp, BQ * SQ, HQ, HQ, (const float*)0, 0,
            (unsigned int*)0, (unsigned int*)0);
        k_idftln<<<dim3(SQ / 64, BQ), 512>>>(conv_b + l * HQ, ln_g + l * HQ, ln_b + l * HQ);
    }

    // output projection: H -> H/2 -> H/4 -> 1
    k_gemm_tc2<<<dim3(BQ * SQ / 128, (HQ / 2) / 64), 256, dynSmem>>>(
        a0p, a1p, w0p + op1WOff, w1p + op1WOff, yp, BQ * SQ, HQ / 2, HQ,
        op1_b, 3, o10p, o11p);
    k_gemm_tc2<<<dim3(BQ * SQ / 128, (HQ / 4) / 64), 256, dynSmem>>>(
        o10p, o11p, w0p + op2WOff, w1p + op2WOff, o2p, BQ * SQ, HQ / 4, HQ / 2,
        op2_b, 1, (unsigned int*)0, (unsigned int*)0);
    k_op3<<<BQ * SQ / 4, 128>>>(op3_w, op3_b, out);

    // cryptanalytic head
    k_mean1<<<dim3(BQ * 4, 16), 128>>>();
    k_mean2<<<(BQ * HQ + 255) / 256, 256>>>();
    k_head1<<<dim3(BQ, HQ / 128), 128>>>(h1_w, h1_b);
    k_head2<<<dim3(BQ, KBQ / 128), 128>>>(h2_w, h2_b, out);
}

// round 12
// speedup vs baseline: 1.3437x; 1.3437x over previous
#include <cuda_runtime.h>
#include <cstdint>
#include <stdint.h>
#include <math.h>

#define BQ 8
#define SQ 2048
#define HQ 512
#define LQ 8
#define MQ 32
#define KBQ 256

// ---------------- scratch (device globals, allocation-free) ----------------
__device__ float  g_h [BQ*SQ*HQ];           // hidden state [B,S,H]
__device__ float  g_y [BQ*SQ*HQ];           // conv GEMM out
__device__ float  g_xfC[SQ*BQ*HQ];          // inv DFT out [s][(b*H+c)]
__device__ float  g_Xc[128*BQ*HQ];          // fwd DFT out [128 rows][B*H cols]
__device__ float  g_Yr[BQ*MQ*HQ];
__device__ float  g_Yi[BQ*MQ*HQ];
__device__ float  g_o2[BQ*SQ*(HQ/4)];
__device__ float  g_gf[BQ*HQ];
__device__ float  g_k1[BQ*HQ];
__device__ float  g_mred[16*BQ*HQ];

// bf16 hi/lo packed operands (2 bf16 per word)
#define WTOT (LQ*HQ*HQ + (HQ/2)*HQ + (HQ/4)*(HQ/2))
__device__ unsigned int g_A0[BQ*SQ*HQ/2];   // h pairs along H
__device__ unsigned int g_A1[BQ*SQ*HQ/2];
__device__ unsigned int g_W0[WTOT/2];
__device__ unsigned int g_W1[WTOT/2];
__device__ unsigned int g_o10[BQ*SQ*(HQ/2)/2];
__device__ unsigned int g_o11[BQ*SQ*(HQ/2)/2];
__device__ unsigned int g_T0[128*SQ/2];     // fwd twiddle [128 rows][1024 words]
__device__ unsigned int g_T1[128*SQ/2];
__device__ unsigned int g_Ti0[SQ*32];       // inv twiddle [2048 rows][32 words]
__device__ unsigned int g_Ti1[SQ*32];
__device__ unsigned int g_hT0[BQ*HQ*SQ/2];  // h^T[(b*H+c)][s-pairs]
__device__ unsigned int g_hT1[BQ*HQ*SQ/2];
__device__ unsigned int g_Ys0[BQ*HQ*32];    // Y stacked [(b*H+c)][32 words = 64 k]
__device__ unsigned int g_Ys1[BQ*HQ*32];

__device__ __forceinline__ float gelu_exact(float x) {
    return 0.5f * x * (1.0f + erff(x * 0.70710678118654752440f));
}

// ---------------- bf16 helpers ----------------
__device__ __forceinline__ unsigned int bfpack(float x0, float x1) {
    unsigned int rr;
    asm("cvt.rn.bf16x2.f32 %0, %1, %2;" : "=r"(rr) : "f"(x1), "f"(x0));
    return rr;
}

__device__ __forceinline__ void bfsplit2(float x0, float x1,
                                         unsigned int& whi, unsigned int& wlo) {
    unsigned int hic = bfpack(x0, x1);
    float res0 = x0 - __uint_as_float(hic << 16);
    float res1 = x1 - __uint_as_float(hic & 0xffff0000u);
    whi = hic;
    wlo = bfpack(res0, res1);
}

__device__ __forceinline__ void ldsm4(unsigned int& ra, unsigned int& rb,
                                      unsigned int& rc, unsigned int& rd,
                                      unsigned int addr) {
    asm volatile("ldmatrix.sync.aligned.m8n8.x4.shared.b16 {%0,%1,%2,%3}, [%4];"
                 : "=r"(ra), "=r"(rb), "=r"(rc), "=r"(rd) : "r"(addr));
}

__device__ __forceinline__ void mma_bf16(float* dacc, const unsigned int* amat,
                                         const unsigned int* bmat) {
    asm volatile(
        "mma.sync.aligned.m16n8k16.row.col.f32.bf16.bf16.f32 "
        "{%0,%1,%2,%3}, {%4,%5,%6,%7}, {%8,%9}, {%0,%1,%2,%3};"
        : "+f"(dacc[0]), "+f"(dacc[1]), "+f"(dacc[2]), "+f"(dacc[3])
        : "r"(amat[0]), "r"(amat[1]), "r"(amat[2]), "r"(amat[3]),
          "r"(bmat[0]), "r"(bmat[1]));
}

#define CPASYNC16(dstaddr, srcptr) \
    asm volatile("cp.async.cg.shared.global [%0], [%1], 16;" \
                 :: "r"(dstaddr), "l"(srcptr))
#define CPCOMMIT() asm volatile("cp.async.commit_group;")
#define CPWAIT(nn) asm volatile("cp.async.wait_group %0;" :: "n"(nn))

// ---------------- fwd twiddle matrix T ----------------
// rows 0-31: cos(2*pi*m*s/S) ; rows 32-63: -sin ; rows 64-127: zero
__global__ void k_tabT() {
    int i = blockIdx.x * 256 + threadIdx.x;
    if (i < 128 * SQ / 2) {
        int sp  = i & (SQ / 2 - 1);
        int row = i >> 10;
        float v0 = 0.f, v1 = 0.f;
        if (row < 32) {
            float a0 = (float)(row * (2 * sp))     * (1.0f / 1024.0f);
            float a1 = (float)(row * (2 * sp + 1)) * (1.0f / 1024.0f);
            v0 = cospif(a0); v1 = cospif(a1);
        } else if (row < 64) {
            int m = row - 32;
            float a0 = (float)(m * (2 * sp))     * (1.0f / 1024.0f);
            float a1 = (float)(m * (2 * sp + 1)) * (1.0f / 1024.0f);
            v0 = -sinpif(a0); v1 = -sinpif(a1);
        }
        bfsplit2(v0, v1, g_T0[i], g_T1[i]);
    }
}

// ---------------- inverse twiddle matrix Tinv [s][64 k] ----------------
// k<32: m=k, coef c_m*cos ; k>=32: m=k-32, -c_m*sin ; c_0=1/S, c_m=2/S
__global__ void k_tabI() {
    int i = blockIdx.x * 256 + threadIdx.x;
    if (i < SQ * 32) {
        int kw = i & 31;
        int s  = i >> 5;
        int k0 = 2 * kw, k1 = 2 * kw + 1;
        float v0, v1;
        if (k0 < 32) {
            float c0 = (k0 == 0 ? 1.0f : 2.0f) / (float)SQ;
            float c1 = 2.0f / (float)SQ;
            v0 = c0 * cospif((float)(k0 * s) * (1.0f / 1024.0f));
            v1 = c1 * cospif((float)(k1 * s) * (1.0f / 1024.0f));
        } else {
            int m0 = k0 - 32, m1 = k1 - 32;
            float c0 = (m0 == 0 ? 1.0f : 2.0f) / (float)SQ;
            float c1 = 2.0f / (float)SQ;
            v0 = -c0 * sinpif((float)(m0 * s) * (1.0f / 1024.0f));
            v1 = -c1 * sinpif((float)(m1 * s) * (1.0f / 1024.0f));
        }
        bfsplit2(v0, v1, g_Ti0[i], g_Ti1[i]);
    }
}

// ---------------- h^T init ----------------
__global__ void k_initT(const float* __restrict__ x, const float* __restrict__ in_w,
                        const float* __restrict__ in_b) {
    int i = blockIdx.x * 256 + threadIdx.x;
    if (i < BQ * HQ * SQ / 2) {
        int sp = i & (SQ / 2 - 1);
        int bc = i >> 10;
        int c  = bc & (HQ - 1);
        int b  = bc >> 9;
        float wv = in_w[c], bv = in_b[c];
        float v0 = x[b * SQ + 2 * sp] * wv + bv;
        float v1 = x[b * SQ + 2 * sp + 1] * wv + bv;
        bfsplit2(v0, v1, g_hT0[i], g_hT1[i]);
    }
}

// ---------------- input projection ----------------
__global__ void k_init(const float* __restrict__ x, const float* __restrict__ in_w,
                       const float* __restrict__ in_b) {
    int i = blockIdx.x * 256 + threadIdx.x;
    if (i < BQ * SQ * HQ / 2) {
        int e0 = 2 * i;
        int c0 = e0 & (HQ - 1);
        int bs = e0 >> 9;
        float xv = x[bs];
        float v0 = xv * in_w[c0] + in_b[c0];
        float v1 = xv * in_w[c0 + 1] + in_b[c0 + 1];
        g_h[e0] = v0;
        g_h[e0 + 1] = v1;
        bfsplit2(v0, v1, g_A0[i], g_A1[i]);
    }
}

// ---------------- fp32 -> bf16 hi/lo (weights) ----------------
__global__ void k_cvt(const float* __restrict__ src, unsigned int* __restrict__ dsthi,
                      unsigned int* __restrict__ dstlo, int npairs) {
    int i = blockIdx.x * 256 + threadIdx.x;
    if (i < npairs) {
        bfsplit2(src[2 * i], src[2 * i + 1], dsthi[i], dstlo[i]);
    }
}

// ---------------- per-mode complex GEMM ----------------
__global__ void k_spec(const float* __restrict__ Wr, const float* __restrict__ Wi) {
    int m = blockIdx.x, tid = threadIdx.x;
    __shared__ float sXr[BQ][HQ];
    __shared__ float sXi[BQ][HQ];
    for (int i = tid; i < BQ * HQ; i += 128) {
        int b = i >> 9, hh = i & 511;
        sXr[b][hh] = g_Xc[(size_t)m * (BQ * HQ) + i];
        sXi[b][hh] = g_Xc[(size_t)(32 + m) * (BQ * HQ) + i];
    }
    __syncthreads();
    int k = blockIdx.y * 128 + tid;
    float yr[BQ], yi[BQ];
#pragma unroll
    for (int b = 0; b < BQ; b++) { yr[b] = 0.f; yi[b] = 0.f; }
#pragma unroll 4
    for (int h = 0; h < HQ; h++) {
        float wr = Wr[(m * HQ + h) * HQ + k];
        float wi = Wi[(m * HQ + h) * HQ + k];
#pragma unroll
        for (int b = 0; b < BQ; b++) {
            float xr = sXr[b][h], xi = sXi[b][h];
            yr[b] = fmaf(xr, wr, fmaf(-xi, wi, yr[b]));
            yi[b] = fmaf(xr, wi, fmaf( xi, wr, yi[b]));
        }
    }
#pragma unroll
    for (int b = 0; b < BQ; b++) {
        g_Yr[(b * MQ + m) * HQ + k] = yr[b];
        g_Yi[(b * MQ + m) * HQ + k] = yi[b];
    }
}

// ---------------- pack Yr/Yi -> bf16 K-major Ystack ----------------
__global__ void k_packY() {
    int i = blockIdx.x * 256 + threadIdx.x;
    if (i < BQ * HQ * 32) {
        int kw = i & 31;
        int bc = i >> 5;
        int c  = bc & (HQ - 1);
        int b  = bc >> 9;
        int k0 = 2 * kw, k1 = 2 * kw + 1;
        float v0 = (k0 < 32) ? g_Yr[(b * MQ + k0) * HQ + c]
                             : g_Yi[(b * MQ + k0 - 32) * HQ + c];
        float v1 = (k1 < 32) ? g_Yr[(b * MQ + k1) * HQ + c]
                             : g_Yi[(b * MQ + k1 - 32) * HQ + c];
        bfsplit2(v0, v1, g_Ys0[i], g_Ys1[i]);
    }
}

// ---------------- LN row kernel: y + xf + cb ; LN ; +h residual ; bf16 pairs ----------------
// grid BQ*SQ blocks, 128 threads (4 consecutive c each)
__global__ void k_lnrow(const float* __restrict__ cb, const float* __restrict__ gg,
                        const float* __restrict__ bb) {
    int row = blockIdx.x, tid = threadIdx.x;
    int b = row >> 11, s = row & (SQ - 1);
    int j0 = tid * 4;
    float v[4], s1 = 0.f, s2 = 0.f;
#pragma unroll
    for (int i = 0; i < 4; i++) {
        int j = j0 + i;
        float t = g_y[(size_t)row * HQ + j] +
                  g_xfC[(size_t)s * (BQ * HQ) + b * HQ + j] + cb[j];
        v[i] = t; s1 += t; s2 += t * t;
    }
#pragma unroll
    for (int o = 16; o; o >>= 1) {
        s1 += __shfl_xor_sync(0xffffffffu, s1, o);
        s2 += __shfl_xor_sync(0xffffffffu, s2, o);
    }
    __shared__ float red[64];
    int w = tid >> 5;
    if ((tid & 31) == 0) { red[w] = s1; red[32 + w] = s2; }
    __syncthreads();
    float ts  = red[0] + red[1] + red[2] + red[3];
    float ts2 = red[32] + red[33] + red[34] + red[35];
    float mu  = ts * (1.f / HQ);
    float var = ts2 * (1.f / HQ) - mu * mu;
    float rinv = rsqrtf(var + 1e-5f);
    float hv[4];
#pragma unroll
    for (int i = 0; i < 4; i++) {
        int j = j0 + i;
        size_t idx = (size_t)row * HQ + j;
        hv[i] = (v[i] - mu) * rinv * gg[j] + bb[j] + g_h[idx];
        g_h[idx] = hv[i];
    }
    size_t wbase = (size_t)row * (HQ / 2) + tid * 2;
    bfsplit2(hv[0], hv[1], g_A0[wbase], g_A1[wbase]);
    bfsplit2(hv[2], hv[3], g_A0[wbase + 1], g_A1[wbase + 1]);
}

// ---------------- h -> hT transpose (bf16 pairs along s) ----------------
// grid (SQ/64, HQ/32, BQ), 256 threads
__global__ void k_hTt() {
    __shared__ float tile[64][33];
    int s0 = blockIdx.x * 64;
    int c0 = blockIdx.y * 32;
    int b  = blockIdx.z;
    int tid = threadIdx.x;
    for (int i = tid; i < 64 * 32; i += 256) {
        int si = i >> 5, ci = i & 31;
        tile[si][ci] = g_h[(size_t)(b * SQ + s0 + si) * HQ + c0 + ci];
    }
    __syncthreads();
    for (int i = tid; i < 32 * 32; i += 256) {
        int ci = i >> 5, spi = i & 31;
        unsigned int w0v, w1v;
        bfsplit2(tile[2 * spi][ci], tile[2 * spi + 1][ci], w0v, w1v);
        size_t o = ((size_t)(b * HQ + c0 + ci) << 10) + (size_t)(s0 >> 1) + spi;
        g_hT0[o] = w0v;
        g_hT1[o] = w1v;
    }
}

// ============ 3xBF16 tensor-core GEMM (hi/lo compensated) ============
#define STG_WORDS 12288

__device__ __forceinline__ void issue_slab(
    unsigned int smemBase, int stageSel,
    const unsigned int* __restrict__ Amat0, const unsigned int* __restrict__ Amat1,
    const unsigned int* __restrict__ Bmat0, const unsigned int* __restrict__ Bmat1,
    int rowBase, int colBase, int Kw, int kw, int tid)
{
#pragma unroll
    for (int it = 0; it < 4; it++) {
        int idx = tid + it * 256;
        int row = idx >> 3, chk = idx & 7;
        unsigned int woff = (unsigned int)(stageSel * STG_WORDS + row * 32 +
                                           ((chk ^ (row & 7)) << 2));
        size_t gsrc = (size_t)(rowBase + row) * Kw + kw + chk * 4;
        CPASYNC16(smemBase + woff * 4, Amat0 + gsrc);
        CPASYNC16(smemBase + (woff + 4096) * 4, Amat1 + gsrc);
    }
#pragma unroll
    for (int it = 0; it < 2; it++) {
        int idx = tid + it * 256;
        int row = idx >> 3, chk = idx & 7;
        unsigned int woff = (unsigned int)(stageSel * STG_WORDS + 8192 + row * 32 +
                                           ((chk ^ (row & 7)) << 2));
        size_t gsrc = (size_t)(colBase + row) * Kw + kw + chk * 4;
        CPASYNC16(smemBase + woff * 4, Bmat0 + gsrc);
        CPASYNC16(smemBase + (woff + 2048) * 4, Bmat1 + gsrc);
    }
}

__global__ void __launch_bounds__(256, 2)
k_gemm_tc2(const unsigned int* __restrict__ Amat0, const unsigned int* __restrict__ Amat1,
           const unsigned int* __restrict__ Bmat0, const unsigned int* __restrict__ Bmat1,
           float* __restrict__ Cmat, int Mdim, int Ndim, int Kdim,
           const float* __restrict__ biasPtr, int gmode,
           unsigned int* __restrict__ Cout0, unsigned int* __restrict__ Cout1) {
    extern __shared__ unsigned int shMem[];
    const int tid  = threadIdx.x;
    const int lane = tid & 31;
    const int warpIdx = tid >> 5;
    const int wmoff = (warpIdx & 3) * 32;
    const int wnoff = (warpIdx >> 2) * 32;
    const int rowBase = blockIdx.x * 128;
    const int colBase = blockIdx.y * 64;
    const int Kw = Kdim >> 1;

    const unsigned int smemBase = (unsigned int)__cvta_generic_to_shared(shMem);

    const int arowA = wmoff + (lane & 15);
    const int achA  = lane >> 4;
    const int browB = wnoff + ((lane >> 4) << 3) + (lane & 7);
    const int bchB  = (lane >> 3) & 1;

    float acc[2][4][4];
#pragma unroll
    for (int fi = 0; fi < 2; fi++)
#pragma unroll
        for (int ji = 0; ji < 4; ji++)
#pragma unroll
            for (int ci = 0; ci < 4; ci++) acc[fi][ji][ci] = 0.0f;

    const int nSlab = Kw >> 5;
    issue_slab(smemBase, 0, Amat0, Amat1, Bmat0, Bmat1, rowBase, colBase, Kw, 0, tid);
    CPCOMMIT();

    for (int is = 0; is < nSlab; is++) {
        const int stagec = is & 1;
        if (is + 1 < nSlab) {
            issue_slab(smemBase, (is + 1) & 1, Amat0, Amat1, Bmat0, Bmat1,
                       rowBase, colBase, Kw, (is + 1) << 5, tid);
            CPCOMMIT();
            CPWAIT(1);
        } else {
            CPWAIT(0);
        }
        __syncthreads();

        const unsigned int stW = (unsigned int)(stagec * STG_WORDS);
#pragma unroll
        for (int gi = 0; gi < 4; gi++) {
            unsigned int fragA0[2][4];
            unsigned int fragA1[2][4];
            unsigned int fragB0[4][2];
            unsigned int fragB1[4][2];
#pragma unroll
            for (int fi = 0; fi < 2; fi++) {
                int rr = arowA + fi * 16;
                int chq = 2 * gi + achA;
                unsigned int byoff = (stW + rr * 32 + ((chq ^ (rr & 7)) << 2)) << 2;
                ldsm4(fragA0[fi][0], fragA0[fi][1], fragA0[fi][2], fragA0[fi][3],
                      smemBase + byoff);
                ldsm4(fragA1[fi][0], fragA1[fi][1], fragA1[fi][2], fragA1[fi][3],
                      smemBase + byoff + 4096 * 4);
            }
#pragma unroll
            for (int pj = 0; pj < 2; pj++) {
                int rr = browB + pj * 16;
                int chq = 2 * gi + bchB;
                unsigned int byoff = (stW + 8192 + rr * 32 + ((chq ^ (rr & 7)) << 2)) << 2;
                unsigned int tqa[4];
                ldsm4(tqa[0], tqa[1], tqa[2], tqa[3], smemBase + byoff);
                fragB0[2 * pj + 0][0] = tqa[0];
                fragB0[2 * pj + 0][1] = tqa[1];
                fragB0[2 * pj + 1][0] = tqa[2];
                fragB0[2 * pj + 1][1] = tqa[3];
                unsigned int tqb[4];
                ldsm4(tqb[0], tqb[1], tqb[2], tqb[3], smemBase + byoff + 2048 * 4);
                fragB1[2 * pj + 0][0] = tqb[0];
                fragB1[2 * pj + 0][1] = tqb[1];
                fragB1[2 * pj + 1][0] = tqb[2];
                fragB1[2 * pj + 1][1] = tqb[3];
            }
#pragma unroll
            for (int fi = 0; fi < 2; fi++) {
#pragma unroll
                for (int ji = 0; ji < 4; ji++) {
                    mma_bf16(acc[fi][ji], fragA0[fi], fragB0[ji]);
                    mma_bf16(acc[fi][ji], fragA1[fi], fragB0[ji]);
                    mma_bf16(acc[fi][ji], fragA0[fi], fragB1[ji]);
                }
            }
        }
        __syncthreads();
    }

    const int Ndw = Ndim >> 1;
#pragma unroll
    for (int fi = 0; fi < 2; fi++) {
#pragma unroll
        for (int ji = 0; ji < 4; ji++) {
            int orow = rowBase + wmoff + fi * 16 + (lane >> 2);
            int ocol = colBase + wnoff + ji * 8 + (lane & 3) * 2;
            float outA = acc[fi][ji][0];
            float outB = acc[fi][ji][1];
            float outC = acc[fi][ji][2];
            float outD = acc[fi][ji][3];
            if (gmode != 0) {
                float biasLo = biasPtr[ocol];
                float biasHi = biasPtr[ocol + 1];
                outA = gelu_exact(outA + biasLo);
                outB = gelu_exact(outB + biasHi);
                outC = gelu_exact(outC + biasLo);
                outD = gelu_exact(outD + biasHi);
            }
            if (gmode == 3) {
                size_t widx0 = (size_t)orow * Ndw + (ocol >> 1);
                size_t widx1 = (size_t)(orow + 8) * Ndw + (ocol >> 1);
                bfsplit2(outA, outB, Cout0[widx0], Cout1[widx0]);
                bfsplit2(outC, outD, Cout0[widx1], Cout1[widx1]);
            } else {
                *(float2*)&Cmat[(size_t)orow * Ndim + ocol] = make_float2(outA, outB);
                *(float2*)&Cmat[(size_t)(orow + 8) * Ndim + ocol] = make_float2(outC, outD);
            }
        }
    }
}

// ---------------- final projection to scalar ----------------
__global__ void k_op3(const float* __restrict__ w, const float* __restrict__ b3,
                      float* __restrict__ out) {
    int tid = threadIdx.x;
    int row = blockIdx.x * 4 + (tid >> 5);
    int lane = tid & 31;
    float s = 0.f;
#pragma unroll
    for (int i = 0; i < 4; i++) {
        int j = lane + i * 32;
        s += g_o2[(size_t)row * 128 + j] * w[j];
    }
#pragma unroll
    for (int o = 16; o; o >>= 1) s += __shfl_xor_sync(0xffffffffu, s, o);
    if (lane == 0) out[row] = s + b3[0];
}

// ---------------- mean over s (two-stage) ----------------
__global__ void k_mean1() {
    int part = blockIdx.y;
    int b = blockIdx.x >> 2;
    int c = (blockIdx.x & 3) * 128 + threadIdx.x;
    float s = 0.f;
    int sbeg = part * (SQ / 16);
    for (int ss = sbeg; ss < sbeg + (SQ / 16); ss++)
        s += g_h[(size_t)(b * SQ + ss) * HQ + c];
    g_mred[part * (BQ * HQ) + b * HQ + c] = s;
}

__global__ void k_mean2() {
    int i = blockIdx.x * 256 + threadIdx.x;
    if (i < BQ * HQ) {
        float s = 0.f;
#pragma unroll
        for (int part = 0; part < 16; part++) s += g_mred[part * (BQ * HQ) + i];
        g_gf[i] = s * (1.f / SQ);
    }
}

// ---------------- head kernels ----------------
__global__ void k_head1(const float* __restrict__ w, const float* __restrict__ bias) {
    int b = blockIdx.x, tid = threadIdx.x;
    int j = blockIdx.y * 128 + tid;
    __shared__ float sg[HQ];
    for (int i = tid; i < HQ; i += 128) sg[i] = g_gf[b * HQ + i];
    __syncthreads();
    const float4* w4 = (const float4*)(w + (size_t)j * HQ);
    float acc = 0.f;
    for (int c = 0; c < HQ / 4; c++) {
        float4 wv = w4[c];
        float4 gv = *(const float4*)&sg[c * 4];
        acc = fmaf(wv.x, gv.x, acc); acc = fmaf(wv.y, gv.y, acc);
        acc = fmaf(wv.z, gv.z, acc); acc = fmaf(wv.w, gv.w, acc);
    }
    g_k1[b * HQ + j] = gelu_exact(acc + bias[j]);
}

__global__ void k_head2(const float* __restrict__ w, const float* __restrict__ bias,
                        float* __restrict__ out) {
    int b = blockIdx.x, tid = threadIdx.x;
    int j = blockIdx.y * 128 + tid;
    __shared__ float sk[HQ];
    for (int i = tid; i < HQ; i += 128) sk[i] = g_k1[b * HQ + i];
    __syncthreads();
    const float4* w4 = (const float4*)(w + (size_t)j * HQ);
    float acc = 0.f;
    for (int c = 0; c < HQ / 4; c++) {
        float4 wv = w4[c];
        float4 kv = *(const float4*)&sk[c * 4];
        acc = fmaf(wv.x, kv.x, acc); acc = fmaf(wv.y, kv.y, acc);
        acc = fmaf(wv.z, kv.z, acc); acc = fmaf(wv.w, kv.w, acc);
    }
    float t = acc + bias[j];
    out[BQ * SQ + b * KBQ + j] = 1.f / (1.f + expf(-t));
}

// ---------------- launch ----------------
extern "C" void kernel_launch(void* const* d_in, const int* in_sizes, int n_in,
                              void* d_out, int out_size) {
    const float* x      = (const float*)d_in[0];
    const float* in_w   = (const float*)d_in[1];
    const float* in_b   = (const float*)d_in[2];
    const float* fw_r   = (const float*)d_in[3];
    const float* fw_i   = (const float*)d_in[4];
    const float* conv_w = (const float*)d_in[5];
    const float* conv_b = (const float*)d_in[6];
    const float* ln_g   = (const float*)d_in[7];
    const float* ln_b   = (const float*)d_in[8];
    const float* op1_w  = (const float*)d_in[9];
    const float* op1_b  = (const float*)d_in[10];
    const float* op2_w  = (const float*)d_in[11];
    const float* op2_b  = (const float*)d_in[12];
    const float* op3_w  = (const float*)d_in[13];
    const float* op3_b  = (const float*)d_in[14];
    const float* h1_w   = (const float*)d_in[15];
    const float* h1_b   = (const float*)d_in[16];
    const float* h2_w   = (const float*)d_in[17];
    const float* h2_b   = (const float*)d_in[18];
    float* out = (float*)d_out;

    float *yp, *o2p, *xcp, *xfp;
    unsigned int *a0p, *a1p, *w0p, *w1p, *o10p, *o11p;
    unsigned int *t0p, *t1p, *ti0p, *ti1p, *ht0p, *ht1p, *ys0p, *ys1p;
    cudaGetSymbolAddress((void**)&yp,  g_y);
    cudaGetSymbolAddress((void**)&o2p, g_o2);
    cudaGetSymbolAddress((void**)&xcp, g_Xc);
    cudaGetSymbolAddress((void**)&xfp, g_xfC);
    cudaGetSymbolAddress((void**)&a0p, g_A0);
    cudaGetSymbolAddress((void**)&a1p, g_A1);
    cudaGetSymbolAddress((void**)&w0p, g_W0);
    cudaGetSymbolAddress((void**)&w1p, g_W1);
    cudaGetSymbolAddress((void**)&o10p, g_o10);
    cudaGetSymbolAddress((void**)&o11p, g_o11);
    cudaGetSymbolAddress((void**)&t0p, g_T0);
    cudaGetSymbolAddress((void**)&t1p, g_T1);
    cudaGetSymbolAddress((void**)&ti0p, g_Ti0);
    cudaGetSymbolAddress((void**)&ti1p, g_Ti1);
    cudaGetSymbolAddress((void**)&ht0p, g_hT0);
    cudaGetSymbolAddress((void**)&ht1p, g_hT1);
    cudaGetSymbolAddress((void**)&ys0p, g_Ys0);
    cudaGetSymbolAddress((void**)&ys1p, g_Ys1);

    static int smemSet = 0;
    if (!smemSet) {
        cudaFuncSetAttribute(k_gemm_tc2, cudaFuncAttributeMaxDynamicSharedMemorySize,
                             2 * STG_WORDS * 4);
        smemSet = 1;
    }
    const int dynSmem = 2 * STG_WORDS * 4;

    const int convWPairs = LQ * HQ * HQ / 2;
    const int op1WOff    = convWPairs;
    const int op1WPairs  = (HQ / 2) * HQ / 2;
    const int op2WOff    = convWPairs + op1WPairs;
    const int op2WPairs  = (HQ / 4) * (HQ / 2) / 2;
    const int hPairs     = BQ * SQ * HQ / 2;
    const int htWords    = BQ * HQ * SQ / 2;

    // prologue; launch #4 = k_spec layer 0 (ncu capture slot)
    k_tabT<<<(128 * SQ / 2 + 255) / 256, 256>>>();
    k_initT<<<(htWords + 255) / 256, 256>>>(x, in_w, in_b);
    k_gemm_tc2<<<dim3(1, BQ * HQ / 64), 256, dynSmem>>>(
        t0p, t1p, ht0p, ht1p, xcp, 128, BQ * HQ, SQ,
        (const float*)0, 0, (unsigned int*)0, (unsigned int*)0);
    k_spec<<<dim3(MQ, HQ / 128), 128>>>(fw_r, fw_i);
    k_tabI<<<(SQ * 32 + 255) / 256, 256>>>();
    k_init<<<(hPairs + 255) / 256, 256>>>(x, in_w, in_b);
    k_cvt<<<(convWPairs + 255) / 256, 256>>>(conv_w, w0p, w1p, convWPairs);
    k_cvt<<<(op1WPairs + 255) / 256, 256>>>(op1_w, w0p + op1WOff, w1p + op1WOff, op1WPairs);
    k_cvt<<<(op2WPairs + 255) / 256, 256>>>(op2_w, w0p + op2WOff, w1p + op2WOff, op2WPairs);

    for (int l = 0; l < LQ; l++) {
        if (l > 0) {
            k_gemm_tc2<<<dim3(1, BQ * HQ / 64), 256, dynSmem>>>(
                t0p, t1p, ht0p, ht1p, xcp, 128, BQ * HQ, SQ,
                (const float*)0, 0, (unsigned int*)0, (unsigned int*)0);
            k_spec<<<dim3(MQ, HQ / 128), 128>>>(fw_r + (size_t)l * MQ * HQ * HQ,
                                                fw_i + (size_t)l * MQ * HQ * HQ);
        }
        k_packY<<<(BQ * HQ * 32 + 255) / 256, 256>>>();
        // conv GEMM (independent of fourier branch)
        k_gemm_tc2<<<dim3(BQ * SQ / 128, HQ / 64), 256, dynSmem>>>(
            a0p, a1p, w0p + (size_t)l * HQ * HQ / 2, w1p + (size_t)l * HQ * HQ / 2,
            yp, BQ * SQ, HQ, HQ, (const float*)0, 0,
            (unsigned int*)0, (unsigned int*)0);
        // inverse DFT GEMM: xfC[s][(b,c)]
        k_gemm_tc2<<<dim3(SQ / 128, BQ * HQ / 64), 256, dynSmem>>>(
            ti0p, ti1p, ys0p, ys1p, xfp, SQ, BQ * HQ, 64,
            (const float*)0, 0, (unsigned int*)0, (unsigned int*)0);
        k_lnrow<<<BQ * SQ, 128>>>(conv_b + l * HQ, ln_g + l * HQ, ln_b + l * HQ);
        if (l < LQ - 1)
            k_hTt<<<dim3(SQ / 64, HQ / 32, BQ), 256>>>();
    }

    // output projection: H -> H/2 -> H/4 -> 1
    k_gemm_tc2<<<dim3(BQ * SQ / 128, (HQ / 2) / 64), 256, dynSmem>>>(
        a0p, a1p, w0p + op1WOff, w1p + op1WOff, yp, BQ * SQ, HQ / 2, HQ,
        op1_b, 3, o10p, o11p);
    k_gemm_tc2<<<dim3(BQ * SQ / 128, (HQ / 4) / 64), 256, dynSmem>>>(
        o10p, o11p, w0p + op2WOff, w1p + op2WOff, o2p, BQ * SQ, HQ / 4, HQ / 2,
        op2_b, 1, (unsigned int*)0, (unsigned int*)0);
    k_op3<<<BQ * SQ / 4, 128>>>(op3_w, op3_b, out);

    // cryptanalytic head
    k_mean1<<<dim3(BQ * 4, 16), 128>>>();
    k_mean2<<<(BQ * HQ + 255) / 256, 256>>>();
    k_head1<<<dim3(BQ, HQ / 128), 128>>>(h1_w, h1_b);
    k_head2<<<dim3(BQ, KBQ / 128), 128>>>(h2_w, h2_b, out);
}

// round 13
// speedup vs baseline: 2.0057x; 1.4927x over previous
#include <cuda_runtime.h>
#include <cstdint>
#include <stdint.h>
#include <math.h>

#define BQ 8
#define SQ 2048
#define HQ 512
#define LQ 8
#define MQ 32
#define KBQ 256

// ---------------- scratch (device globals, allocation-free) ----------------
__device__ float  g_h [BQ*SQ*HQ];           // hidden state [B,S,H]
__device__ float  g_y [BQ*SQ*HQ];           // conv GEMM out
__device__ float  g_xfC[SQ*BQ*HQ];          // inv DFT out [s][(b*H+c)]
__device__ float  g_Xc[128*BQ*HQ];          // fwd DFT out [128 rows][B*H cols]
__device__ float  g_Psr[4*BQ*MQ*HQ];        // spec partials (real)
__device__ float  g_Psi[4*BQ*MQ*HQ];        // spec partials (imag)
__device__ float  g_o2[BQ*SQ*(HQ/4)];
__device__ float  g_gf[BQ*HQ];
__device__ float  g_k1[BQ*HQ];
__device__ float  g_mred[16*BQ*HQ];

// bf16 hi/lo packed operands (2 bf16 per word)
#define WTOT (LQ*HQ*HQ + (HQ/2)*HQ + (HQ/4)*(HQ/2))
__device__ unsigned int g_A0[BQ*SQ*HQ/2];   // h pairs along H
__device__ unsigned int g_A1[BQ*SQ*HQ/2];
__device__ unsigned int g_W0[WTOT/2];
__device__ unsigned int g_W1[WTOT/2];
__device__ unsigned int g_o10[BQ*SQ*(HQ/2)/2];
__device__ unsigned int g_o11[BQ*SQ*(HQ/2)/2];
__device__ unsigned int g_T0[128*SQ/2];     // fwd twiddle [128 rows][1024 words]
__device__ unsigned int g_T1[128*SQ/2];
__device__ unsigned int g_Ti0[SQ*32];       // inv twiddle [2048 rows][32 words]
__device__ unsigned int g_Ti1[SQ*32];
__device__ unsigned int g_hT0[BQ*HQ*SQ/2];  // h^T[(b*H+c)][s-pairs]
__device__ unsigned int g_hT1[BQ*HQ*SQ/2];
__device__ unsigned int g_Ys0[BQ*HQ*32];    // Y stacked [(b*H+c)][32 words = 64 k]
__device__ unsigned int g_Ys1[BQ*HQ*32];

__device__ __forceinline__ float gelu_exact(float x) {
    return 0.5f * x * (1.0f + erff(x * 0.70710678118654752440f));
}

// ---------------- bf16 helpers ----------------
__device__ __forceinline__ unsigned int bfpack(float x0, float x1) {
    unsigned int rr;
    asm("cvt.rn.bf16x2.f32 %0, %1, %2;" : "=r"(rr) : "f"(x1), "f"(x0));
    return rr;
}

__device__ __forceinline__ void bfsplit2(float x0, float x1,
                                         unsigned int& whi, unsigned int& wlo) {
    unsigned int hic = bfpack(x0, x1);
    float res0 = x0 - __uint_as_float(hic << 16);
    float res1 = x1 - __uint_as_float(hic & 0xffff0000u);
    whi = hic;
    wlo = bfpack(res0, res1);
}

__device__ __forceinline__ void ldsm4(unsigned int& ra, unsigned int& rb,
                                      unsigned int& rc, unsigned int& rd,
                                      unsigned int addr) {
    asm volatile("ldmatrix.sync.aligned.m8n8.x4.shared.b16 {%0,%1,%2,%3}, [%4];"
                 : "=r"(ra), "=r"(rb), "=r"(rc), "=r"(rd) : "r"(addr));
}

__device__ __forceinline__ void mma_bf16(float* dacc, const unsigned int* amat,
                                         const unsigned int* bmat) {
    asm volatile(
        "mma.sync.aligned.m16n8k16.row.col.f32.bf16.bf16.f32 "
        "{%0,%1,%2,%3}, {%4,%5,%6,%7}, {%8,%9}, {%0,%1,%2,%3};"
        : "+f"(dacc[0]), "+f"(dacc[1]), "+f"(dacc[2]), "+f"(dacc[3])
        : "r"(amat[0]), "r"(amat[1]), "r"(amat[2]), "r"(amat[3]),
          "r"(bmat[0]), "r"(bmat[1]));
}

#define CPASYNC16(dstaddr, srcptr) \
    asm volatile("cp.async.cg.shared.global [%0], [%1], 16;" \
                 :: "r"(dstaddr), "l"(srcptr))
#define CPCOMMIT() asm volatile("cp.async.commit_group;")
#define CPWAIT(nn) asm volatile("cp.async.wait_group %0;" :: "n"(nn))

// ---------------- fwd twiddle matrix T ----------------
__global__ void k_tabT() {
    int i = blockIdx.x * 256 + threadIdx.x;
    if (i < 128 * SQ / 2) {
        int sp  = i & (SQ / 2 - 1);
        int row = i >> 10;
        float v0 = 0.f, v1 = 0.f;
        if (row < 32) {
            float a0 = (float)(row * (2 * sp))     * (1.0f / 1024.0f);
            float a1 = (float)(row * (2 * sp + 1)) * (1.0f / 1024.0f);
            v0 = cospif(a0); v1 = cospif(a1);
        } else if (row < 64) {
            int m = row - 32;
            float a0 = (float)(m * (2 * sp))     * (1.0f / 1024.0f);
            float a1 = (float)(m * (2 * sp + 1)) * (1.0f / 1024.0f);
            v0 = -sinpif(a0); v1 = -sinpif(a1);
        }
        bfsplit2(v0, v1, g_T0[i], g_T1[i]);
    }
}

// ---------------- inverse twiddle matrix Tinv ----------------
__global__ void k_tabI() {
    int i = blockIdx.x * 256 + threadIdx.x;
    if (i < SQ * 32) {
        int kw = i & 31;
        int s  = i >> 5;
        int k0 = 2 * kw, k1 = 2 * kw + 1;
        float v0, v1;
        if (k0 < 32) {
            float c0 = (k0 == 0 ? 1.0f : 2.0f) / (float)SQ;
            float c1 = 2.0f / (float)SQ;
            v0 = c0 * cospif((float)(k0 * s) * (1.0f / 1024.0f));
            v1 = c1 * cospif((float)(k1 * s) * (1.0f / 1024.0f));
        } else {
            int m0 = k0 - 32, m1 = k1 - 32;
            float c0 = (m0 == 0 ? 1.0f : 2.0f) / (float)SQ;
            float c1 = 2.0f / (float)SQ;
            v0 = -c0 * sinpif((float)(m0 * s) * (1.0f / 1024.0f));
            v1 = -c1 * sinpif((float)(m1 * s) * (1.0f / 1024.0f));
        }
        bfsplit2(v0, v1, g_Ti0[i], g_Ti1[i]);
    }
}

// ---------------- h^T init ----------------
__global__ void k_initT(const float* __restrict__ x, const float* __restrict__ in_w,
                        const float* __restrict__ in_b) {
    int i = blockIdx.x * 256 + threadIdx.x;
    if (i < BQ * HQ * SQ / 2) {
        int sp = i & (SQ / 2 - 1);
        int bc = i >> 10;
        int c  = bc & (HQ - 1);
        int b  = bc >> 9;
        float wv = in_w[c], bv = in_b[c];
        float v0 = x[b * SQ + 2 * sp] * wv + bv;
        float v1 = x[b * SQ + 2 * sp + 1] * wv + bv;
        bfsplit2(v0, v1, g_hT0[i], g_hT1[i]);
    }
}

// ---------------- input projection ----------------
__global__ void k_init(const float* __restrict__ x, const float* __restrict__ in_w,
                       const float* __restrict__ in_b) {
    int i = blockIdx.x * 256 + threadIdx.x;
    if (i < BQ * SQ * HQ / 2) {
        int e0 = 2 * i;
        int c0 = e0 & (HQ - 1);
        int bs = e0 >> 9;
        float xv = x[bs];
        float v0 = xv * in_w[c0] + in_b[c0];
        float v1 = xv * in_w[c0 + 1] + in_b[c0 + 1];
        g_h[e0] = v0;
        g_h[e0 + 1] = v1;
        bfsplit2(v0, v1, g_A0[i], g_A1[i]);
    }
}

// ---------------- fp32 -> bf16 hi/lo (weights) ----------------
__global__ void k_cvt(const float* __restrict__ src, unsigned int* __restrict__ dsthi,
                      unsigned int* __restrict__ dstlo, int npairs) {
    int i = blockIdx.x * 256 + threadIdx.x;
    if (i < npairs) {
        bfsplit2(src[2 * i], src[2 * i + 1], dsthi[i], dstlo[i]);
    }
}

// ---------------- per-mode complex GEMM, h-split partials ----------------
// grid (MQ, 2, 4), block 256. k = blockIdx.y*256+tid, h in [hpart*128, +128)
__global__ void k_spec2(const float* __restrict__ Wr, const float* __restrict__ Wi) {
    int m = blockIdx.x, tid = threadIdx.x;
    int k = blockIdx.y * 256 + tid;
    int hpart = blockIdx.z;
    int h0 = hpart * 128;
    __shared__ float sXr[BQ][128];
    __shared__ float sXi[BQ][128];
    for (int i = tid; i < BQ * 128; i += 256) {
        int b = i >> 7, hh = i & 127;
        sXr[b][hh] = g_Xc[(size_t)m * (BQ * HQ) + b * HQ + h0 + hh];
        sXi[b][hh] = g_Xc[(size_t)(32 + m) * (BQ * HQ) + b * HQ + h0 + hh];
    }
    __syncthreads();
    float yr[BQ], yi[BQ];
#pragma unroll
    for (int b = 0; b < BQ; b++) { yr[b] = 0.f; yi[b] = 0.f; }
#pragma unroll 4
    for (int h = 0; h < 128; h++) {
        float wr = Wr[(size_t)(m * HQ + h0 + h) * HQ + k];
        float wi = Wi[(size_t)(m * HQ + h0 + h) * HQ + k];
#pragma unroll
        for (int b = 0; b < BQ; b++) {
            float xr = sXr[b][h], xi = sXi[b][h];
            yr[b] = fmaf(xr, wr, fmaf(-xi, wi, yr[b]));
            yi[b] = fmaf(xr, wi, fmaf( xi, wr, yi[b]));
        }
    }
#pragma unroll
    for (int b = 0; b < BQ; b++) {
        size_t o = ((size_t)(hpart * BQ + b) * MQ + m) * HQ + k;
        g_Psr[o] = yr[b];
        g_Psi[o] = yi[b];
    }
}

// ---------------- reduce 4 partials + pack to bf16 Ystack ----------------
// grid (HQ/64, BQ), block 256
__global__ void k_specred() {
    __shared__ float ySr[MQ][64];
    __shared__ float ySi[MQ][64];
    int c0 = blockIdx.x * 64;
    int b  = blockIdx.y;
    int tid = threadIdx.x;
    for (int idx = tid; idx < MQ * 64; idx += 256) {
        int c = idx & 63, m = idx >> 6;
        float sr = 0.f, si = 0.f;
#pragma unroll
        for (int part = 0; part < 4; part++) {
            size_t o = ((size_t)(part * BQ + b) * MQ + m) * HQ + c0 + c;
            sr += g_Psr[o];
            si += g_Psi[o];
        }
        ySr[m][c] = sr;
        ySi[m][c] = si;
    }
    __syncthreads();
    for (int idx = tid; idx < 64 * 32; idx += 256) {
        int kw = idx & 31, c = idx >> 5;
        int k0 = 2 * kw, k1 = 2 * kw + 1;
        float v0 = (k0 < 32) ? ySr[k0][c] : ySi[k0 - 32][c];
        float v1 = (k1 < 32) ? ySr[k1][c] : ySi[k1 - 32][c];
        unsigned int w0v, w1v;
        bfsplit2(v0, v1, w0v, w1v);
        size_t o = (size_t)(b * HQ + c0 + c) * 32 + kw;
        g_Ys0[o] = w0v;
        g_Ys1[o] = w1v;
    }
}

// ---------------- LN row kernel ----------------
__global__ void k_lnrow(const float* __restrict__ cb, const float* __restrict__ gg,
                        const float* __restrict__ bb) {
    int row = blockIdx.x, tid = threadIdx.x;
    int b = row >> 11, s = row & (SQ - 1);
    int j0 = tid * 4;
    float v[4], s1 = 0.f, s2 = 0.f;
#pragma unroll
    for (int i = 0; i < 4; i++) {
        int j = j0 + i;
        float t = g_y[(size_t)row * HQ + j] +
                  g_xfC[(size_t)s * (BQ * HQ) + b * HQ + j] + cb[j];
        v[i] = t; s1 += t; s2 += t * t;
    }
#pragma unroll
    for (int o = 16; o; o >>= 1) {
        s1 += __shfl_xor_sync(0xffffffffu, s1, o);
        s2 += __shfl_xor_sync(0xffffffffu, s2, o);
    }
    __shared__ float red[64];
    int w = tid >> 5;
    if ((tid & 31) == 0) { red[w] = s1; red[32 + w] = s2; }
    __syncthreads();
    float ts  = red[0] + red[1] + red[2] + red[3];
    float ts2 = red[32] + red[33] + red[34] + red[35];
    float mu  = ts * (1.f / HQ);
    float var = ts2 * (1.f / HQ) - mu * mu;
    float rinv = rsqrtf(var + 1e-5f);
    float hv[4];
#pragma unroll
    for (int i = 0; i < 4; i++) {
        int j = j0 + i;
        size_t idx = (size_t)row * HQ + j;
        hv[i] = (v[i] - mu) * rinv * gg[j] + bb[j] + g_h[idx];
        g_h[idx] = hv[i];
    }
    size_t wbase = (size_t)row * (HQ / 2) + tid * 2;
    bfsplit2(hv[0], hv[1], g_A0[wbase], g_A1[wbase]);
    bfsplit2(hv[2], hv[3], g_A0[wbase + 1], g_A1[wbase + 1]);
}

// ---------------- h -> hT transpose ----------------
__global__ void k_hTt() {
    __shared__ float tile[64][33];
    int s0 = blockIdx.x * 64;
    int c0 = blockIdx.y * 32;
    int b  = blockIdx.z;
    int tid = threadIdx.x;
    for (int i = tid; i < 64 * 32; i += 256) {
        int si = i >> 5, ci = i & 31;
        tile[si][ci] = g_h[(size_t)(b * SQ + s0 + si) * HQ + c0 + ci];
    }
    __syncthreads();
    for (int i = tid; i < 32 * 32; i += 256) {
        int ci = i >> 5, spi = i & 31;
        unsigned int w0v, w1v;
        bfsplit2(tile[2 * spi][ci], tile[2 * spi + 1][ci], w0v, w1v);
        size_t o = ((size_t)(b * HQ + c0 + ci) << 10) + (size_t)(s0 >> 1) + spi;
        g_hT0[o] = w0v;
        g_hT1[o] = w1v;
    }
}

// ============ 3xBF16 tensor-core GEMM (hi/lo compensated) ============
#define STG_WORDS 12288

__device__ __forceinline__ void issue_slab(
    unsigned int smemBase, int stageSel,
    const unsigned int* __restrict__ Amat0, const unsigned int* __restrict__ Amat1,
    const unsigned int* __restrict__ Bmat0, const unsigned int* __restrict__ Bmat1,
    int rowBase, int colBase, int Kw, int kw, int tid)
{
#pragma unroll
    for (int it = 0; it < 4; it++) {
        int idx = tid + it * 256;
        int row = idx >> 3, chk = idx & 7;
        unsigned int woff = (unsigned int)(stageSel * STG_WORDS + row * 32 +
                                           ((chk ^ (row & 7)) << 2));
        size_t gsrc = (size_t)(rowBase + row) * Kw + kw + chk * 4;
        CPASYNC16(smemBase + woff * 4, Amat0 + gsrc);
        CPASYNC16(smemBase + (woff + 4096) * 4, Amat1 + gsrc);
    }
#pragma unroll
    for (int it = 0; it < 2; it++) {
        int idx = tid + it * 256;
        int row = idx >> 3, chk = idx & 7;
        unsigned int woff = (unsigned int)(stageSel * STG_WORDS + 8192 + row * 32 +
                                           ((chk ^ (row & 7)) << 2));
        size_t gsrc = (size_t)(colBase + row) * Kw + kw + chk * 4;
        CPASYNC16(smemBase + woff * 4, Bmat0 + gsrc);
        CPASYNC16(smemBase + (woff + 2048) * 4, Bmat1 + gsrc);
    }
}

__global__ void __launch_bounds__(256, 2)
k_gemm_tc2(const unsigned int* __restrict__ Amat0, const unsigned int* __restrict__ Amat1,
           const unsigned int* __restrict__ Bmat0, const unsigned int* __restrict__ Bmat1,
           float* __restrict__ Cmat, int Mdim, int Ndim, int Kdim,
           const float* __restrict__ biasPtr, int gmode,
           unsigned int* __restrict__ Cout0, unsigned int* __restrict__ Cout1) {
    extern __shared__ unsigned int shMem[];
    const int tid  = threadIdx.x;
    const int lane = tid & 31;
    const int warpIdx = tid >> 5;
    const int wmoff = (warpIdx & 3) * 32;
    const int wnoff = (warpIdx >> 2) * 32;
    const int rowBase = blockIdx.x * 128;
    const int colBase = blockIdx.y * 64;
    const int Kw = Kdim >> 1;

    const unsigned int smemBase = (unsigned int)__cvta_generic_to_shared(shMem);

    const int arowA = wmoff + (lane & 15);
    const int achA  = lane >> 4;
    const int browB = wnoff + ((lane >> 4) << 3) + (lane & 7);
    const int bchB  = (lane >> 3) & 1;

    float acc[2][4][4];
#pragma unroll
    for (int fi = 0; fi < 2; fi++)
#pragma unroll
        for (int ji = 0; ji < 4; ji++)
#pragma unroll
            for (int ci = 0; ci < 4; ci++) acc[fi][ji][ci] = 0.0f;

    const int nSlab = Kw >> 5;
    issue_slab(smemBase, 0, Amat0, Amat1, Bmat0, Bmat1, rowBase, colBase, Kw, 0, tid);
    CPCOMMIT();

    for (int is = 0; is < nSlab; is++) {
        const int stagec = is & 1;
        if (is + 1 < nSlab) {
            issue_slab(smemBase, (is + 1) & 1, Amat0, Amat1, Bmat0, Bmat1,
                       rowBase, colBase, Kw, (is + 1) << 5, tid);
            CPCOMMIT();
            CPWAIT(1);
        } else {
            CPWAIT(0);
        }
        __syncthreads();

        const unsigned int stW = (unsigned int)(stagec * STG_WORDS);
#pragma unroll
        for (int gi = 0; gi < 4; gi++) {
            unsigned int fragA0[2][4];
            unsigned int fragA1[2][4];
            unsigned int fragB0[4][2];
            unsigned int fragB1[4][2];
#pragma unroll
            for (int fi = 0; fi < 2; fi++) {
                int rr = arowA + fi * 16;
                int chq = 2 * gi + achA;
                unsigned int byoff = (stW + rr * 32 + ((chq ^ (rr & 7)) << 2)) << 2;
                ldsm4(fragA0[fi][0], fragA0[fi][1], fragA0[fi][2], fragA0[fi][3],
                      smemBase + byoff);
                ldsm4(fragA1[fi][0], fragA1[fi][1], fragA1[fi][2], fragA1[fi][3],
                      smemBase + byoff + 4096 * 4);
            }
#pragma unroll
            for (int pj = 0; pj < 2; pj++) {
                int rr = browB + pj * 16;
                int chq = 2 * gi + bchB;
                unsigned int byoff = (stW + 8192 + rr * 32 + ((chq ^ (rr & 7)) << 2)) << 2;
                unsigned int tqa[4];
                ldsm4(tqa[0], tqa[1], tqa[2], tqa[3], smemBase + byoff);
                fragB0[2 * pj + 0][0] = tqa[0];
                fragB0[2 * pj + 0][1] = tqa[1];
                fragB0[2 * pj + 1][0] = tqa[2];
                fragB0[2 * pj + 1][1] = tqa[3];
                unsigned int tqb[4];
                ldsm4(tqb[0], tqb[1], tqb[2], tqb[3], smemBase + byoff + 2048 * 4);
                fragB1[2 * pj + 0][0] = tqb[0];
                fragB1[2 * pj + 0][1] = tqb[1];
                fragB1[2 * pj + 1][0] = tqb[2];
                fragB1[2 * pj + 1][1] = tqb[3];
            }
#pragma unroll
            for (int fi = 0; fi < 2; fi++) {
#pragma unroll
                for (int ji = 0; ji < 4; ji++) {
                    mma_bf16(acc[fi][ji], fragA0[fi], fragB0[ji]);
                    mma_bf16(acc[fi][ji], fragA1[fi], fragB0[ji]);
                    mma_bf16(acc[fi][ji], fragA0[fi], fragB1[ji]);
                }
            }
        }
        __syncthreads();
    }

    const int Ndw = Ndim >> 1;
#pragma unroll
    for (int fi = 0; fi < 2; fi++) {
#pragma unroll
        for (int ji = 0; ji < 4; ji++) {
            int orow = rowBase + wmoff + fi * 16 + (lane >> 2);
            int ocol = colBase + wnoff + ji * 8 + (lane & 3) * 2;
            float outA = acc[fi][ji][0];
            float outB = acc[fi][ji][1];
            float outC = acc[fi][ji][2];
            float outD = acc[fi][ji][3];
            if (gmode != 0) {
                float biasLo = biasPtr[ocol];
                float biasHi = biasPtr[ocol + 1];
                outA = gelu_exact(outA + biasLo);
                outB = gelu_exact(outB + biasHi);
                outC = gelu_exact(outC + biasLo);
                outD = gelu_exact(outD + biasHi);
            }
            if (gmode == 3) {
                size_t widx0 = (size_t)orow * Ndw + (ocol >> 1);
                size_t widx1 = (size_t)(orow + 8) * Ndw + (ocol >> 1);
                bfsplit2(outA, outB, Cout0[widx0], Cout1[widx0]);
                bfsplit2(outC, outD, Cout0[widx1], Cout1[widx1]);
            } else {
                *(float2*)&Cmat[(size_t)orow * Ndim + ocol] = make_float2(outA, outB);
                *(float2*)&Cmat[(size_t)(orow + 8) * Ndim + ocol] = make_float2(outC, outD);
            }
        }
    }
}

// ---------------- final projection to scalar ----------------
__global__ void k_op3(const float* __restrict__ w, const float* __restrict__ b3,
                      float* __restrict__ out) {
    int tid = threadIdx.x;
    int row = blockIdx.x * 4 + (tid >> 5);
    int lane = tid & 31;
    float s = 0.f;
#pragma unroll
    for (int i = 0; i < 4; i++) {
        int j = lane + i * 32;
        s += g_o2[(size_t)row * 128 + j] * w[j];
    }
#pragma unroll
    for (int o = 16; o; o >>= 1) s += __shfl_xor_sync(0xffffffffu, s, o);
    if (lane == 0) out[row] = s + b3[0];
}

// ---------------- mean over s (two-stage) ----------------
__global__ void k_mean1() {
    int part = blockIdx.y;
    int b = blockIdx.x >> 2;
    int c = (blockIdx.x & 3) * 128 + threadIdx.x;
    float s = 0.f;
    int sbeg = part * (SQ / 16);
    for (int ss = sbeg; ss < sbeg + (SQ / 16); ss++)
        s += g_h[(size_t)(b * SQ + ss) * HQ + c];
    g_mred[part * (BQ * HQ) + b * HQ + c] = s;
}

__global__ void k_mean2() {
    int i = blockIdx.x * 256 + threadIdx.x;
    if (i < BQ * HQ) {
        float s = 0.f;
#pragma unroll
        for (int part = 0; part < 16; part++) s += g_mred[part * (BQ * HQ) + i];
        g_gf[i] = s * (1.f / SQ);
    }
}

// ---------------- head kernels ----------------
__global__ void k_head1(const float* __restrict__ w, const float* __restrict__ bias) {
    int b = blockIdx.x, tid = threadIdx.x;
    int j = blockIdx.y * 128 + tid;
    __shared__ float sg[HQ];
    for (int i = tid; i < HQ; i += 128) sg[i] = g_gf[b * HQ + i];
    __syncthreads();
    const float4* w4 = (const float4*)(w + (size_t)j * HQ);
    float acc = 0.f;
    for (int c = 0; c < HQ / 4; c++) {
        float4 wv = w4[c];
        float4 gv = *(const float4*)&sg[c * 4];
        acc = fmaf(wv.x, gv.x, acc); acc = fmaf(wv.y, gv.y, acc);
        acc = fmaf(wv.z, gv.z, acc); acc = fmaf(wv.w, gv.w, acc);
    }
    g_k1[b * HQ + j] = gelu_exact(acc + bias[j]);
}

__global__ void k_head2(const float* __restrict__ w, const float* __restrict__ bias,
                        float* __restrict__ out) {
    int b = blockIdx.x, tid = threadIdx.x;
    int j = blockIdx.y * 128 + tid;
    __shared__ float sk[HQ];
    for (int i = tid; i < HQ; i += 128) sk[i] = g_k1[b * HQ + i];
    __syncthreads();
    const float4* w4 = (const float4*)(w + (size_t)j * HQ);
    float acc = 0.f;
    for (int c = 0; c < HQ / 4; c++) {
        float4 wv = w4[c];
        float4 kv = *(const float4*)&sk[c * 4];
        acc = fmaf(wv.x, kv.x, acc); acc = fmaf(wv.y, kv.y, acc);
        acc = fmaf(wv.z, kv.z, acc); acc = fmaf(wv.w, kv.w, acc);
    }
    float t = acc + bias[j];
    out[BQ * SQ + b * KBQ + j] = 1.f / (1.f + expf(-t));
}

// ---------------- launch ----------------
extern "C" void kernel_launch(void* const* d_in, const int* in_sizes, int n_in,
                              void* d_out, int out_size) {
    const float* x      = (const float*)d_in[0];
    const float* in_w   = (const float*)d_in[1];
    const float* in_b   = (const float*)d_in[2];
    const float* fw_r   = (const float*)d_in[3];
    const float* fw_i   = (const float*)d_in[4];
    const float* conv_w = (const float*)d_in[5];
    const float* conv_b = (const float*)d_in[6];
    const float* ln_g   = (const float*)d_in[7];
    const float* ln_b   = (const float*)d_in[8];
    const float* op1_w  = (const float*)d_in[9];
    const float* op1_b  = (const float*)d_in[10];
    const float* op2_w  = (const float*)d_in[11];
    const float* op2_b  = (const float*)d_in[12];
    const float* op3_w  = (const float*)d_in[13];
    const float* op3_b  = (const float*)d_in[14];
    const float* h1_w   = (const float*)d_in[15];
    const float* h1_b   = (const float*)d_in[16];
    const float* h2_w   = (const float*)d_in[17];
    const float* h2_b   = (const float*)d_in[18];
    float* out = (float*)d_out;

    float *yp, *o2p, *xcp, *xfp;
    unsigned int *a0p, *a1p, *w0p, *w1p, *o10p, *o11p;
    unsigned int *t0p, *t1p, *ti0p, *ti1p, *ht0p, *ht1p, *ys0p, *ys1p;
    cudaGetSymbolAddress((void**)&yp,  g_y);
    cudaGetSymbolAddress((void**)&o2p, g_o2);
    cudaGetSymbolAddress((void**)&xcp, g_Xc);
    cudaGetSymbolAddress((void**)&xfp, g_xfC);
    cudaGetSymbolAddress((void**)&a0p, g_A0);
    cudaGetSymbolAddress((void**)&a1p, g_A1);
    cudaGetSymbolAddress((void**)&w0p, g_W0);
    cudaGetSymbolAddress((void**)&w1p, g_W1);
    cudaGetSymbolAddress((void**)&o10p, g_o10);
    cudaGetSymbolAddress((void**)&o11p, g_o11);
    cudaGetSymbolAddress((void**)&t0p, g_T0);
    cudaGetSymbolAddress((void**)&t1p, g_T1);
    cudaGetSymbolAddress((void**)&ti0p, g_Ti0);
    cudaGetSymbolAddress((void**)&ti1p, g_Ti1);
    cudaGetSymbolAddress((void**)&ht0p, g_hT0);
    cudaGetSymbolAddress((void**)&ht1p, g_hT1);
    cudaGetSymbolAddress((void**)&ys0p, g_Ys0);
    cudaGetSymbolAddress((void**)&ys1p, g_Ys1);

    static int smemSet = 0;
    if (!smemSet) {
        cudaFuncSetAttribute(k_gemm_tc2, cudaFuncAttributeMaxDynamicSharedMemorySize,
                             2 * STG_WORDS * 4);
        smemSet = 1;
    }
    const int dynSmem = 2 * STG_WORDS * 4;

    const int convWPairs = LQ * HQ * HQ / 2;
    const int op1WOff    = convWPairs;
    const int op1WPairs  = (HQ / 2) * HQ / 2;
    const int op2WOff    = convWPairs + op1WPairs;
    const int op2WPairs  = (HQ / 4) * (HQ / 2) / 2;
    const int hPairs     = BQ * SQ * HQ / 2;
    const int htWords    = BQ * HQ * SQ / 2;

    // prologue; launch #4 = k_spec2 layer 0 (ncu capture slot)
    k_tabT<<<(128 * SQ / 2 + 255) / 256, 256>>>();
    k_initT<<<(htWords + 255) / 256, 256>>>(x, in_w, in_b);
    k_gemm_tc2<<<dim3(1, BQ * HQ / 64), 256, dynSmem>>>(
        t0p, t1p, ht0p, ht1p, xcp, 128, BQ * HQ, SQ,
        (const float*)0, 0, (unsigned int*)0, (unsigned int*)0);
    k_spec2<<<dim3(MQ, 2, 4), 256>>>(fw_r, fw_i);
    k_specred<<<dim3(HQ / 64, BQ), 256>>>();
    k_tabI<<<(SQ * 32 + 255) / 256, 256>>>();
    k_init<<<(hPairs + 255) / 256, 256>>>(x, in_w, in_b);
    k_cvt<<<(convWPairs + 255) / 256, 256>>>(conv_w, w0p, w1p, convWPairs);
    k_cvt<<<(op1WPairs + 255) / 256, 256>>>(op1_w, w0p + op1WOff, w1p + op1WOff, op1WPairs);
    k_cvt<<<(op2WPairs + 255) / 256, 256>>>(op2_w, w0p + op2WOff, w1p + op2WOff, op2WPairs);

    for (int l = 0; l < LQ; l++) {
        if (l > 0) {
            k_gemm_tc2<<<dim3(1, BQ * HQ / 64), 256, dynSmem>>>(
                t0p, t1p, ht0p, ht1p, xcp, 128, BQ * HQ, SQ,
                (const float*)0, 0, (unsigned int*)0, (unsigned int*)0);
            k_spec2<<<dim3(MQ, 2, 4), 256>>>(fw_r + (size_t)l * MQ * HQ * HQ,
                                             fw_i + (size_t)l * MQ * HQ * HQ);
            k_specred<<<dim3(HQ / 64, BQ), 256>>>();
        }
        // conv GEMM (independent of fourier branch)
        k_gemm_tc2<<<dim3(BQ * SQ / 128, HQ / 64), 256, dynSmem>>>(
            a0p, a1p, w0p + (size_t)l * HQ * HQ / 2, w1p + (size_t)l * HQ * HQ / 2,
            yp, BQ * SQ, HQ, HQ, (const float*)0, 0,
            (unsigned int*)0, (unsigned int*)0);
        // inverse DFT GEMM: xfC[s][(b,c)]
        k_gemm_tc2<<<dim3(SQ / 128, BQ * HQ / 64), 256, dynSmem>>>(
            ti0p, ti1p, ys0p, ys1p, xfp, SQ, BQ * HQ, 64,
            (const float*)0, 0, (unsigned int*)0, (unsigned int*)0);
        k_lnrow<<<BQ * SQ, 128>>>(conv_b + l * HQ, ln_g + l * HQ, ln_b + l * HQ);
        if (l < LQ - 1)
            k_hTt<<<dim3(SQ / 64, HQ / 32, BQ), 256>>>();
    }

    // output projection: H -> H/2 -> H/4 -> 1
    k_gemm_tc2<<<dim3(BQ * SQ / 128, (HQ / 2) / 64), 256, dynSmem>>>(
        a0p, a1p, w0p + op1WOff, w1p + op1WOff, yp, BQ * SQ, HQ / 2, HQ,
        op1_b, 3, o10p, o11p);
    k_gemm_tc2<<<dim3(BQ * SQ / 128, (HQ / 4) / 64), 256, dynSmem>>>(
        o10p, o11p, w0p + op2WOff, w1p + op2WOff, o2p, BQ * SQ, HQ / 4, HQ / 2,
        op2_b, 1, (unsigned int*)0, (unsigned int*)0);
    k_op3<<<BQ * SQ / 4, 128>>>(op3_w, op3_b, out);

    // cryptanalytic head
    k_mean1<<<dim3(BQ * 4, 16), 128>>>();
    k_mean2<<<(BQ * HQ + 255) / 256, 256>>>();
    k_head1<<<dim3(BQ, HQ / 128), 128>>>(h1_w, h1_b);
    k_head2<<<dim3(BQ, KBQ / 128), 128>>>(h2_w, h2_b, out);
}

// round 14
// speedup vs baseline: 2.0100x; 1.0021x over previous
#include <cuda_runtime.h>
#include <cstdint>
#include <stdint.h>
#include <math.h>

#define BQ 8
#define SQ 2048
#define HQ 512
#define LQ 8
#define MQ 32
#define KBQ 256

// ---------------- scratch (device globals, allocation-free) ----------------
__device__ float  g_h [BQ*SQ*HQ];           // hidden state [B,S,H]
__device__ float  g_y [BQ*SQ*HQ];           // conv GEMM out
__device__ float  g_xfC[SQ*BQ*HQ];          // inv DFT out [s][(b*H+c)]
__device__ float  g_Xc[128*BQ*HQ];          // fwd DFT out [128 rows][B*H cols]
__device__ float  g_Psr[8*BQ*MQ*HQ];        // spec partials (real)
__device__ float  g_Psi[8*BQ*MQ*HQ];        // spec partials (imag)
__device__ float  g_o2[BQ*SQ*(HQ/4)];
__device__ float  g_gf[BQ*HQ];
__device__ float  g_k1[BQ*HQ];
__device__ float  g_mred[16*BQ*HQ];

// bf16 hi/lo packed operands (2 bf16 per word)
#define WTOT (LQ*HQ*HQ + (HQ/2)*HQ + (HQ/4)*(HQ/2))
__device__ unsigned int g_A0[BQ*SQ*HQ/2];   // h pairs along H
__device__ unsigned int g_A1[BQ*SQ*HQ/2];
__device__ unsigned int g_W0[WTOT/2];
__device__ unsigned int g_W1[WTOT/2];
__device__ unsigned int g_o10[BQ*SQ*(HQ/2)/2];
__device__ unsigned int g_o11[BQ*SQ*(HQ/2)/2];
__device__ unsigned int g_T0[128*SQ/2];     // fwd twiddle [128 rows][1024 words]
__device__ unsigned int g_T1[128*SQ/2];
__device__ unsigned int g_Ti0[SQ*32];       // inv twiddle [2048 rows][32 words]
__device__ unsigned int g_Ti1[SQ*32];
__device__ unsigned int g_hT0[BQ*HQ*SQ/2];  // h^T[(b*H+c)][s-pairs]
__device__ unsigned int g_hT1[BQ*HQ*SQ/2];
__device__ unsigned int g_Ys0[BQ*HQ*32];    // Y stacked [(b*H+c)][32 words = 64 k]
__device__ unsigned int g_Ys1[BQ*HQ*32];

__device__ __forceinline__ float gelu_exact(float x) {
    return 0.5f * x * (1.0f + erff(x * 0.70710678118654752440f));
}

// ---------------- bf16 helpers ----------------
__device__ __forceinline__ unsigned int bfpack(float x0, float x1) {
    unsigned int rr;
    asm("cvt.rn.bf16x2.f32 %0, %1, %2;" : "=r"(rr) : "f"(x1), "f"(x0));
    return rr;
}

__device__ __forceinline__ void bfsplit2(float x0, float x1,
                                         unsigned int& whi, unsigned int& wlo) {
    unsigned int hic = bfpack(x0, x1);
    float res0 = x0 - __uint_as_float(hic << 16);
    float res1 = x1 - __uint_as_float(hic & 0xffff0000u);
    whi = hic;
    wlo = bfpack(res0, res1);
}

__device__ __forceinline__ void ldsm4(unsigned int& ra, unsigned int& rb,
                                      unsigned int& rc, unsigned int& rd,
                                      unsigned int addr) {
    asm volatile("ldmatrix.sync.aligned.m8n8.x4.shared.b16 {%0,%1,%2,%3}, [%4];"
                 : "=r"(ra), "=r"(rb), "=r"(rc), "=r"(rd) : "r"(addr));
}

__device__ __forceinline__ void mma_bf16(float* dacc, const unsigned int* amat,
                                         const unsigned int* bmat) {
    asm volatile(
        "mma.sync.aligned.m16n8k16.row.col.f32.bf16.bf16.f32 "
        "{%0,%1,%2,%3}, {%4,%5,%6,%7}, {%8,%9}, {%0,%1,%2,%3};"
        : "+f"(dacc[0]), "+f"(dacc[1]), "+f"(dacc[2]), "+f"(dacc[3])
        : "r"(amat[0]), "r"(amat[1]), "r"(amat[2]), "r"(amat[3]),
          "r"(bmat[0]), "r"(bmat[1]));
}

#define CPASYNC16(dstaddr, srcptr) \
    asm volatile("cp.async.cg.shared.global [%0], [%1], 16;" \
                 :: "r"(dstaddr), "l"(srcptr))
#define CPCOMMIT() asm volatile("cp.async.commit_group;")
#define CPWAIT(nn) asm volatile("cp.async.wait_group %0;" :: "n"(nn))

// ---------------- fwd twiddle matrix T ----------------
__global__ void k_tabT() {
    int i = blockIdx.x * 256 + threadIdx.x;
    if (i < 128 * SQ / 2) {
        int sp  = i & (SQ / 2 - 1);
        int row = i >> 10;
        float v0 = 0.f, v1 = 0.f;
        if (row < 32) {
            float a0 = (float)(row * (2 * sp))     * (1.0f / 1024.0f);
            float a1 = (float)(row * (2 * sp + 1)) * (1.0f / 1024.0f);
            v0 = cospif(a0); v1 = cospif(a1);
        } else if (row < 64) {
            int m = row - 32;
            float a0 = (float)(m * (2 * sp))     * (1.0f / 1024.0f);
            float a1 = (float)(m * (2 * sp + 1)) * (1.0f / 1024.0f);
            v0 = -sinpif(a0); v1 = -sinpif(a1);
        }
        bfsplit2(v0, v1, g_T0[i], g_T1[i]);
    }
}

// ---------------- inverse twiddle matrix Tinv ----------------
__global__ void k_tabI() {
    int i = blockIdx.x * 256 + threadIdx.x;
    if (i < SQ * 32) {
        int kw = i & 31;
        int s  = i >> 5;
        int k0 = 2 * kw, k1 = 2 * kw + 1;
        float v0, v1;
        if (k0 < 32) {
            float c0 = (k0 == 0 ? 1.0f : 2.0f) / (float)SQ;
            float c1 = 2.0f / (float)SQ;
            v0 = c0 * cospif((float)(k0 * s) * (1.0f / 1024.0f));
            v1 = c1 * cospif((float)(k1 * s) * (1.0f / 1024.0f));
        } else {
            int m0 = k0 - 32, m1 = k1 - 32;
            float c0 = (m0 == 0 ? 1.0f : 2.0f) / (float)SQ;
            float c1 = 2.0f / (float)SQ;
            v0 = -c0 * sinpif((float)(m0 * s) * (1.0f / 1024.0f));
            v1 = -c1 * sinpif((float)(m1 * s) * (1.0f / 1024.0f));
        }
        bfsplit2(v0, v1, g_Ti0[i], g_Ti1[i]);
    }
}

// ---------------- h^T init ----------------
__global__ void k_initT(const float* __restrict__ x, const float* __restrict__ in_w,
                        const float* __restrict__ in_b) {
    int i = blockIdx.x * 256 + threadIdx.x;
    if (i < BQ * HQ * SQ / 2) {
        int sp = i & (SQ / 2 - 1);
        int bc = i >> 10;
        int c  = bc & (HQ - 1);
        int b  = bc >> 9;
        float wv = in_w[c], bv = in_b[c];
        float v0 = x[b * SQ + 2 * sp] * wv + bv;
        float v1 = x[b * SQ + 2 * sp + 1] * wv + bv;
        bfsplit2(v0, v1, g_hT0[i], g_hT1[i]);
    }
}

// ---------------- input projection ----------------
__global__ void k_init(const float* __restrict__ x, const float* __restrict__ in_w,
                       const float* __restrict__ in_b) {
    int i = blockIdx.x * 256 + threadIdx.x;
    if (i < BQ * SQ * HQ / 2) {
        int e0 = 2 * i;
        int c0 = e0 & (HQ - 1);
        int bs = e0 >> 9;
        float xv = x[bs];
        float v0 = xv * in_w[c0] + in_b[c0];
        float v1 = xv * in_w[c0 + 1] + in_b[c0 + 1];
        g_h[e0] = v0;
        g_h[e0 + 1] = v1;
        bfsplit2(v0, v1, g_A0[i], g_A1[i]);
    }
}

// ---------------- fp32 -> bf16 hi/lo (weights) ----------------
__global__ void k_cvt(const float* __restrict__ src, unsigned int* __restrict__ dsthi,
                      unsigned int* __restrict__ dstlo, int npairs) {
    int i = blockIdx.x * 256 + threadIdx.x;
    if (i < npairs) {
        bfsplit2(src[2 * i], src[2 * i + 1], dsthi[i], dstlo[i]);
    }
}

// ---------------- per-mode complex GEMM, 8-way h-split partials ----------------
// grid (MQ, 2, 8), block 256. k = blockIdx.y*256+tid, h in [hpart*64, +64)
__global__ void k_spec2(const float* __restrict__ Wr, const float* __restrict__ Wi) {
    int m = blockIdx.x, tid = threadIdx.x;
    int k = blockIdx.y * 256 + tid;
    int hpart = blockIdx.z;
    int h0 = hpart * 64;
    __shared__ float sXr[BQ][64];
    __shared__ float sXi[BQ][64];
    for (int i = tid; i < BQ * 64; i += 256) {
        int b = i >> 6, hh = i & 63;
        sXr[b][hh] = g_Xc[(size_t)m * (BQ * HQ) + b * HQ + h0 + hh];
        sXi[b][hh] = g_Xc[(size_t)(32 + m) * (BQ * HQ) + b * HQ + h0 + hh];
    }
    __syncthreads();
    float yr[BQ], yi[BQ];
#pragma unroll
    for (int b = 0; b < BQ; b++) { yr[b] = 0.f; yi[b] = 0.f; }
#pragma unroll 4
    for (int h = 0; h < 64; h++) {
        float wr = Wr[(size_t)(m * HQ + h0 + h) * HQ + k];
        float wi = Wi[(size_t)(m * HQ + h0 + h) * HQ + k];
#pragma unroll
        for (int b = 0; b < BQ; b++) {
            float xr = sXr[b][h], xi = sXi[b][h];
            yr[b] = fmaf(xr, wr, fmaf(-xi, wi, yr[b]));
            yi[b] = fmaf(xr, wi, fmaf( xi, wr, yi[b]));
        }
    }
#pragma unroll
    for (int b = 0; b < BQ; b++) {
        size_t o = ((size_t)(hpart * BQ + b) * MQ + m) * HQ + k;
        g_Psr[o] = yr[b];
        g_Psi[o] = yi[b];
    }
}

// ---------------- reduce 8 partials + pack to bf16 Ystack ----------------
// grid (HQ/64, BQ), block 256
__global__ void k_specred() {
    __shared__ float ySr[MQ][64];
    __shared__ float ySi[MQ][64];
    int c0 = blockIdx.x * 64;
    int b  = blockIdx.y;
    int tid = threadIdx.x;
    for (int idx = tid; idx < MQ * 64; idx += 256) {
        int c = idx & 63, m = idx >> 6;
        float sr = 0.f, si = 0.f;
#pragma unroll
        for (int part = 0; part < 8; part++) {
            size_t o = ((size_t)(part * BQ + b) * MQ + m) * HQ + c0 + c;
            sr += g_Psr[o];
            si += g_Psi[o];
        }
        ySr[m][c] = sr;
        ySi[m][c] = si;
    }
    __syncthreads();
    for (int idx = tid; idx < 64 * 32; idx += 256) {
        int kw = idx & 31, c = idx >> 5;
        int k0 = 2 * kw, k1 = 2 * kw + 1;
        float v0 = (k0 < 32) ? ySr[k0][c] : ySi[k0 - 32][c];
        float v1 = (k1 < 32) ? ySr[k1][c] : ySi[k1 - 32][c];
        unsigned int w0v, w1v;
        bfsplit2(v0, v1, w0v, w1v);
        size_t o = (size_t)(b * HQ + c0 + c) * 32 + kw;
        g_Ys0[o] = w0v;
        g_Ys1[o] = w1v;
    }
}

// ---------------- LN row kernel ----------------
__global__ void k_lnrow(const float* __restrict__ cb, const float* __restrict__ gg,
                        const float* __restrict__ bb) {
    int row = blockIdx.x, tid = threadIdx.x;
    int b = row >> 11, s = row & (SQ - 1);
    int j0 = tid * 4;
    float v[4], s1 = 0.f, s2 = 0.f;
#pragma unroll
    for (int i = 0; i < 4; i++) {
        int j = j0 + i;
        float t = g_y[(size_t)row * HQ + j] +
                  g_xfC[(size_t)s * (BQ * HQ) + b * HQ + j] + cb[j];
        v[i] = t; s1 += t; s2 += t * t;
    }
#pragma unroll
    for (int o = 16; o; o >>= 1) {
        s1 += __shfl_xor_sync(0xffffffffu, s1, o);
        s2 += __shfl_xor_sync(0xffffffffu, s2, o);
    }
    __shared__ float red[64];
    int w = tid >> 5;
    if ((tid & 31) == 0) { red[w] = s1; red[32 + w] = s2; }
    __syncthreads();
    float ts  = red[0] + red[1] + red[2] + red[3];
    float ts2 = red[32] + red[33] + red[34] + red[35];
    float mu  = ts * (1.f / HQ);
    float var = ts2 * (1.f / HQ) - mu * mu;
    float rinv = rsqrtf(var + 1e-5f);
    float hv[4];
#pragma unroll
    for (int i = 0; i < 4; i++) {
        int j = j0 + i;
        size_t idx = (size_t)row * HQ + j;
        hv[i] = (v[i] - mu) * rinv * gg[j] + bb[j] + g_h[idx];
        g_h[idx] = hv[i];
    }
    size_t wbase = (size_t)row * (HQ / 2) + tid * 2;
    bfsplit2(hv[0], hv[1], g_A0[wbase], g_A1[wbase]);
    bfsplit2(hv[2], hv[3], g_A0[wbase + 1], g_A1[wbase + 1]);
}

// ---------------- h -> hT transpose ----------------
__global__ void k_hTt() {
    __shared__ float tile[64][33];
    int s0 = blockIdx.x * 64;
    int c0 = blockIdx.y * 32;
    int b  = blockIdx.z;
    int tid = threadIdx.x;
    for (int i = tid; i < 64 * 32; i += 256) {
        int si = i >> 5, ci = i & 31;
        tile[si][ci] = g_h[(size_t)(b * SQ + s0 + si) * HQ + c0 + ci];
    }
    __syncthreads();
    for (int i = tid; i < 32 * 32; i += 256) {
        int ci = i >> 5, spi = i & 31;
        unsigned int w0v, w1v;
        bfsplit2(tile[2 * spi][ci], tile[2 * spi + 1][ci], w0v, w1v);
        size_t o = ((size_t)(b * HQ + c0 + ci) << 10) + (size_t)(s0 >> 1) + spi;
        g_hT0[o] = w0v;
        g_hT1[o] = w1v;
    }
}

// ============ 3xBF16 tensor-core GEMM (hi/lo compensated) ============
#define STG_WORDS 12288

__device__ __forceinline__ void issue_slab(
    unsigned int smemBase, int stageSel,
    const unsigned int* __restrict__ Amat0, const unsigned int* __restrict__ Amat1,
    const unsigned int* __restrict__ Bmat0, const unsigned int* __restrict__ Bmat1,
    int rowBase, int colBase, int Kw, int kw, int tid)
{
#pragma unroll
    for (int it = 0; it < 4; it++) {
        int idx = tid + it * 256;
        int row = idx >> 3, chk = idx & 7;
        unsigned int woff = (unsigned int)(stageSel * STG_WORDS + row * 32 +
                                           ((chk ^ (row & 7)) << 2));
        size_t gsrc = (size_t)(rowBase + row) * Kw + kw + chk * 4;
        CPASYNC16(smemBase + woff * 4, Amat0 + gsrc);
        CPASYNC16(smemBase + (woff + 4096) * 4, Amat1 + gsrc);
    }
#pragma unroll
    for (int it = 0; it < 2; it++) {
        int idx = tid + it * 256;
        int row = idx >> 3, chk = idx & 7;
        unsigned int woff = (unsigned int)(stageSel * STG_WORDS + 8192 + row * 32 +
                                           ((chk ^ (row & 7)) << 2));
        size_t gsrc = (size_t)(colBase + row) * Kw + kw + chk * 4;
        CPASYNC16(smemBase + woff * 4, Bmat0 + gsrc);
        CPASYNC16(smemBase + (woff + 2048) * 4, Bmat1 + gsrc);
    }
}

__global__ void __launch_bounds__(256, 2)
k_gemm_tc2(const unsigned int* __restrict__ Amat0, const unsigned int* __restrict__ Amat1,
           const unsigned int* __restrict__ Bmat0, const unsigned int* __restrict__ Bmat1,
           float* __restrict__ Cmat, int Mdim, int Ndim, int Kdim,
           const float* __restrict__ biasPtr, int gmode,
           unsigned int* __restrict__ Cout0, unsigned int* __restrict__ Cout1) {
    extern __shared__ unsigned int shMem[];
    const int tid  = threadIdx.x;
    const int lane = tid & 31;
    const int warpIdx = tid >> 5;
    const int wmoff = (warpIdx & 3) * 32;
    const int wnoff = (warpIdx >> 2) * 32;
    const int rowBase = blockIdx.x * 128;
    const int colBase = blockIdx.y * 64;
    const int Kw = Kdim >> 1;

    const unsigned int smemBase = (unsigned int)__cvta_generic_to_shared(shMem);

    const int arowA = wmoff + (lane & 15);
    const int achA  = lane >> 4;
    const int browB = wnoff + ((lane >> 4) << 3) + (lane & 7);
    const int bchB  = (lane >> 3) & 1;

    float acc[2][4][4];
#pragma unroll
    for (int fi = 0; fi < 2; fi++)
#pragma unroll
        for (int ji = 0; ji < 4; ji++)
#pragma unroll
            for (int ci = 0; ci < 4; ci++) acc[fi][ji][ci] = 0.0f;

    const int nSlab = Kw >> 5;
    issue_slab(smemBase, 0, Amat0, Amat1, Bmat0, Bmat1, rowBase, colBase, Kw, 0, tid);
    CPCOMMIT();

    for (int is = 0; is < nSlab; is++) {
        const int stagec = is & 1;
        if (is + 1 < nSlab) {
            issue_slab(smemBase, (is + 1) & 1, Amat0, Amat1, Bmat0, Bmat1,
                       rowBase, colBase, Kw, (is + 1) << 5, tid);
            CPCOMMIT();
            CPWAIT(1);
        } else {
            CPWAIT(0);
        }
        __syncthreads();

        const unsigned int stW = (unsigned int)(stagec * STG_WORDS);
#pragma unroll
        for (int gi = 0; gi < 4; gi++) {
            unsigned int fragA0[2][4];
            unsigned int fragA1[2][4];
            unsigned int fragB0[4][2];
            unsigned int fragB1[4][2];
#pragma unroll
            for (int fi = 0; fi < 2; fi++) {
                int rr = arowA + fi * 16;
                int chq = 2 * gi + achA;
                unsigned int byoff = (stW + rr * 32 + ((chq ^ (rr & 7)) << 2)) << 2;
                ldsm4(fragA0[fi][0], fragA0[fi][1], fragA0[fi][2], fragA0[fi][3],
                      smemBase + byoff);
                ldsm4(fragA1[fi][0], fragA1[fi][1], fragA1[fi][2], fragA1[fi][3],
                      smemBase + byoff + 4096 * 4);
            }
#pragma unroll
            for (int pj = 0; pj < 2; pj++) {
                int rr = browB + pj * 16;
                int chq = 2 * gi + bchB;
                unsigned int byoff = (stW + 8192 + rr * 32 + ((chq ^ (rr & 7)) << 2)) << 2;
                unsigned int tqa[4];
                ldsm4(tqa[0], tqa[1], tqa[2], tqa[3], smemBase + byoff);
                fragB0[2 * pj + 0][0] = tqa[0];
                fragB0[2 * pj + 0][1] = tqa[1];
                fragB0[2 * pj + 1][0] = tqa[2];
                fragB0[2 * pj + 1][1] = tqa[3];
                unsigned int tqb[4];
                ldsm4(tqb[0], tqb[1], tqb[2], tqb[3], smemBase + byoff + 2048 * 4);
                fragB1[2 * pj + 0][0] = tqb[0];
                fragB1[2 * pj + 0][1] = tqb[1];
                fragB1[2 * pj + 1][0] = tqb[2];
                fragB1[2 * pj + 1][1] = tqb[3];
            }
#pragma unroll
            for (int fi = 0; fi < 2; fi++) {
#pragma unroll
                for (int ji = 0; ji < 4; ji++) {
                    mma_bf16(acc[fi][ji], fragA0[fi], fragB0[ji]);
                    mma_bf16(acc[fi][ji], fragA1[fi], fragB0[ji]);
                    mma_bf16(acc[fi][ji], fragA0[fi], fragB1[ji]);
                }
            }
        }
        __syncthreads();
    }

    const int Ndw = Ndim >> 1;
#pragma unroll
    for (int fi = 0; fi < 2; fi++) {
#pragma unroll
        for (int ji = 0; ji < 4; ji++) {
            int orow = rowBase + wmoff + fi * 16 + (lane >> 2);
            int ocol = colBase + wnoff + ji * 8 + (lane & 3) * 2;
            float outA = acc[fi][ji][0];
            float outB = acc[fi][ji][1];
            float outC = acc[fi][ji][2];
            float outD = acc[fi][ji][3];
            if (gmode != 0) {
                float biasLo = biasPtr[ocol];
                float biasHi = biasPtr[ocol + 1];
                outA = gelu_exact(outA + biasLo);
                outB = gelu_exact(outB + biasHi);
                outC = gelu_exact(outC + biasLo);
                outD = gelu_exact(outD + biasHi);
            }
            if (gmode == 3) {
                size_t widx0 = (size_t)orow * Ndw + (ocol >> 1);
                size_t widx1 = (size_t)(orow + 8) * Ndw + (ocol >> 1);
                bfsplit2(outA, outB, Cout0[widx0], Cout1[widx0]);
                bfsplit2(outC, outD, Cout0[widx1], Cout1[widx1]);
            } else {
                *(float2*)&Cmat[(size_t)orow * Ndim + ocol] = make_float2(outA, outB);
                *(float2*)&Cmat[(size_t)(orow + 8) * Ndim + ocol] = make_float2(outC, outD);
            }
        }
    }
}

// ---------------- final projection to scalar ----------------
__global__ void k_op3(const float* __restrict__ w, const float* __restrict__ b3,
                      float* __restrict__ out) {
    int tid = threadIdx.x;
    int row = blockIdx.x * 4 + (tid >> 5);
    int lane = tid & 31;
    float s = 0.f;
#pragma unroll
    for (int i = 0; i < 4; i++) {
        int j = lane + i * 32;
        s += g_o2[(size_t)row * 128 + j] * w[j];
    }
#pragma unroll
    for (int o = 16; o; o >>= 1) s += __shfl_xor_sync(0xffffffffu, s, o);
    if (lane == 0) out[row] = s + b3[0];
}

// ---------------- mean over s (two-stage) ----------------
__global__ void k_mean1() {
    int part = blockIdx.y;
    int b = blockIdx.x >> 2;
    int c = (blockIdx.x & 3) * 128 + threadIdx.x;
    float s = 0.f;
    int sbeg = part * (SQ / 16);
    for (int ss = sbeg; ss < sbeg + (SQ / 16); ss++)
        s += g_h[(size_t)(b * SQ + ss) * HQ + c];
    g_mred[part * (BQ * HQ) + b * HQ + c] = s;
}

__global__ void k_mean2() {
    int i = blockIdx.x * 256 + threadIdx.x;
    if (i < BQ * HQ) {
        float s = 0.f;
#pragma unroll
        for (int part = 0; part < 16; part++) s += g_mred[part * (BQ * HQ) + i];
        g_gf[i] = s * (1.f / SQ);
    }
}

// ---------------- head kernels ----------------
__global__ void k_head1(const float* __restrict__ w, const float* __restrict__ bias) {
    int b = blockIdx.x, tid = threadIdx.x;
    int j = blockIdx.y * 128 + tid;
    __shared__ float sg[HQ];
    for (int i = tid; i < HQ; i += 128) sg[i] = g_gf[b * HQ + i];
    __syncthreads();
    const float4* w4 = (const float4*)(w + (size_t)j * HQ);
    float acc = 0.f;
    for (int c = 0; c < HQ / 4; c++) {
        float4 wv = w4[c];
        float4 gv = *(const float4*)&sg[c * 4];
        acc = fmaf(wv.x, gv.x, acc); acc = fmaf(wv.y, gv.y, acc);
        acc = fmaf(wv.z, gv.z, acc); acc = fmaf(wv.w, gv.w, acc);
    }
    g_k1[b * HQ + j] = gelu_exact(acc + bias[j]);
}

__global__ void k_head2(const float* __restrict__ w, const float* __restrict__ bias,
                        float* __restrict__ out) {
    int b = blockIdx.x, tid = threadIdx.x;
    int j = blockIdx.y * 128 + tid;
    __shared__ float sk[HQ];
    for (int i = tid; i < HQ; i += 128) sk[i] = g_k1[b * HQ + i];
    __syncthreads();
    const float4* w4 = (const float4*)(w + (size_t)j * HQ);
    float acc = 0.f;
    for (int c = 0; c < HQ / 4; c++) {
        float4 wv = w4[c];
        float4 kv = *(const float4*)&sk[c * 4];
        acc = fmaf(wv.x, kv.x, acc); acc = fmaf(wv.y, kv.y, acc);
        acc = fmaf(wv.z, kv.z, acc); acc = fmaf(wv.w, kv.w, acc);
    }
    float t = acc + bias[j];
    out[BQ * SQ + b * KBQ + j] = 1.f / (1.f + expf(-t));
}

// ---------------- launch ----------------
extern "C" void kernel_launch(void* const* d_in, const int* in_sizes, int n_in,
                              void* d_out, int out_size) {
    const float* x      = (const float*)d_in[0];
    const float* in_w   = (const float*)d_in[1];
    const float* in_b   = (const float*)d_in[2];
    const float* fw_r   = (const float*)d_in[3];
    const float* fw_i   = (const float*)d_in[4];
    const float* conv_w = (const float*)d_in[5];
    const float* conv_b = (const float*)d_in[6];
    const float* ln_g   = (const float*)d_in[7];
    const float* ln_b   = (const float*)d_in[8];
    const float* op1_w  = (const float*)d_in[9];
    const float* op1_b  = (const float*)d_in[10];
    const float* op2_w  = (const float*)d_in[11];
    const float* op2_b  = (const float*)d_in[12];
    const float* op3_w  = (const float*)d_in[13];
    const float* op3_b  = (const float*)d_in[14];
    const float* h1_w   = (const float*)d_in[15];
    const float* h1_b   = (const float*)d_in[16];
    const float* h2_w   = (const float*)d_in[17];
    const float* h2_b   = (const float*)d_in[18];
    float* out = (float*)d_out;

    float *yp, *o2p, *xcp, *xfp;
    unsigned int *a0p, *a1p, *w0p, *w1p, *o10p, *o11p;
    unsigned int *t0p, *t1p, *ti0p, *ti1p, *ht0p, *ht1p, *ys0p, *ys1p;
    cudaGetSymbolAddress((void**)&yp,  g_y);
    cudaGetSymbolAddress((void**)&o2p, g_o2);
    cudaGetSymbolAddress((void**)&xcp, g_Xc);
    cudaGetSymbolAddress((void**)&xfp, g_xfC);
    cudaGetSymbolAddress((void**)&a0p, g_A0);
    cudaGetSymbolAddress((void**)&a1p, g_A1);
    cudaGetSymbolAddress((void**)&w0p, g_W0);
    cudaGetSymbolAddress((void**)&w1p, g_W1);
    cudaGetSymbolAddress((void**)&o10p, g_o10);
    cudaGetSymbolAddress((void**)&o11p, g_o11);
    cudaGetSymbolAddress((void**)&t0p, g_T0);
    cudaGetSymbolAddress((void**)&t1p, g_T1);
    cudaGetSymbolAddress((void**)&ti0p, g_Ti0);
    cudaGetSymbolAddress((void**)&ti1p, g_Ti1);
    cudaGetSymbolAddress((void**)&ht0p, g_hT0);
    cudaGetSymbolAddress((void**)&ht1p, g_hT1);
    cudaGetSymbolAddress((void**)&ys0p, g_Ys0);
    cudaGetSymbolAddress((void**)&ys1p, g_Ys1);

    static int smemSet = 0;
    if (!smemSet) {
        cudaFuncSetAttribute(k_gemm_tc2, cudaFuncAttributeMaxDynamicSharedMemorySize,
                             2 * STG_WORDS * 4);
        smemSet = 1;
    }
    const int dynSmem = 2 * STG_WORDS * 4;

    const int convWPairs = LQ * HQ * HQ / 2;
    const int op1WOff    = convWPairs;
    const int op1WPairs  = (HQ / 2) * HQ / 2;
    const int op2WOff    = convWPairs + op1WPairs;
    const int op2WPairs  = (HQ / 4) * (HQ / 2) / 2;
    const int hPairs     = BQ * SQ * HQ / 2;
    const int htWords    = BQ * HQ * SQ / 2;

    // prologue; launch #4 = k_spec2 layer 0 (ncu capture slot)
    k_tabT<<<(128 * SQ / 2 + 255) / 256, 256>>>();
    k_initT<<<(htWords + 255) / 256, 256>>>(x, in_w, in_b);
    k_gemm_tc2<<<dim3(1, BQ * HQ / 64), 256, dynSmem>>>(
        t0p, t1p, ht0p, ht1p, xcp, 128, BQ * HQ, SQ,
        (const float*)0, 0, (unsigned int*)0, (unsigned int*)0);
    k_spec2<<<dim3(MQ, 2, 8), 256>>>(fw_r, fw_i);
    k_specred<<<dim3(HQ / 64, BQ), 256>>>();
    k_tabI<<<(SQ * 32 + 255) / 256, 256>>>();
    k_init<<<(hPairs + 255) / 256, 256>>>(x, in_w, in_b);
    k_cvt<<<(convWPairs + 255) / 256, 256>>>(conv_w, w0p, w1p, convWPairs);
    k_cvt<<<(op1WPairs + 255) / 256, 256>>>(op1_w, w0p + op1WOff, w1p + op1WOff, op1WPairs);
    k_cvt<<<(op2WPairs + 255) / 256, 256>>>(op2_w, w0p + op2WOff, w1p + op2WOff, op2WPairs);

    for (int l = 0; l < LQ; l++) {
        if (l > 0) {
            k_gemm_tc2<<<dim3(1, BQ * HQ / 64), 256, dynSmem>>>(
                t0p, t1p, ht0p, ht1p, xcp, 128, BQ * HQ, SQ,
                (const float*)0, 0, (unsigned int*)0, (unsigned int*)0);
            k_spec2<<<dim3(MQ, 2, 8), 256>>>(fw_r + (size_t)l * MQ * HQ * HQ,
                                             fw_i + (size_t)l * MQ * HQ * HQ);
            k_specred<<<dim3(HQ / 64, BQ), 256>>>();
        }
        // conv GEMM (independent of fourier branch)
        k_gemm_tc2<<<dim3(BQ * SQ / 128, HQ / 64), 256, dynSmem>>>(
            a0p, a1p, w0p + (size_t)l * HQ * HQ / 2, w1p + (size_t)l * HQ * HQ / 2,
            yp, BQ * SQ, HQ, HQ, (const float*)0, 0,
            (unsigned int*)0, (unsigned int*)0);
        // inverse DFT GEMM: xfC[s][(b,c)]
        k_gemm_tc2<<<dim3(SQ / 128, BQ * HQ / 64), 256, dynSmem>>>(
            ti0p, ti1p, ys0p, ys1p, xfp, SQ, BQ * HQ, 64,
            (const float*)0, 0, (unsigned int*)0, (unsigned int*)0);
        k_lnrow<<<BQ * SQ, 128>>>(conv_b + l * HQ, ln_g + l * HQ, ln_b + l * HQ);
        if (l < LQ - 1)
            k_hTt<<<dim3(SQ / 64, HQ / 32, BQ), 256>>>();
    }

    // output projection: H -> H/2 -> H/4 -> 1
    k_gemm_tc2<<<dim3(BQ * SQ / 128, (HQ / 2) / 64), 256, dynSmem>>>(
        a0p, a1p, w0p + op1WOff, w1p + op1WOff, yp, BQ * SQ, HQ / 2, HQ,
        op1_b, 3, o10p, o11p);
    k_gemm_tc2<<<dim3(BQ * SQ / 128, (HQ / 4) / 64), 256, dynSmem>>>(
        o10p, o11p, w0p + op2WOff, w1p + op2WOff, o2p, BQ * SQ, HQ / 4, HQ / 2,
        op2_b, 1, (unsigned int*)0, (unsigned int*)0);
    k_op3<<<BQ * SQ / 4, 128>>>(op3_w, op3_b, out);

    // cryptanalytic head
    k_mean1<<<dim3(BQ * 4, 16), 128>>>();
    k_mean2<<<(BQ * HQ + 255) / 256, 256>>>();
    k_head1<<<dim3(BQ, HQ / 128), 128>>>(h1_w, h1_b);
    k_head2<<<dim3(BQ, KBQ / 128), 128>>>(h2_w, h2_b, out);
}

// round 15
// speedup vs baseline: 2.3110x; 1.1498x over previous
#include <cuda_runtime.h>
#include <cstdint>
#include <stdint.h>
#include <math.h>

#define BQ 8
#define SQ 2048
#define HQ 512
#define LQ 8
#define MQ 32
#define KBQ 256

// ---------------- scratch (device globals, allocation-free) ----------------
__device__ float  g_h [BQ*SQ*HQ];           // hidden state [B,S,H]
__device__ float  g_y [BQ*SQ*HQ];           // conv GEMM out
__device__ float  g_xfC[SQ*BQ*HQ];          // inv DFT out [s][(b*H+c)]
__device__ float  g_Xc[4*BQ*HQ*64];         // fwd DFT K-partials: [part][(b*H+c)][64]
__device__ float  g_Psr[8*BQ*MQ*HQ];        // spec partials (real)
__device__ float  g_Psi[8*BQ*MQ*HQ];        // spec partials (imag)
__device__ float  g_o2[BQ*SQ*(HQ/4)];
__device__ float  g_gf[BQ*HQ];
__device__ float  g_k1[BQ*HQ];
__device__ float  g_mred[16*BQ*HQ];

// bf16 hi/lo packed operands (2 bf16 per word)
#define WTOT (LQ*HQ*HQ + (HQ/2)*HQ + (HQ/4)*(HQ/2))
__device__ unsigned int g_A0[BQ*SQ*HQ/2];   // h pairs along H
__device__ unsigned int g_A1[BQ*SQ*HQ/2];
__device__ unsigned int g_W0[WTOT/2];
__device__ unsigned int g_W1[WTOT/2];
__device__ unsigned int g_o10[BQ*SQ*(HQ/2)/2];
__device__ unsigned int g_o11[BQ*SQ*(HQ/2)/2];
__device__ unsigned int g_T0[128*SQ/2];     // fwd twiddle [128 rows][1024 words] (rows 0-63 used)
__device__ unsigned int g_T1[128*SQ/2];
__device__ unsigned int g_Ti0[SQ*32];       // inv twiddle [2048 rows][32 words]
__device__ unsigned int g_Ti1[SQ*32];
__device__ unsigned int g_hT0[BQ*HQ*SQ/2];  // h^T[(b*H+c)][s-pairs]
__device__ unsigned int g_hT1[BQ*HQ*SQ/2];
__device__ unsigned int g_Ys0[BQ*HQ*32];    // Y stacked [(b*H+c)][32 words = 64 k]
__device__ unsigned int g_Ys1[BQ*HQ*32];

__device__ __forceinline__ float gelu_exact(float x) {
    return 0.5f * x * (1.0f + erff(x * 0.70710678118654752440f));
}

// ---------------- bf16 helpers ----------------
__device__ __forceinline__ unsigned int bfpack(float x0, float x1) {
    unsigned int rr;
    asm("cvt.rn.bf16x2.f32 %0, %1, %2;" : "=r"(rr) : "f"(x1), "f"(x0));
    return rr;
}

__device__ __forceinline__ void bfsplit2(float x0, float x1,
                                         unsigned int& whi, unsigned int& wlo) {
    unsigned int hic = bfpack(x0, x1);
    float res0 = x0 - __uint_as_float(hic << 16);
    float res1 = x1 - __uint_as_float(hic & 0xffff0000u);
    whi = hic;
    wlo = bfpack(res0, res1);
}

__device__ __forceinline__ void ldsm4(unsigned int& ra, unsigned int& rb,
                                      unsigned int& rc, unsigned int& rd,
                                      unsigned int addr) {
    asm volatile("ldmatrix.sync.aligned.m8n8.x4.shared.b16 {%0,%1,%2,%3}, [%4];"
                 : "=r"(ra), "=r"(rb), "=r"(rc), "=r"(rd) : "r"(addr));
}

__device__ __forceinline__ void mma_bf16(float* dacc, const unsigned int* amat,
                                         const unsigned int* bmat) {
    asm volatile(
        "mma.sync.aligned.m16n8k16.row.col.f32.bf16.bf16.f32 "
        "{%0,%1,%2,%3}, {%4,%5,%6,%7}, {%8,%9}, {%0,%1,%2,%3};"
        : "+f"(dacc[0]), "+f"(dacc[1]), "+f"(dacc[2]), "+f"(dacc[3])
        : "r"(amat[0]), "r"(amat[1]), "r"(amat[2]), "r"(amat[3]),
          "r"(bmat[0]), "r"(bmat[1]));
}

#define CPASYNC16(dstaddr, srcptr) \
    asm volatile("cp.async.cg.shared.global [%0], [%1], 16;" \
                 :: "r"(dstaddr), "l"(srcptr))
#define CPCOMMIT() asm volatile("cp.async.commit_group;")
#define CPWAIT(nn) asm volatile("cp.async.wait_group %0;" :: "n"(nn))

// ---------------- fwd twiddle matrix T ----------------
__global__ void k_tabT() {
    int i = blockIdx.x * 256 + threadIdx.x;
    if (i < 128 * SQ / 2) {
        int sp  = i & (SQ / 2 - 1);
        int row = i >> 10;
        float v0 = 0.f, v1 = 0.f;
        if (row < 32) {
            float a0 = (float)(row * (2 * sp))     * (1.0f / 1024.0f);
            float a1 = (float)(row * (2 * sp + 1)) * (1.0f / 1024.0f);
            v0 = cospif(a0); v1 = cospif(a1);
        } else if (row < 64) {
            int m = row - 32;
            float a0 = (float)(m * (2 * sp))     * (1.0f / 1024.0f);
            float a1 = (float)(m * (2 * sp + 1)) * (1.0f / 1024.0f);
            v0 = -sinpif(a0); v1 = -sinpif(a1);
        }
        bfsplit2(v0, v1, g_T0[i], g_T1[i]);
    }
}

// ---------------- inverse twiddle matrix Tinv ----------------
__global__ void k_tabI() {
    int i = blockIdx.x * 256 + threadIdx.x;
    if (i < SQ * 32) {
        int kw = i & 31;
        int s  = i >> 5;
        int k0 = 2 * kw, k1 = 2 * kw + 1;
        float v0, v1;
        if (k0 < 32) {
            float c0 = (k0 == 0 ? 1.0f : 2.0f) / (float)SQ;
            float c1 = 2.0f / (float)SQ;
            v0 = c0 * cospif((float)(k0 * s) * (1.0f / 1024.0f));
            v1 = c1 * cospif((float)(k1 * s) * (1.0f / 1024.0f));
        } else {
            int m0 = k0 - 32, m1 = k1 - 32;
            float c0 = (m0 == 0 ? 1.0f : 2.0f) / (float)SQ;
            float c1 = 2.0f / (float)SQ;
            v0 = -c0 * sinpif((float)(m0 * s) * (1.0f / 1024.0f));
            v1 = -c1 * sinpif((float)(m1 * s) * (1.0f / 1024.0f));
        }
        bfsplit2(v0, v1, g_Ti0[i], g_Ti1[i]);
    }
}

// ---------------- h^T init ----------------
__global__ void k_initT(const float* __restrict__ x, const float* __restrict__ in_w,
                        const float* __restrict__ in_b) {
    int i = blockIdx.x * 256 + threadIdx.x;
    if (i < BQ * HQ * SQ / 2) {
        int sp = i & (SQ / 2 - 1);
        int bc = i >> 10;
        int c  = bc & (HQ - 1);
        int b  = bc >> 9;
        float wv = in_w[c], bv = in_b[c];
        float v0 = x[b * SQ + 2 * sp] * wv + bv;
        float v1 = x[b * SQ + 2 * sp + 1] * wv + bv;
        bfsplit2(v0, v1, g_hT0[i], g_hT1[i]);
    }
}

// ---------------- input projection ----------------
__global__ void k_init(const float* __restrict__ x, const float* __restrict__ in_w,
                       const float* __restrict__ in_b) {
    int i = blockIdx.x * 256 + threadIdx.x;
    if (i < BQ * SQ * HQ / 2) {
        int e0 = 2 * i;
        int c0 = e0 & (HQ - 1);
        int bs = e0 >> 9;
        float xv = x[bs];
        float v0 = xv * in_w[c0] + in_b[c0];
        float v1 = xv * in_w[c0 + 1] + in_b[c0 + 1];
        g_h[e0] = v0;
        g_h[e0 + 1] = v1;
        bfsplit2(v0, v1, g_A0[i], g_A1[i]);
    }
}

// ---------------- fp32 -> bf16 hi/lo (weights) ----------------
__global__ void k_cvt(const float* __restrict__ src, unsigned int* __restrict__ dsthi,
                      unsigned int* __restrict__ dstlo, int npairs) {
    int i = blockIdx.x * 256 + threadIdx.x;
    if (i < npairs) {
        bfsplit2(src[2 * i], src[2 * i + 1], dsthi[i], dstlo[i]);
    }
}

// ---------------- per-mode complex GEMM, 8-way h-split, chain-split accs ----------------
// grid (MQ, 2, 8), block 256. k = blockIdx.y*256+tid, h in [hpart*64, +64)
// Xc layout: [part 0..3][(b*H+c)][64] (cols 0-31 Xr, 32-63 Xi); sum 4 K-parts on load.
__global__ void k_spec2(const float* __restrict__ Wr, const float* __restrict__ Wi) {
    int m = blockIdx.x, tid = threadIdx.x;
    int k = blockIdx.y * 256 + tid;
    int hpart = blockIdx.z;
    int h0 = hpart * 64;
    __shared__ float sXr[BQ][64];
    __shared__ float sXi[BQ][64];
    for (int i = tid; i < BQ * 64; i += 256) {
        int b = i >> 6, hh = i & 63;
        size_t base = (size_t)(b * HQ + h0 + hh) * 64;
        float xrS = 0.f, xiS = 0.f;
#pragma unroll
        for (int part = 0; part < 4; part++) {
            xrS += g_Xc[(size_t)part * (BQ * HQ * 64) + base + m];
            xiS += g_Xc[(size_t)part * (BQ * HQ * 64) + base + 32 + m];
        }
        sXr[b][hh] = xrS;
        sXi[b][hh] = xiS;
    }
    __syncthreads();
    float yrc[BQ], yrs[BQ], yic[BQ], yis[BQ];
#pragma unroll
    for (int b = 0; b < BQ; b++) { yrc[b] = 0.f; yrs[b] = 0.f; yic[b] = 0.f; yis[b] = 0.f; }
#pragma unroll 4
    for (int h = 0; h < 64; h++) {
        float wr = Wr[(size_t)(m * HQ + h0 + h) * HQ + k];
        float wi = Wi[(size_t)(m * HQ + h0 + h) * HQ + k];
#pragma unroll
        for (int b = 0; b < BQ; b++) {
            float xr = sXr[b][h], xi = sXi[b][h];
            yrc[b] = fmaf(xr, wr, yrc[b]);
            yrs[b] = fmaf(xi, wi, yrs[b]);
            yic[b] = fmaf(xr, wi, yic[b]);
            yis[b] = fmaf(xi, wr, yis[b]);
        }
    }
#pragma unroll
    for (int b = 0; b < BQ; b++) {
        size_t o = ((size_t)(hpart * BQ + b) * MQ + m) * HQ + k;
        g_Psr[o] = yrc[b] - yrs[b];
        g_Psi[o] = yic[b] + yis[b];
    }
}

// ---------------- reduce 8 partials + pack to bf16 Ystack ----------------
// grid (HQ/64, BQ), block 256
__global__ void k_specred() {
    __shared__ float ySr[MQ][64];
    __shared__ float ySi[MQ][64];
    int c0 = blockIdx.x * 64;
    int b  = blockIdx.y;
    int tid = threadIdx.x;
    for (int idx = tid; idx < MQ * 64; idx += 256) {
        int c = idx & 63, m = idx >> 6;
        float sr = 0.f, si = 0.f;
#pragma unroll
        for (int part = 0; part < 8; part++) {
            size_t o = ((size_t)(part * BQ + b) * MQ + m) * HQ + c0 + c;
            sr += g_Psr[o];
            si += g_Psi[o];
        }
        ySr[m][c] = sr;
        ySi[m][c] = si;
    }
    __syncthreads();
    for (int idx = tid; idx < 64 * 32; idx += 256) {
        int kw = idx & 31, c = idx >> 5;
        int k0 = 2 * kw, k1 = 2 * kw + 1;
        float v0 = (k0 < 32) ? ySr[k0][c] : ySi[k0 - 32][c];
        float v1 = (k1 < 32) ? ySr[k1][c] : ySi[k1 - 32][c];
        unsigned int w0v, w1v;
        bfsplit2(v0, v1, w0v, w1v);
        size_t o = (size_t)(b * HQ + c0 + c) * 32 + kw;
        g_Ys0[o] = w0v;
        g_Ys1[o] = w1v;
    }
}

// ---------------- LN row kernel ----------------
__global__ void k_lnrow(const float* __restrict__ cb, const float* __restrict__ gg,
                        const float* __restrict__ bb) {
    int row = blockIdx.x, tid = threadIdx.x;
    int b = row >> 11, s = row & (SQ - 1);
    int j0 = tid * 4;
    float v[4], s1 = 0.f, s2 = 0.f;
#pragma unroll
    for (int i = 0; i < 4; i++) {
        int j = j0 + i;
        float t = g_y[(size_t)row * HQ + j] +
                  g_xfC[(size_t)s * (BQ * HQ) + b * HQ + j] + cb[j];
        v[i] = t; s1 += t; s2 += t * t;
    }
#pragma unroll
    for (int o = 16; o; o >>= 1) {
        s1 += __shfl_xor_sync(0xffffffffu, s1, o);
        s2 += __shfl_xor_sync(0xffffffffu, s2, o);
    }
    __shared__ float red[64];
    int w = tid >> 5;
    if ((tid & 31) == 0) { red[w] = s1; red[32 + w] = s2; }
    __syncthreads();
    float ts  = red[0] + red[1] + red[2] + red[3];
    float ts2 = red[32] + red[33] + red[34] + red[35];
    float mu  = ts * (1.f / HQ);
    float var = ts2 * (1.f / HQ) - mu * mu;
    float rinv = rsqrtf(var + 1e-5f);
    float hv[4];
#pragma unroll
    for (int i = 0; i < 4; i++) {
        int j = j0 + i;
        size_t idx = (size_t)row * HQ + j;
        hv[i] = (v[i] - mu) * rinv * gg[j] + bb[j] + g_h[idx];
        g_h[idx] = hv[i];
    }
    size_t wbase = (size_t)row * (HQ / 2) + tid * 2;
    bfsplit2(hv[0], hv[1], g_A0[wbase], g_A1[wbase]);
    bfsplit2(hv[2], hv[3], g_A0[wbase + 1], g_A1[wbase + 1]);
}

// ---------------- h -> hT transpose ----------------
__global__ void k_hTt() {
    __shared__ float tile[64][33];
    int s0 = blockIdx.x * 64;
    int c0 = blockIdx.y * 32;
    int b  = blockIdx.z;
    int tid = threadIdx.x;
    for (int i = tid; i < 64 * 32; i += 256) {
        int si = i >> 5, ci = i & 31;
        tile[si][ci] = g_h[(size_t)(b * SQ + s0 + si) * HQ + c0 + ci];
    }
    __syncthreads();
    for (int i = tid; i < 32 * 32; i += 256) {
        int ci = i >> 5, spi = i & 31;
        unsigned int w0v, w1v;
        bfsplit2(tile[2 * spi][ci], tile[2 * spi + 1][ci], w0v, w1v);
        size_t o = ((size_t)(b * HQ + c0 + ci) << 10) + (size_t)(s0 >> 1) + spi;
        g_hT0[o] = w0v;
        g_hT1[o] = w1v;
    }
}

// ============ 3xBF16 tensor-core GEMM (hi/lo compensated, gridDim.z K-split) ============
// With gridDim.z > 1: block z computes partial over K-window z, writing C + z*M*N.
#define STG_WORDS 12288

__device__ __forceinline__ void issue_slab(
    unsigned int smemBase, int stageSel,
    const unsigned int* __restrict__ Amat0, const unsigned int* __restrict__ Amat1,
    const unsigned int* __restrict__ Bmat0, const unsigned int* __restrict__ Bmat1,
    int rowBase, int colBase, int Kw, int kw, int tid)
{
#pragma unroll
    for (int it = 0; it < 4; it++) {
        int idx = tid + it * 256;
        int row = idx >> 3, chk = idx & 7;
        unsigned int woff = (unsigned int)(stageSel * STG_WORDS + row * 32 +
                                           ((chk ^ (row & 7)) << 2));
        size_t gsrc = (size_t)(rowBase + row) * Kw + kw + chk * 4;
        CPASYNC16(smemBase + woff * 4, Amat0 + gsrc);
        CPASYNC16(smemBase + (woff + 4096) * 4, Amat1 + gsrc);
    }
#pragma unroll
    for (int it = 0; it < 2; it++) {
        int idx = tid + it * 256;
        int row = idx >> 3, chk = idx & 7;
        unsigned int woff = (unsigned int)(stageSel * STG_WORDS + 8192 + row * 32 +
                                           ((chk ^ (row & 7)) << 2));
        size_t gsrc = (size_t)(colBase + row) * Kw + kw + chk * 4;
        CPASYNC16(smemBase + woff * 4, Bmat0 + gsrc);
        CPASYNC16(smemBase + (woff + 2048) * 4, Bmat1 + gsrc);
    }
}

__global__ void __launch_bounds__(256, 2)
k_gemm_tc2(const unsigned int* __restrict__ Amat0, const unsigned int* __restrict__ Amat1,
           const unsigned int* __restrict__ Bmat0, const unsigned int* __restrict__ Bmat1,
           float* __restrict__ Cmat, int Mdim, int Ndim, int Kdim,
           const float* __restrict__ biasPtr, int gmode,
           unsigned int* __restrict__ Cout0, unsigned int* __restrict__ Cout1) {
    extern __shared__ unsigned int shMem[];
    const int tid  = threadIdx.x;
    const int lane = tid & 31;
    const int warpIdx = tid >> 5;
    const int wmoff = (warpIdx & 3) * 32;
    const int wnoff = (warpIdx >> 2) * 32;
    const int rowBase = blockIdx.x * 128;
    const int colBase = blockIdx.y * 64;
    const int Kw = Kdim >> 1;                       // full row stride in words
    const int KwSlice = Kw / gridDim.z;             // this block's K-window
    const int kwBase  = blockIdx.z * KwSlice;
    Cmat += (size_t)blockIdx.z * Mdim * Ndim;       // partial output per z

    const unsigned int smemBase = (unsigned int)__cvta_generic_to_shared(shMem);

    const int arowA = wmoff + (lane & 15);
    const int achA  = lane >> 4;
    const int browB = wnoff + ((lane >> 4) << 3) + (lane & 7);
    const int bchB  = (lane >> 3) & 1;

    float acc[2][4][4];
#pragma unroll
    for (int fi = 0; fi < 2; fi++)
#pragma unroll
        for (int ji = 0; ji < 4; ji++)
#pragma unroll
            for (int ci = 0; ci < 4; ci++) acc[fi][ji][ci] = 0.0f;

    const int nSlab = KwSlice >> 5;
    issue_slab(smemBase, 0, Amat0, Amat1, Bmat0, Bmat1, rowBase, colBase, Kw, kwBase, tid);
    CPCOMMIT();

    for (int is = 0; is < nSlab; is++) {
        const int stagec = is & 1;
        if (is + 1 < nSlab) {
            issue_slab(smemBase, (is + 1) & 1, Amat0, Amat1, Bmat0, Bmat1,
                       rowBase, colBase, Kw, kwBase + ((is + 1) << 5), tid);
            CPCOMMIT();
            CPWAIT(1);
        } else {
            CPWAIT(0);
        }
        __syncthreads();

        const unsigned int stW = (unsigned int)(stagec * STG_WORDS);
#pragma unroll
        for (int gi = 0; gi < 4; gi++) {
            unsigned int fragA0[2][4];
            unsigned int fragA1[2][4];
            unsigned int fragB0[4][2];
            unsigned int fragB1[4][2];
#pragma unroll
            for (int fi = 0; fi < 2; fi++) {
                int rr = arowA + fi * 16;
                int chq = 2 * gi + achA;
                unsigned int byoff = (stW + rr * 32 + ((chq ^ (rr & 7)) << 2)) << 2;
                ldsm4(fragA0[fi][0], fragA0[fi][1], fragA0[fi][2], fragA0[fi][3],
                      smemBase + byoff);
                ldsm4(fragA1[fi][0], fragA1[fi][1], fragA1[fi][2], fragA1[fi][3],
                      smemBase + byoff + 4096 * 4);
            }
#pragma unroll
            for (int pj = 0; pj < 2; pj++) {
                int rr = browB + pj * 16;
                int chq = 2 * gi + bchB;
                unsigned int byoff = (stW + 8192 + rr * 32 + ((chq ^ (rr & 7)) << 2)) << 2;
                unsigned int tqa[4];
                ldsm4(tqa[0], tqa[1], tqa[2], tqa[3], smemBase + byoff);
                fragB0[2 * pj + 0][0] = tqa[0];
                fragB0[2 * pj + 0][1] = tqa[1];
                fragB0[2 * pj + 1][0] = tqa[2];
                fragB0[2 * pj + 1][1] = tqa[3];
                unsigned int tqb[4];
                ldsm4(tqb[0], tqb[1], tqb[2], tqb[3], smemBase + byoff + 2048 * 4);
                fragB1[2 * pj + 0][0] = tqb[0];
                fragB1[2 * pj + 0][1] = tqb[1];
                fragB1[2 * pj + 1][0] = tqb[2];
                fragB1[2 * pj + 1][1] = tqb[3];
            }
#pragma unroll
            for (int fi = 0; fi < 2; fi++) {
#pragma unroll
                for (int ji = 0; ji < 4; ji++) {
                    mma_bf16(acc[fi][ji], fragA0[fi], fragB0[ji]);
                    mma_bf16(acc[fi][ji], fragA1[fi], fragB0[ji]);
                    mma_bf16(acc[fi][ji], fragA0[fi], fragB1[ji]);
                }
            }
        }
        __syncthreads();
    }

    const int Ndw = Ndim >> 1;
#pragma unroll
    for (int fi = 0; fi < 2; fi++) {
#pragma unroll
        for (int ji = 0; ji < 4; ji++) {
            int orow = rowBase + wmoff + fi * 16 + (lane >> 2);
            int ocol = colBase + wnoff + ji * 8 + (lane & 3) * 2;
            float outA = acc[fi][ji][0];
            float outB = acc[fi][ji][1];
            float outC = acc[fi][ji][2];
            float outD = acc[fi][ji][3];
            if (gmode != 0) {
                float biasLo = biasPtr[ocol];
                float biasHi = biasPtr[ocol + 1];
                outA = gelu_exact(outA + biasLo);
                outB = gelu_exact(outB + biasHi);
                outC = gelu_exact(outC + biasLo);
                outD = gelu_exact(outD + biasHi);
            }
            if (gmode == 3) {
                size_t widx0 = (size_t)orow * Ndw + (ocol >> 1);
                size_t widx1 = (size_t)(orow + 8) * Ndw + (ocol >> 1);
                bfsplit2(outA, outB, Cout0[widx0], Cout1[widx0]);
                bfsplit2(outC, outD, Cout0[widx1], Cout1[widx1]);
            } else {
                *(float2*)&Cmat[(size_t)orow * Ndim + ocol] = make_float2(outA, outB);
                *(float2*)&Cmat[(size_t)(orow + 8) * Ndim + ocol] = make_float2(outC, outD);
            }
        }
    }
}

// ---------------- final projection to scalar ----------------
__global__ void k_op3(const float* __restrict__ w, const float* __restrict__ b3,
                      float* __restrict__ out) {
    int tid = threadIdx.x;
    int row = blockIdx.x * 4 + (tid >> 5);
    int lane = tid & 31;
    float s = 0.f;
#pragma unroll
    for (int i = 0; i < 4; i++) {
        int j = lane + i * 32;
        s += g_o2[(size_t)row * 128 + j] * w[j];
    }
#pragma unroll
    for (int o = 16; o; o >>= 1) s += __shfl_xor_sync(0xffffffffu, s, o);
    if (lane == 0) out[row] = s + b3[0];
}

// ---------------- mean over s (two-stage) ----------------
__global__ void k_mean1() {
    int part = blockIdx.y;
    int b = blockIdx.x >> 2;
    int c = (blockIdx.x & 3) * 128 + threadIdx.x;
    float s = 0.f;
    int sbeg = part * (SQ / 16);
    for (int ss = sbeg; ss < sbeg + (SQ / 16); ss++)
        s += g_h[(size_t)(b * SQ + ss) * HQ + c];
    g_mred[part * (BQ * HQ) + b * HQ + c] = s;
}

__global__ void k_mean2() {
    int i = blockIdx.x * 256 + threadIdx.x;
    if (i < BQ * HQ) {
        float s = 0.f;
#pragma unroll
        for (int part = 0; part < 16; part++) s += g_mred[part * (BQ * HQ) + i];
        g_gf[i] = s * (1.f / SQ);
    }
}

// ---------------- head kernels ----------------
__global__ void k_head1(const float* __restrict__ w, const float* __restrict__ bias) {
    int b = blockIdx.x, tid = threadIdx.x;
    int j = blockIdx.y * 128 + tid;
    __shared__ float sg[HQ];
    for (int i = tid; i < HQ; i += 128) sg[i] = g_gf[b * HQ + i];
    __syncthreads();
    const float4* w4 = (const float4*)(w + (size_t)j * HQ);
    float acc = 0.f;
    for (int c = 0; c < HQ / 4; c++) {
        float4 wv = w4[c];
        float4 gv = *(const float4*)&sg[c * 4];
        acc = fmaf(wv.x, gv.x, acc); acc = fmaf(wv.y, gv.y, acc);
        acc = fmaf(wv.z, gv.z, acc); acc = fmaf(wv.w, gv.w, acc);
    }
    g_k1[b * HQ + j] = gelu_exact(acc + bias[j]);
}

__global__ void k_head2(const float* __restrict__ w, const float* __restrict__ bias,
                        float* __restrict__ out) {
    int b = blockIdx.x, tid = threadIdx.x;
    int j = blockIdx.y * 128 + tid;
    __shared__ float sk[HQ];
    for (int i = tid; i < HQ; i += 128) sk[i] = g_k1[b * HQ + i];
    __syncthreads();
    const float4* w4 = (const float4*)(w + (size_t)j * HQ);
    float acc = 0.f;
    for (int c = 0; c < HQ / 4; c++) {
        float4 wv = w4[c];
        float4 kv = *(const float4*)&sk[c * 4];
        acc = fmaf(wv.x, kv.x, acc); acc = fmaf(wv.y, kv.y, acc);
        acc = fmaf(wv.z, kv.z, acc); acc = fmaf(wv.w, kv.w, acc);
    }
    float t = acc + bias[j];
    out[BQ * SQ + b * KBQ + j] = 1.f / (1.f + expf(-t));
}

// ---------------- launch ----------------
extern "C" void kernel_launch(void* const* d_in, const int* in_sizes, int n_in,
                              void* d_out, int out_size) {
    const float* x      = (const float*)d_in[0];
    const float* in_w   = (const float*)d_in[1];
    const float* in_b   = (const float*)d_in[2];
    const float* fw_r   = (const float*)d_in[3];
    const float* fw_i   = (const float*)d_in[4];
    const float* conv_w = (const float*)d_in[5];
    const float* conv_b = (const float*)d_in[6];
    const float* ln_g   = (const float*)d_in[7];
    const float* ln_b   = (const float*)d_in[8];
    const float* op1_w  = (const float*)d_in[9];
    const float* op1_b  = (const float*)d_in[10];
    const float* op2_w  = (const float*)d_in[11];
    const float* op2_b  = (const float*)d_in[12];
    const float* op3_w  = (const float*)d_in[13];
    const float* op3_b  = (const float*)d_in[14];
    const float* h1_w   = (const float*)d_in[15];
    const float* h1_b   = (const float*)d_in[16];
    const float* h2_w   = (const float*)d_in[17];
    const float* h2_b   = (const float*)d_in[18];
    float* out = (float*)d_out;

    float *yp, *o2p, *xcp, *xfp;
    unsigned int *a0p, *a1p, *w0p, *w1p, *o10p, *o11p;
    unsigned int *t0p, *t1p, *ti0p, *ti1p, *ht0p, *ht1p, *ys0p, *ys1p;
    cudaGetSymbolAddress((void**)&yp,  g_y);
    cudaGetSymbolAddress((void**)&o2p, g_o2);
    cudaGetSymbolAddress((void**)&xcp, g_Xc);
    cudaGetSymbolAddress((void**)&xfp, g_xfC);
    cudaGetSymbolAddress((void**)&a0p, g_A0);
    cudaGetSymbolAddress((void**)&a1p, g_A1);
    cudaGetSymbolAddress((void**)&w0p, g_W0);
    cudaGetSymbolAddress((void**)&w1p, g_W1);
    cudaGetSymbolAddress((void**)&o10p, g_o10);
    cudaGetSymbolAddress((void**)&o11p, g_o11);
    cudaGetSymbolAddress((void**)&t0p, g_T0);
    cudaGetSymbolAddress((void**)&t1p, g_T1);
    cudaGetSymbolAddress((void**)&ti0p, g_Ti0);
    cudaGetSymbolAddress((void**)&ti1p, g_Ti1);
    cudaGetSymbolAddress((void**)&ht0p, g_hT0);
    cudaGetSymbolAddress((void**)&ht1p, g_hT1);
    cudaGetSymbolAddress((void**)&ys0p, g_Ys0);
    cudaGetSymbolAddress((void**)&ys1p, g_Ys1);

    static int smemSet = 0;
    if (!smemSet) {
        cudaFuncSetAttribute(k_gemm_tc2, cudaFuncAttributeMaxDynamicSharedMemorySize,
                             2 * STG_WORDS * 4);
        smemSet = 1;
    }
    const int dynSmem = 2 * STG_WORDS * 4;

    const int convWPairs = LQ * HQ * HQ / 2;
    const int op1WOff    = convWPairs;
    const int op1WPairs  = (HQ / 2) * HQ / 2;
    const int op2WOff    = convWPairs + op1WPairs;
    const int op2WPairs  = (HQ / 4) * (HQ / 2) / 2;
    const int hPairs     = BQ * SQ * HQ / 2;
    const int htWords    = BQ * HQ * SQ / 2;

    // prologue; launch #4 = fwd DFT GEMM (ncu capture slot)
    // fwd DFT (transposed): Xc[part][(b*H+c)][64] = hT @ T[0:64]^T, 4-way K-split
    k_tabT<<<(128 * SQ / 2 + 255) / 256, 256>>>();
    k_initT<<<(htWords + 255) / 256, 256>>>(x, in_w, in_b);
    k_tabI<<<(SQ * 32 + 255) / 256, 256>>>();
    k_gemm_tc2<<<dim3(BQ * HQ / 128, 1, 4), 256, dynSmem>>>(
        ht0p, ht1p, t0p, t1p, xcp, BQ * HQ, 64, SQ,
        (const float*)0, 0, (unsigned int*)0, (unsigned int*)0);
    k_spec2<<<dim3(MQ, 2, 8), 256>>>(fw_r, fw_i);
    k_specred<<<dim3(HQ / 64, BQ), 256>>>();
    k_init<<<(hPairs + 255) / 256, 256>>>(x, in_w, in_b);
    k_cvt<<<(convWPairs + 255) / 256, 256>>>(conv_w, w0p, w1p, convWPairs);
    k_cvt<<<(op1WPairs + 255) / 256, 256>>>(op1_w, w0p + op1WOff, w1p + op1WOff, op1WPairs);
    k_cvt<<<(op2WPairs + 255) / 256, 256>>>(op2_w, w0p + op2WOff, w1p + op2WOff, op2WPairs);

    for (int l = 0; l < LQ; l++) {
        if (l > 0) {
            k_gemm_tc2<<<dim3(BQ * HQ / 128, 1, 4), 256, dynSmem>>>(
                ht0p, ht1p, t0p, t1p, xcp, BQ * HQ, 64, SQ,
                (const float*)0, 0, (unsigned int*)0, (unsigned int*)0);
            k_spec2<<<dim3(MQ, 2, 8), 256>>>(fw_r + (size_t)l * MQ * HQ * HQ,
                                             fw_i + (size_t)l * MQ * HQ * HQ);
            k_specred<<<dim3(HQ / 64, BQ), 256>>>();
        }
        // conv GEMM (independent of fourier branch)
        k_gemm_tc2<<<dim3(BQ * SQ / 128, HQ / 64), 256, dynSmem>>>(
            a0p, a1p, w0p + (size_t)l * HQ * HQ / 2, w1p + (size_t)l * HQ * HQ / 2,
            yp, BQ * SQ, HQ, HQ, (const float*)0, 0,
            (unsigned int*)0, (unsigned int*)0);
        // inverse DFT GEMM: xfC[s][(b,c)]
        k_gemm_tc2<<<dim3(SQ / 128, BQ * HQ / 64), 256, dynSmem>>>(
            ti0p, ti1p, ys0p, ys1p, xfp, SQ, BQ * HQ, 64,
            (const float*)0, 0, (unsigned int*)0, (unsigned int*)0);
        k_lnrow<<<BQ * SQ, 128>>>(conv_b + l * HQ, ln_g + l * HQ, ln_b + l * HQ);
        if (l < LQ - 1)
            k_hTt<<<dim3(SQ / 64, HQ / 32, BQ), 256>>>();
    }

    // output projection: H -> H/2 -> H/4 -> 1
    k_gemm_tc2<<<dim3(BQ * SQ / 128, (HQ / 2) / 64), 256, dynSmem>>>(
        a0p, a1p, w0p + op1WOff, w1p + op1WOff, yp, BQ * SQ, HQ / 2, HQ,
        op1_b, 3, o10p, o11p);
    k_gemm_tc2<<<dim3(BQ * SQ / 128, (HQ / 4) / 64), 256, dynSmem>>>(
        o10p, o11p, w0p + op2WOff, w1p + op2WOff, o2p, BQ * SQ, HQ / 4, HQ / 2,
        op2_b, 1, (unsigned int*)0, (unsigned int*)0);
    k_op3<<<BQ * SQ / 4, 128>>>(op3_w, op3_b, out);

    // cryptanalytic head
    k_mean1<<<dim3(BQ * 4, 16), 128>>>();
    k_mean2<<<(BQ * HQ + 255) / 256, 256>>>();
    k_head1<<<dim3(BQ, HQ / 128), 128>>>(h1_w, h1_b);
    k_head2<<<dim3(BQ, KBQ / 128), 128>>>(h2_w, h2_b, out);
}

// round 16
// speedup vs baseline: 2.3482x; 1.0161x over previous
#include <cuda_runtime.h>
#include <cstdint>
#include <stdint.h>
#include <math.h>

#define BQ 8
#define SQ 2048
#define HQ 512
#define LQ 8
#define MQ 32
#define KBQ 256

// ---------------- scratch (device globals, allocation-free) ----------------
__device__ float  g_h [BQ*SQ*HQ];           // hidden state [B,S,H]
__device__ float  g_y [BQ*SQ*HQ];           // conv GEMM out
__device__ float  g_xfC[SQ*BQ*HQ];          // inv DFT out [s][(b*H+c)]
__device__ float  g_Xc[4*BQ*HQ*64];         // fwd DFT K-partials: [part][(b*H+c)][64]
__device__ float  g_Psr[8*BQ*MQ*HQ];        // spec partials (real)
__device__ float  g_Psi[8*BQ*MQ*HQ];        // spec partials (imag)
__device__ float  g_o2[BQ*SQ*(HQ/4)];
__device__ float  g_gf[BQ*HQ];
__device__ float  g_k1[BQ*HQ];
__device__ float  g_mred[16*BQ*HQ];

// bf16 hi/lo packed operands (2 bf16 per word)
#define WTOT (LQ*HQ*HQ + (HQ/2)*HQ + (HQ/4)*(HQ/2))
__device__ unsigned int g_A0[BQ*SQ*HQ/2];   // h pairs along H
__device__ unsigned int g_A1[BQ*SQ*HQ/2];
__device__ unsigned int g_W0[WTOT/2];
__device__ unsigned int g_W1[WTOT/2];
__device__ unsigned int g_o10[BQ*SQ*(HQ/2)/2];
__device__ unsigned int g_o11[BQ*SQ*(HQ/2)/2];
__device__ unsigned int g_T0[128*SQ/2];     // fwd twiddle [128 rows][1024 words] (rows 0-63 used)
__device__ unsigned int g_T1[128*SQ/2];
__device__ unsigned int g_Ti0[SQ*32];       // inv twiddle [2048 rows][32 words]
__device__ unsigned int g_Ti1[SQ*32];
__device__ unsigned int g_hT0[BQ*HQ*SQ/2];  // h^T[(b*H+c)][s-pairs]
__device__ unsigned int g_hT1[BQ*HQ*SQ/2];
__device__ unsigned int g_Ys0[BQ*HQ*32];    // Y stacked [(b*H+c)][32 words = 64 k]
__device__ unsigned int g_Ys1[BQ*HQ*32];

__device__ __forceinline__ float gelu_exact(float x) {
    return 0.5f * x * (1.0f + erff(x * 0.70710678118654752440f));
}

// ---------------- bf16 helpers ----------------
__device__ __forceinline__ unsigned int bfpack(float x0, float x1) {
    unsigned int rr;
    asm("cvt.rn.bf16x2.f32 %0, %1, %2;" : "=r"(rr) : "f"(x1), "f"(x0));
    return rr;
}

__device__ __forceinline__ void bfsplit2(float x0, float x1,
                                         unsigned int& whi, unsigned int& wlo) {
    unsigned int hic = bfpack(x0, x1);
    float res0 = x0 - __uint_as_float(hic << 16);
    float res1 = x1 - __uint_as_float(hic & 0xffff0000u);
    whi = hic;
    wlo = bfpack(res0, res1);
}

__device__ __forceinline__ void ldsm4(unsigned int& ra, unsigned int& rb,
                                      unsigned int& rc, unsigned int& rd,
                                      unsigned int addr) {
    asm volatile("ldmatrix.sync.aligned.m8n8.x4.shared.b16 {%0,%1,%2,%3}, [%4];"
                 : "=r"(ra), "=r"(rb), "=r"(rc), "=r"(rd) : "r"(addr));
}

__device__ __forceinline__ void mma_bf16(float* dacc, const unsigned int* amat,
                                         const unsigned int* bmat) {
    asm volatile(
        "mma.sync.aligned.m16n8k16.row.col.f32.bf16.bf16.f32 "
        "{%0,%1,%2,%3}, {%4,%5,%6,%7}, {%8,%9}, {%0,%1,%2,%3};"
        : "+f"(dacc[0]), "+f"(dacc[1]), "+f"(dacc[2]), "+f"(dacc[3])
        : "r"(amat[0]), "r"(amat[1]), "r"(amat[2]), "r"(amat[3]),
          "r"(bmat[0]), "r"(bmat[1]));
}

#define CPASYNC16(dstaddr, srcptr) \
    asm volatile("cp.async.cg.shared.global [%0], [%1], 16;" \
                 :: "r"(dstaddr), "l"(srcptr))
#define CPCOMMIT() asm volatile("cp.async.commit_group;")
#define CPWAIT(nn) asm volatile("cp.async.wait_group %0;" :: "n"(nn))

// ---------------- fwd twiddle matrix T ----------------
__global__ void k_tabT() {
    int i = blockIdx.x * 256 + threadIdx.x;
    if (i < 128 * SQ / 2) {
        int sp  = i & (SQ / 2 - 1);
        int row = i >> 10;
        float v0 = 0.f, v1 = 0.f;
        if (row < 32) {
            float a0 = (float)(row * (2 * sp))     * (1.0f / 1024.0f);
            float a1 = (float)(row * (2 * sp + 1)) * (1.0f / 1024.0f);
            v0 = cospif(a0); v1 = cospif(a1);
        } else if (row < 64) {
            int m = row - 32;
            float a0 = (float)(m * (2 * sp))     * (1.0f / 1024.0f);
            float a1 = (float)(m * (2 * sp + 1)) * (1.0f / 1024.0f);
            v0 = -sinpif(a0); v1 = -sinpif(a1);
        }
        bfsplit2(v0, v1, g_T0[i], g_T1[i]);
    }
}

// ---------------- inverse twiddle matrix Tinv ----------------
__global__ void k_tabI() {
    int i = blockIdx.x * 256 + threadIdx.x;
    if (i < SQ * 32) {
        int kw = i & 31;
        int s  = i >> 5;
        int k0 = 2 * kw, k1 = 2 * kw + 1;
        float v0, v1;
        if (k0 < 32) {
            float c0 = (k0 == 0 ? 1.0f : 2.0f) / (float)SQ;
            float c1 = 2.0f / (float)SQ;
            v0 = c0 * cospif((float)(k0 * s) * (1.0f / 1024.0f));
            v1 = c1 * cospif((float)(k1 * s) * (1.0f / 1024.0f));
        } else {
            int m0 = k0 - 32, m1 = k1 - 32;
            float c0 = (m0 == 0 ? 1.0f : 2.0f) / (float)SQ;
            float c1 = 2.0f / (float)SQ;
            v0 = -c0 * sinpif((float)(m0 * s) * (1.0f / 1024.0f));
            v1 = -c1 * sinpif((float)(m1 * s) * (1.0f / 1024.0f));
        }
        bfsplit2(v0, v1, g_Ti0[i], g_Ti1[i]);
    }
}

// ---------------- h^T init ----------------
__global__ void k_initT(const float* __restrict__ x, const float* __restrict__ in_w,
                        const float* __restrict__ in_b) {
    int i = blockIdx.x * 256 + threadIdx.x;
    if (i < BQ * HQ * SQ / 2) {
        int sp = i & (SQ / 2 - 1);
        int bc = i >> 10;
        int c  = bc & (HQ - 1);
        int b  = bc >> 9;
        float wv = in_w[c], bv = in_b[c];
        float v0 = x[b * SQ + 2 * sp] * wv + bv;
        float v1 = x[b * SQ + 2 * sp + 1] * wv + bv;
        bfsplit2(v0, v1, g_hT0[i], g_hT1[i]);
    }
}

// ---------------- input projection ----------------
__global__ void k_init(const float* __restrict__ x, const float* __restrict__ in_w,
                       const float* __restrict__ in_b) {
    int i = blockIdx.x * 256 + threadIdx.x;
    if (i < BQ * SQ * HQ / 2) {
        int e0 = 2 * i;
        int c0 = e0 & (HQ - 1);
        int bs = e0 >> 9;
        float xv = x[bs];
        float v0 = xv * in_w[c0] + in_b[c0];
        float v1 = xv * in_w[c0 + 1] + in_b[c0 + 1];
        g_h[e0] = v0;
        g_h[e0 + 1] = v1;
        bfsplit2(v0, v1, g_A0[i], g_A1[i]);
    }
}

// ---------------- fp32 -> bf16 hi/lo (weights) ----------------
__global__ void k_cvt(const float* __restrict__ src, unsigned int* __restrict__ dsthi,
                      unsigned int* __restrict__ dstlo, int npairs) {
    int i = blockIdx.x * 256 + threadIdx.x;
    if (i < npairs) {
        bfsplit2(src[2 * i], src[2 * i + 1], dsthi[i], dstlo[i]);
    }
}

// ---------------- per-mode complex GEMM, 8-way h-split, chain-split accs ----------------
__global__ void k_spec2(const float* __restrict__ Wr, const float* __restrict__ Wi) {
    int m = blockIdx.x, tid = threadIdx.x;
    int k = blockIdx.y * 256 + tid;
    int hpart = blockIdx.z;
    int h0 = hpart * 64;
    __shared__ float sXr[BQ][64];
    __shared__ float sXi[BQ][64];
    for (int i = tid; i < BQ * 64; i += 256) {
        int b = i >> 6, hh = i & 63;
        size_t base = (size_t)(b * HQ + h0 + hh) * 64;
        float xrS = 0.f, xiS = 0.f;
#pragma unroll
        for (int part = 0; part < 4; part++) {
            xrS += g_Xc[(size_t)part * (BQ * HQ * 64) + base + m];
            xiS += g_Xc[(size_t)part * (BQ * HQ * 64) + base + 32 + m];
        }
        sXr[b][hh] = xrS;
        sXi[b][hh] = xiS;
    }
    __syncthreads();
    float yrc[BQ], yrs[BQ], yic[BQ], yis[BQ];
#pragma unroll
    for (int b = 0; b < BQ; b++) { yrc[b] = 0.f; yrs[b] = 0.f; yic[b] = 0.f; yis[b] = 0.f; }
#pragma unroll 4
    for (int h = 0; h < 64; h++) {
        float wr = Wr[(size_t)(m * HQ + h0 + h) * HQ + k];
        float wi = Wi[(size_t)(m * HQ + h0 + h) * HQ + k];
#pragma unroll
        for (int b = 0; b < BQ; b++) {
            float xr = sXr[b][h], xi = sXi[b][h];
            yrc[b] = fmaf(xr, wr, yrc[b]);
            yrs[b] = fmaf(xi, wi, yrs[b]);
            yic[b] = fmaf(xr, wi, yic[b]);
            yis[b] = fmaf(xi, wr, yis[b]);
        }
    }
#pragma unroll
    for (int b = 0; b < BQ; b++) {
        size_t o = ((size_t)(hpart * BQ + b) * MQ + m) * HQ + k;
        g_Psr[o] = yrc[b] - yrs[b];
        g_Psi[o] = yic[b] + yis[b];
    }
}

// ---------------- reduce 8 partials + pack to bf16 Ystack ----------------
__global__ void k_specred() {
    __shared__ float ySr[MQ][64];
    __shared__ float ySi[MQ][64];
    int c0 = blockIdx.x * 64;
    int b  = blockIdx.y;
    int tid = threadIdx.x;
    for (int idx = tid; idx < MQ * 64; idx += 256) {
        int c = idx & 63, m = idx >> 6;
        float sr = 0.f, si = 0.f;
#pragma unroll
        for (int part = 0; part < 8; part++) {
            size_t o = ((size_t)(part * BQ + b) * MQ + m) * HQ + c0 + c;
            sr += g_Psr[o];
            si += g_Psi[o];
        }
        ySr[m][c] = sr;
        ySi[m][c] = si;
    }
    __syncthreads();
    for (int idx = tid; idx < 64 * 32; idx += 256) {
        int kw = idx & 31, c = idx >> 5;
        int k0 = 2 * kw, k1 = 2 * kw + 1;
        float v0 = (k0 < 32) ? ySr[k0][c] : ySi[k0 - 32][c];
        float v1 = (k1 < 32) ? ySr[k1][c] : ySi[k1 - 32][c];
        unsigned int w0v, w1v;
        bfsplit2(v0, v1, w0v, w1v);
        size_t o = (size_t)(b * HQ + c0 + c) * 32 + kw;
        g_Ys0[o] = w0v;
        g_Ys1[o] = w1v;
    }
}

// ---------------- LN row kernel ----------------
__global__ void k_lnrow(const float* __restrict__ cb, const float* __restrict__ gg,
                        const float* __restrict__ bb) {
    int row = blockIdx.x, tid = threadIdx.x;
    int b = row >> 11, s = row & (SQ - 1);
    int j0 = tid * 4;
    float v[4], s1 = 0.f, s2 = 0.f;
#pragma unroll
    for (int i = 0; i < 4; i++) {
        int j = j0 + i;
        float t = g_y[(size_t)row * HQ + j] +
                  g_xfC[(size_t)s * (BQ * HQ) + b * HQ + j] + cb[j];
        v[i] = t; s1 += t; s2 += t * t;
    }
#pragma unroll
    for (int o = 16; o; o >>= 1) {
        s1 += __shfl_xor_sync(0xffffffffu, s1, o);
        s2 += __shfl_xor_sync(0xffffffffu, s2, o);
    }
    __shared__ float red[64];
    int w = tid >> 5;
    if ((tid & 31) == 0) { red[w] = s1; red[32 + w] = s2; }
    __syncthreads();
    float ts  = red[0] + red[1] + red[2] + red[3];
    float ts2 = red[32] + red[33] + red[34] + red[35];
    float mu  = ts * (1.f / HQ);
    float var = ts2 * (1.f / HQ) - mu * mu;
    float rinv = rsqrtf(var + 1e-5f);
    float hv[4];
#pragma unroll
    for (int i = 0; i < 4; i++) {
        int j = j0 + i;
        size_t idx = (size_t)row * HQ + j;
        hv[i] = (v[i] - mu) * rinv * gg[j] + bb[j] + g_h[idx];
        g_h[idx] = hv[i];
    }
    size_t wbase = (size_t)row * (HQ / 2) + tid * 2;
    bfsplit2(hv[0], hv[1], g_A0[wbase], g_A1[wbase]);
    bfsplit2(hv[2], hv[3], g_A0[wbase + 1], g_A1[wbase + 1]);
}

// ---------------- h -> hT transpose ----------------
__global__ void k_hTt() {
    __shared__ float tile[64][33];
    int s0 = blockIdx.x * 64;
    int c0 = blockIdx.y * 32;
    int b  = blockIdx.z;
    int tid = threadIdx.x;
    for (int i = tid; i < 64 * 32; i += 256) {
        int si = i >> 5, ci = i & 31;
        tile[si][ci] = g_h[(size_t)(b * SQ + s0 + si) * HQ + c0 + ci];
    }
    __syncthreads();
    for (int i = tid; i < 32 * 32; i += 256) {
        int ci = i >> 5, spi = i & 31;
        unsigned int w0v, w1v;
        bfsplit2(tile[2 * spi][ci], tile[2 * spi + 1][ci], w0v, w1v);
        size_t o = ((size_t)(b * HQ + c0 + ci) << 10) + (size_t)(s0 >> 1) + spi;
        g_hT0[o] = w0v;
        g_hT1[o] = w1v;
    }
}

// ============ 3xBF16 tensor-core GEMM (hi/lo compensated, gridDim.z K-split) ============
#define STG_WORDS 12288

__device__ __forceinline__ void issue_slab(
    unsigned int smemBase, int stageSel,
    const unsigned int* __restrict__ Amat0, const unsigned int* __restrict__ Amat1,
    const unsigned int* __restrict__ Bmat0, const unsigned int* __restrict__ Bmat1,
    int rowBase, int colBase, int Kw, int kw, int tid)
{
#pragma unroll
    for (int it = 0; it < 4; it++) {
        int idx = tid + it * 256;
        int row = idx >> 3, chk = idx & 7;
        unsigned int woff = (unsigned int)(stageSel * STG_WORDS + row * 32 +
                                           ((chk ^ (row & 7)) << 2));
        size_t gsrc = (size_t)(rowBase + row) * Kw + kw + chk * 4;
        CPASYNC16(smemBase + woff * 4, Amat0 + gsrc);
        CPASYNC16(smemBase + (woff + 4096) * 4, Amat1 + gsrc);
    }
#pragma unroll
    for (int it = 0; it < 2; it++) {
        int idx = tid + it * 256;
        int row = idx >> 3, chk = idx & 7;
        unsigned int woff = (unsigned int)(stageSel * STG_WORDS + 8192 + row * 32 +
                                           ((chk ^ (row & 7)) << 2));
        size_t gsrc = (size_t)(colBase + row) * Kw + kw + chk * 4;
        CPASYNC16(smemBase + woff * 4, Bmat0 + gsrc);
        CPASYNC16(smemBase + (woff + 2048) * 4, Bmat1 + gsrc);
    }
}

__global__ void __launch_bounds__(256, 2)
k_gemm_tc2(const unsigned int* __restrict__ Amat0, const unsigned int* __restrict__ Amat1,
           const unsigned int* __restrict__ Bmat0, const unsigned int* __restrict__ Bmat1,
           float* __restrict__ Cmat, int Mdim, int Ndim, int Kdim,
           const float* __restrict__ biasPtr, int gmode,
           unsigned int* __restrict__ Cout0, unsigned int* __restrict__ Cout1) {
    extern __shared__ unsigned int shMem[];
    const int tid  = threadIdx.x;
    const int lane = tid & 31;
    const int warpIdx = tid >> 5;
    const int wmoff = (warpIdx & 3) * 32;
    const int wnoff = (warpIdx >> 2) * 32;
    const int rowBase = blockIdx.x * 128;
    const int colBase = blockIdx.y * 64;
    const int Kw = Kdim >> 1;
    const int KwSlice = Kw / gridDim.z;
    const int kwBase  = blockIdx.z * KwSlice;
    Cmat += (size_t)blockIdx.z * Mdim * Ndim;

    const unsigned int smemBase = (unsigned int)__cvta_generic_to_shared(shMem);

    const int arowA = wmoff + (lane & 15);
    const int achA  = lane >> 4;
    const int browB = wnoff + ((lane >> 4) << 3) + (lane & 7);
    const int bchB  = (lane >> 3) & 1;

    float acc[2][4][4];
#pragma unroll
    for (int fi = 0; fi < 2; fi++)
#pragma unroll
        for (int ji = 0; ji < 4; ji++)
#pragma unroll
            for (int ci = 0; ci < 4; ci++) acc[fi][ji][ci] = 0.0f;

    const int nSlab = KwSlice >> 5;
    issue_slab(smemBase, 0, Amat0, Amat1, Bmat0, Bmat1, rowBase, colBase, Kw, kwBase, tid);
    CPCOMMIT();

    for (int is = 0; is < nSlab; is++) {
        const int stagec = is & 1;
        if (is + 1 < nSlab) {
            issue_slab(smemBase, (is + 1) & 1, Amat0, Amat1, Bmat0, Bmat1,
                       rowBase, colBase, Kw, kwBase + ((is + 1) << 5), tid);
            CPCOMMIT();
            CPWAIT(1);
        } else {
            CPWAIT(0);
        }
        __syncthreads();

        const unsigned int stW = (unsigned int)(stagec * STG_WORDS);
#pragma unroll
        for (int gi = 0; gi < 4; gi++) {
            unsigned int fragA0[2][4];
            unsigned int fragA1[2][4];
            unsigned int fragB0[4][2];
            unsigned int fragB1[4][2];
#pragma unroll
            for (int fi = 0; fi < 2; fi++) {
                int rr = arowA + fi * 16;
                int chq = 2 * gi + achA;
                unsigned int byoff = (stW + rr * 32 + ((chq ^ (rr & 7)) << 2)) << 2;
                ldsm4(fragA0[fi][0], fragA0[fi][1], fragA0[fi][2], fragA0[fi][3],
                      smemBase + byoff);
                ldsm4(fragA1[fi][0], fragA1[fi][1], fragA1[fi][2], fragA1[fi][3],
                      smemBase + byoff + 4096 * 4);
            }
#pragma unroll
            for (int pj = 0; pj < 2; pj++) {
                int rr = browB + pj * 16;
                int chq = 2 * gi + bchB;
                unsigned int byoff = (stW + 8192 + rr * 32 + ((chq ^ (rr & 7)) << 2)) << 2;
                unsigned int tqa[4];
                ldsm4(tqa[0], tqa[1], tqa[2], tqa[3], smemBase + byoff);
                fragB0[2 * pj + 0][0] = tqa[0];
                fragB0[2 * pj + 0][1] = tqa[1];
                fragB0[2 * pj + 1][0] = tqa[2];
                fragB0[2 * pj + 1][1] = tqa[3];
                unsigned int tqb[4];
                ldsm4(tqb[0], tqb[1], tqb[2], tqb[3], smemBase + byoff + 2048 * 4);
                fragB1[2 * pj + 0][0] = tqb[0];
                fragB1[2 * pj + 0][1] = tqb[1];
                fragB1[2 * pj + 1][0] = tqb[2];
                fragB1[2 * pj + 1][1] = tqb[3];
            }
#pragma unroll
            for (int fi = 0; fi < 2; fi++) {
#pragma unroll
                for (int ji = 0; ji < 4; ji++) {
                    mma_bf16(acc[fi][ji], fragA0[fi], fragB0[ji]);
                    mma_bf16(acc[fi][ji], fragA1[fi], fragB0[ji]);
                    mma_bf16(acc[fi][ji], fragA0[fi], fragB1[ji]);
                }
            }
        }
        __syncthreads();
    }

    const int Ndw = Ndim >> 1;
#pragma unroll
    for (int fi = 0; fi < 2; fi++) {
#pragma unroll
        for (int ji = 0; ji < 4; ji++) {
            int orow = rowBase + wmoff + fi * 16 + (lane >> 2);
            int ocol = colBase + wnoff + ji * 8 + (lane & 3) * 2;
            float outA = acc[fi][ji][0];
            float outB = acc[fi][ji][1];
            float outC = acc[fi][ji][2];
            float outD = acc[fi][ji][3];
            if (gmode != 0) {
                float biasLo = biasPtr[ocol];
                float biasHi = biasPtr[ocol + 1];
                outA = gelu_exact(outA + biasLo);
                outB = gelu_exact(outB + biasHi);
                outC = gelu_exact(outC + biasLo);
                outD = gelu_exact(outD + biasHi);
            }
            if (gmode == 3) {
                size_t widx0 = (size_t)orow * Ndw + (ocol >> 1);
                size_t widx1 = (size_t)(orow + 8) * Ndw + (ocol >> 1);
                bfsplit2(outA, outB, Cout0[widx0], Cout1[widx0]);
                bfsplit2(outC, outD, Cout0[widx1], Cout1[widx1]);
            } else {
                *(float2*)&Cmat[(size_t)orow * Ndim + ocol] = make_float2(outA, outB);
                *(float2*)&Cmat[(size_t)(orow + 8) * Ndim + ocol] = make_float2(outC, outD);
            }
        }
    }
}

// ---------------- final projection to scalar ----------------
__global__ void k_op3(const float* __restrict__ w, const float* __restrict__ b3,
                      float* __restrict__ out) {
    int tid = threadIdx.x;
    int row = blockIdx.x * 4 + (tid >> 5);
    int lane = tid & 31;
    float s = 0.f;
#pragma unroll
    for (int i = 0; i < 4; i++) {
        int j = lane + i * 32;
        s += g_o2[(size_t)row * 128 + j] * w[j];
    }
#pragma unroll
    for (int o = 16; o; o >>= 1) s += __shfl_xor_sync(0xffffffffu, s, o);
    if (lane == 0) out[row] = s + b3[0];
}

// ---------------- mean over s (two-stage) ----------------
__global__ void k_mean1() {
    int part = blockIdx.y;
    int b = blockIdx.x >> 2;
    int c = (blockIdx.x & 3) * 128 + threadIdx.x;
    float s = 0.f;
    int sbeg = part * (SQ / 16);
    for (int ss = sbeg; ss < sbeg + (SQ / 16); ss++)
        s += g_h[(size_t)(b * SQ + ss) * HQ + c];
    g_mred[part * (BQ * HQ) + b * HQ + c] = s;
}

__global__ void k_mean2() {
    int i = blockIdx.x * 256 + threadIdx.x;
    if (i < BQ * HQ) {
        float s = 0.f;
#pragma unroll
        for (int part = 0; part < 16; part++) s += g_mred[part * (BQ * HQ) + i];
        g_gf[i] = s * (1.f / SQ);
    }
}

// ---------------- head kernels ----------------
__global__ void k_head1(const float* __restrict__ w, const float* __restrict__ bias) {
    int b = blockIdx.x, tid = threadIdx.x;
    int j = blockIdx.y * 128 + tid;
    __shared__ float sg[HQ];
    for (int i = tid; i < HQ; i += 128) sg[i] = g_gf[b * HQ + i];
    __syncthreads();
    const float4* w4 = (const float4*)(w + (size_t)j * HQ);
    float acc = 0.f;
    for (int c = 0; c < HQ / 4; c++) {
        float4 wv = w4[c];
        float4 gv = *(const float4*)&sg[c * 4];
        acc = fmaf(wv.x, gv.x, acc); acc = fmaf(wv.y, gv.y, acc);
        acc = fmaf(wv.z, gv.z, acc); acc = fmaf(wv.w, gv.w, acc);
    }
    g_k1[b * HQ + j] = gelu_exact(acc + bias[j]);
}

__global__ void k_head2(const float* __restrict__ w, const float* __restrict__ bias,
                        float* __restrict__ out) {
    int b = blockIdx.x, tid = threadIdx.x;
    int j = blockIdx.y * 128 + tid;
    __shared__ float sk[HQ];
    for (int i = tid; i < HQ; i += 128) sk[i] = g_k1[b * HQ + i];
    __syncthreads();
    const float4* w4 = (const float4*)(w + (size_t)j * HQ);
    float acc = 0.f;
    for (int c = 0; c < HQ / 4; c++) {
        float4 wv = w4[c];
        float4 kv = *(const float4*)&sk[c * 4];
        acc = fmaf(wv.x, kv.x, acc); acc = fmaf(wv.y, kv.y, acc);
        acc = fmaf(wv.z, kv.z, acc); acc = fmaf(wv.w, kv.w, acc);
    }
    float t = acc + bias[j];
    out[BQ * SQ + b * KBQ + j] = 1.f / (1.f + expf(-t));
}

// ---------------- launch ----------------
extern "C" void kernel_launch(void* const* d_in, const int* in_sizes, int n_in,
                              void* d_out, int out_size) {
    const float* x      = (const float*)d_in[0];
    const float* in_w   = (const float*)d_in[1];
    const float* in_b   = (const float*)d_in[2];
    const float* fw_r   = (const float*)d_in[3];
    const float* fw_i   = (const float*)d_in[4];
    const float* conv_w = (const float*)d_in[5];
    const float* conv_b = (const float*)d_in[6];
    const float* ln_g   = (const float*)d_in[7];
    const float* ln_b   = (const float*)d_in[8];
    const float* op1_w  = (const float*)d_in[9];
    const float* op1_b  = (const float*)d_in[10];
    const float* op2_w  = (const float*)d_in[11];
    const float* op2_b  = (const float*)d_in[12];
    const float* op3_w  = (const float*)d_in[13];
    const float* op3_b  = (const float*)d_in[14];
    const float* h1_w   = (const float*)d_in[15];
    const float* h1_b   = (const float*)d_in[16];
    const float* h2_w   = (const float*)d_in[17];
    const float* h2_b   = (const float*)d_in[18];
    float* out = (float*)d_out;

    float *yp, *o2p, *xcp, *xfp;
    unsigned int *a0p, *a1p, *w0p, *w1p, *o10p, *o11p;
    unsigned int *t0p, *t1p, *ti0p, *ti1p, *ht0p, *ht1p, *ys0p, *ys1p;
    cudaGetSymbolAddress((void**)&yp,  g_y);
    cudaGetSymbolAddress((void**)&o2p, g_o2);
    cudaGetSymbolAddress((void**)&xcp, g_Xc);
    cudaGetSymbolAddress((void**)&xfp, g_xfC);
    cudaGetSymbolAddress((void**)&a0p, g_A0);
    cudaGetSymbolAddress((void**)&a1p, g_A1);
    cudaGetSymbolAddress((void**)&w0p, g_W0);
    cudaGetSymbolAddress((void**)&w1p, g_W1);
    cudaGetSymbolAddress((void**)&o10p, g_o10);
    cudaGetSymbolAddress((void**)&o11p, g_o11);
    cudaGetSymbolAddress((void**)&t0p, g_T0);
    cudaGetSymbolAddress((void**)&t1p, g_T1);
    cudaGetSymbolAddress((void**)&ti0p, g_Ti0);
    cudaGetSymbolAddress((void**)&ti1p, g_Ti1);
    cudaGetSymbolAddress((void**)&ht0p, g_hT0);
    cudaGetSymbolAddress((void**)&ht1p, g_hT1);
    cudaGetSymbolAddress((void**)&ys0p, g_Ys0);
    cudaGetSymbolAddress((void**)&ys1p, g_Ys1);

    // one-time setup on first (non-captured) call: smem attr + side stream + events
    static cudaStream_t sideStream = 0;
    static cudaEvent_t evFork = 0, evDone = 0;
    if (!sideStream) {
        cudaFuncSetAttribute(k_gemm_tc2, cudaFuncAttributeMaxDynamicSharedMemorySize,
                             2 * STG_WORDS * 4);
        cudaStreamCreateWithFlags(&sideStream, cudaStreamNonBlocking);
        cudaEventCreateWithFlags(&evFork, cudaEventDisableTiming);
        cudaEventCreateWithFlags(&evDone, cudaEventDisableTiming);
    }
    const int dynSmem = 2 * STG_WORDS * 4;

    const int convWPairs = LQ * HQ * HQ / 2;
    const int op1WOff    = convWPairs;
    const int op1WPairs  = (HQ / 2) * HQ / 2;
    const int op2WOff    = convWPairs + op1WPairs;
    const int op2WPairs  = (HQ / 4) * (HQ / 2) / 2;
    const int hPairs     = BQ * SQ * HQ / 2;
    const int htWords    = BQ * HQ * SQ / 2;

    // prologue (main = legacy stream)
    k_tabT<<<(128 * SQ / 2 + 255) / 256, 256>>>();
    k_initT<<<(htWords + 255) / 256, 256>>>(x, in_w, in_b);
    k_tabI<<<(SQ * 32 + 255) / 256, 256>>>();
    k_init<<<(hPairs + 255) / 256, 256>>>(x, in_w, in_b);
    k_cvt<<<(convWPairs + 255) / 256, 256>>>(conv_w, w0p, w1p, convWPairs);
    k_cvt<<<(op1WPairs + 255) / 256, 256>>>(op1_w, w0p + op1WOff, w1p + op1WOff, op1WPairs);
    k_cvt<<<(op2WPairs + 255) / 256, 256>>>(op2_w, w0p + op2WOff, w1p + op2WOff, op2WPairs);

    for (int l = 0; l < LQ; l++) {
        // fork: conv GEMM on side stream (needs g_A0/A1 + conv weights, both ready)
        cudaEventRecord(evFork, 0);
        cudaStreamWaitEvent(sideStream, evFork, 0);
        k_gemm_tc2<<<dim3(BQ * SQ / 128, HQ / 64), 256, dynSmem, sideStream>>>(
            a0p, a1p, w0p + (size_t)l * HQ * HQ / 2, w1p + (size_t)l * HQ * HQ / 2,
            yp, BQ * SQ, HQ, HQ, (const float*)0, 0,
            (unsigned int*)0, (unsigned int*)0);
        cudaEventRecord(evDone, sideStream);

        // main: fourier chain
        k_gemm_tc2<<<dim3(BQ * HQ / 128, 1, 4), 256, dynSmem>>>(
            ht0p, ht1p, t0p, t1p, xcp, BQ * HQ, 64, SQ,
            (const float*)0, 0, (unsigned int*)0, (unsigned int*)0);
        k_spec2<<<dim3(MQ, 2, 8), 256>>>(fw_r + (size_t)l * MQ * HQ * HQ,
                                         fw_i + (size_t)l * MQ * HQ * HQ);
        k_specred<<<dim3(HQ / 64, BQ), 256>>>();
        k_gemm_tc2<<<dim3(SQ / 128, BQ * HQ / 64), 256, dynSmem>>>(
            ti0p, ti1p, ys0p, ys1p, xfp, SQ, BQ * HQ, 64,
            (const float*)0, 0, (unsigned int*)0, (unsigned int*)0);

        // join: lnrow needs conv output g_y
        cudaStreamWaitEvent(0, evDone, 0);
        k_lnrow<<<BQ * SQ, 128>>>(conv_b + l * HQ, ln_g + l * HQ, ln_b + l * HQ);
        if (l < LQ - 1)
            k_hTt<<<dim3(SQ / 64, HQ / 32, BQ), 256>>>();
    }

    // output projection: H -> H/2 -> H/4 -> 1
    k_gemm_tc2<<<dim3(BQ * SQ / 128, (HQ / 2) / 64), 256, dynSmem>>>(
        a0p, a1p, w0p + op1WOff, w1p + op1WOff, yp, BQ * SQ, HQ / 2, HQ,
        op1_b, 3, o10p, o11p);
    k_gemm_tc2<<<dim3(BQ * SQ / 128, (HQ / 4) / 64), 256, dynSmem>>>(
        o10p, o11p, w0p + op2WOff, w1p + op2WOff, o2p, BQ * SQ, HQ / 4, HQ / 2,
        op2_b, 1, (unsigned int*)0, (unsigned int*)0);
    k_op3<<<BQ * SQ / 4, 128>>>(op3_w, op3_b, out);

    // cryptanalytic head
    k_mean1<<<dim3(BQ * 4, 16), 128>>>();
    k_mean2<<<(BQ * HQ + 255) / 256, 256>>>();
    k_head1<<<dim3(BQ, HQ / 128), 128>>>(h1_w, h1_b);
    k_head2<<<dim3(BQ, KBQ / 128), 128>>>(h2_w, h2_b, out);
}

// round 17
// speedup vs baseline: 2.4427x; 1.0402x over previous
#include <cuda_runtime.h>
#include <cstdint>
#include <stdint.h>
#include <math.h>

#define BQ 8
#define SQ 2048
#define HQ 512
#define LQ 8
#define MQ 32
#define KBQ 256

// ---------------- scratch (device globals, allocation-free) ----------------
__device__ float  g_h [BQ*SQ*HQ];           // hidden state [B,S,H]
__device__ float  g_y [BQ*SQ*HQ];           // conv GEMM out
__device__ float  g_xfC[SQ*BQ*HQ];          // inv DFT out [s][(b*H+c)]
__device__ float  g_Xc[4*BQ*HQ*64];         // fwd DFT K-partials: [part][(b*H+c)][64]
__device__ float  g_Psr[8*BQ*MQ*HQ];        // spec partials (real)
__device__ float  g_Psi[8*BQ*MQ*HQ];        // spec partials (imag)
__device__ float  g_o2[BQ*SQ*(HQ/4)];
__device__ float  g_gf[BQ*HQ];
__device__ float  g_k1[BQ*HQ];
__device__ float  g_mred[16*BQ*HQ];

// bf16 hi/lo packed operands (2 bf16 per word)
#define WTOT (LQ*HQ*HQ + (HQ/2)*HQ + (HQ/4)*(HQ/2))
__device__ unsigned int g_A0[BQ*SQ*HQ/2];   // h pairs along H
__device__ unsigned int g_A1[BQ*SQ*HQ/2];
__device__ unsigned int g_W0[WTOT/2];
__device__ unsigned int g_W1[WTOT/2];
__device__ unsigned int g_o10[BQ*SQ*(HQ/2)/2];
__device__ unsigned int g_o11[BQ*SQ*(HQ/2)/2];
__device__ unsigned int g_T0[128*SQ/2];     // fwd twiddle [128 rows][1024 words] (rows 0-63 used)
__device__ unsigned int g_T1[128*SQ/2];
__device__ unsigned int g_Ti0[SQ*32];       // inv twiddle [2048 rows][32 words]
__device__ unsigned int g_Ti1[SQ*32];
__device__ unsigned int g_hT0[BQ*HQ*SQ/2];  // h^T[(b*H+c)][s-pairs]
__device__ unsigned int g_hT1[BQ*HQ*SQ/2];
__device__ unsigned int g_Ys0[BQ*HQ*32];    // Y stacked [(b*H+c)][32 words = 64 k]
__device__ unsigned int g_Ys1[BQ*HQ*32];

__device__ __forceinline__ float gelu_exact(float x) {
    return 0.5f * x * (1.0f + erff(x * 0.70710678118654752440f));
}

// ---------------- bf16 helpers ----------------
__device__ __forceinline__ unsigned int bfpack(float x0, float x1) {
    unsigned int rr;
    asm("cvt.rn.bf16x2.f32 %0, %1, %2;" : "=r"(rr) : "f"(x1), "f"(x0));
    return rr;
}

__device__ __forceinline__ void bfsplit2(float x0, float x1,
                                         unsigned int& whi, unsigned int& wlo) {
    unsigned int hic = bfpack(x0, x1);
    float res0 = x0 - __uint_as_float(hic << 16);
    float res1 = x1 - __uint_as_float(hic & 0xffff0000u);
    whi = hic;
    wlo = bfpack(res0, res1);
}

__device__ __forceinline__ void ldsm4(unsigned int& ra, unsigned int& rb,
                                      unsigned int& rc, unsigned int& rd,
                                      unsigned int addr) {
    asm volatile("ldmatrix.sync.aligned.m8n8.x4.shared.b16 {%0,%1,%2,%3}, [%4];"
                 : "=r"(ra), "=r"(rb), "=r"(rc), "=r"(rd) : "r"(addr));
}

__device__ __forceinline__ void mma_bf16(float* dacc, const unsigned int* amat,
                                         const unsigned int* bmat) {
    asm volatile(
        "mma.sync.aligned.m16n8k16.row.col.f32.bf16.bf16.f32 "
        "{%0,%1,%2,%3}, {%4,%5,%6,%7}, {%8,%9}, {%0,%1,%2,%3};"
        : "+f"(dacc[0]), "+f"(dacc[1]), "+f"(dacc[2]), "+f"(dacc[3])
        : "r"(amat[0]), "r"(amat[1]), "r"(amat[2]), "r"(amat[3]),
          "r"(bmat[0]), "r"(bmat[1]));
}

#define CPASYNC16(dstaddr, srcptr) \
    asm volatile("cp.async.cg.shared.global [%0], [%1], 16;" \
                 :: "r"(dstaddr), "l"(srcptr))
#define CPCOMMIT() asm volatile("cp.async.commit_group;")
#define CPWAIT(nn) asm volatile("cp.async.wait_group %0;" :: "n"(nn))

// ---------------- fwd twiddle matrix T ----------------
__global__ void k_tabT() {
    int i = blockIdx.x * 256 + threadIdx.x;
    if (i < 128 * SQ / 2) {
        int sp  = i & (SQ / 2 - 1);
        int row = i >> 10;
        float v0 = 0.f, v1 = 0.f;
        if (row < 32) {
            float a0 = (float)(row * (2 * sp))     * (1.0f / 1024.0f);
            float a1 = (float)(row * (2 * sp + 1)) * (1.0f / 1024.0f);
            v0 = cospif(a0); v1 = cospif(a1);
        } else if (row < 64) {
            int m = row - 32;
            float a0 = (float)(m * (2 * sp))     * (1.0f / 1024.0f);
            float a1 = (float)(m * (2 * sp + 1)) * (1.0f / 1024.0f);
            v0 = -sinpif(a0); v1 = -sinpif(a1);
        }
        bfsplit2(v0, v1, g_T0[i], g_T1[i]);
    }
}

// ---------------- inverse twiddle matrix Tinv ----------------
__global__ void k_tabI() {
    int i = blockIdx.x * 256 + threadIdx.x;
    if (i < SQ * 32) {
        int kw = i & 31;
        int s  = i >> 5;
        int k0 = 2 * kw, k1 = 2 * kw + 1;
        float v0, v1;
        if (k0 < 32) {
            float c0 = (k0 == 0 ? 1.0f : 2.0f) / (float)SQ;
            float c1 = 2.0f / (float)SQ;
            v0 = c0 * cospif((float)(k0 * s) * (1.0f / 1024.0f));
            v1 = c1 * cospif((float)(k1 * s) * (1.0f / 1024.0f));
        } else {
            int m0 = k0 - 32, m1 = k1 - 32;
            float c0 = (m0 == 0 ? 1.0f : 2.0f) / (float)SQ;
            float c1 = 2.0f / (float)SQ;
            v0 = -c0 * sinpif((float)(m0 * s) * (1.0f / 1024.0f));
            v1 = -c1 * sinpif((float)(m1 * s) * (1.0f / 1024.0f));
        }
        bfsplit2(v0, v1, g_Ti0[i], g_Ti1[i]);
    }
}

// ---------------- h^T init ----------------
__global__ void k_initT(const float* __restrict__ x, const float* __restrict__ in_w,
                        const float* __restrict__ in_b) {
    int i = blockIdx.x * 256 + threadIdx.x;
    if (i < BQ * HQ * SQ / 2) {
        int sp = i & (SQ / 2 - 1);
        int bc = i >> 10;
        int c  = bc & (HQ - 1);
        int b  = bc >> 9;
        float wv = in_w[c], bv = in_b[c];
        float v0 = x[b * SQ + 2 * sp] * wv + bv;
        float v1 = x[b * SQ + 2 * sp + 1] * wv + bv;
        bfsplit2(v0, v1, g_hT0[i], g_hT1[i]);
    }
}

// ---------------- input projection ----------------
__global__ void k_init(const float* __restrict__ x, const float* __restrict__ in_w,
                       const float* __restrict__ in_b) {
    int i = blockIdx.x * 256 + threadIdx.x;
    if (i < BQ * SQ * HQ / 2) {
        int e0 = 2 * i;
        int c0 = e0 & (HQ - 1);
        int bs = e0 >> 9;
        float xv = x[bs];
        float v0 = xv * in_w[c0] + in_b[c0];
        float v1 = xv * in_w[c0 + 1] + in_b[c0 + 1];
        g_h[e0] = v0;
        g_h[e0 + 1] = v1;
        bfsplit2(v0, v1, g_A0[i], g_A1[i]);
    }
}

// ---------------- fp32 -> bf16 hi/lo (weights) ----------------
__global__ void k_cvt(const float* __restrict__ src, unsigned int* __restrict__ dsthi,
                      unsigned int* __restrict__ dstlo, int npairs) {
    int i = blockIdx.x * 256 + threadIdx.x;
    if (i < npairs) {
        bfsplit2(src[2 * i], src[2 * i + 1], dsthi[i], dstlo[i]);
    }
}

// ---------------- per-mode complex GEMM, 8-way h-split ----------------
// grid (MQ, 2, 8), block 256, forced 4 CTAs/SM for load-latency coverage
__global__ void __launch_bounds__(256, 4)
k_spec2(const float* __restrict__ Wr, const float* __restrict__ Wi) {
    int m = blockIdx.x, tid = threadIdx.x;
    int k = blockIdx.y * 256 + tid;
    int hpart = blockIdx.z;
    int h0 = hpart * 64;
    __shared__ float sXr[BQ][64];
    __shared__ float sXi[BQ][64];
    for (int i = tid; i < BQ * 64; i += 256) {
        int b = i >> 6, hh = i & 63;
        size_t base = (size_t)(b * HQ + h0 + hh) * 64;
        float xrS = 0.f, xiS = 0.f;
#pragma unroll
        for (int part = 0; part < 4; part++) {
            xrS += g_Xc[(size_t)part * (BQ * HQ * 64) + base + m];
            xiS += g_Xc[(size_t)part * (BQ * HQ * 64) + base + 32 + m];
        }
        sXr[b][hh] = xrS;
        sXi[b][hh] = xiS;
    }
    __syncthreads();
    float yr[BQ], yi[BQ];
#pragma unroll
    for (int b = 0; b < BQ; b++) { yr[b] = 0.f; yi[b] = 0.f; }
#pragma unroll 4
    for (int h = 0; h < 64; h++) {
        float wr = Wr[(size_t)(m * HQ + h0 + h) * HQ + k];
        float wi = Wi[(size_t)(m * HQ + h0 + h) * HQ + k];
#pragma unroll
        for (int b = 0; b < BQ; b++) {
            float xr = sXr[b][h], xi = sXi[b][h];
            yr[b] = fmaf(xr, wr, fmaf(-xi, wi, yr[b]));
            yi[b] = fmaf(xr, wi, fmaf( xi, wr, yi[b]));
        }
    }
#pragma unroll
    for (int b = 0; b < BQ; b++) {
        size_t o = ((size_t)(hpart * BQ + b) * MQ + m) * HQ + k;
        g_Psr[o] = yr[b];
        g_Psi[o] = yi[b];
    }
}

// ---------------- reduce 8 partials + pack to bf16 Ystack ----------------
__global__ void k_specred() {
    __shared__ float ySr[MQ][64];
    __shared__ float ySi[MQ][64];
    int c0 = blockIdx.x * 64;
    int b  = blockIdx.y;
    int tid = threadIdx.x;
    for (int idx = tid; idx < MQ * 64; idx += 256) {
        int c = idx & 63, m = idx >> 6;
        float sr = 0.f, si = 0.f;
#pragma unroll
        for (int part = 0; part < 8; part++) {
            size_t o = ((size_t)(part * BQ + b) * MQ + m) * HQ + c0 + c;
            sr += g_Psr[o];
            si += g_Psi[o];
        }
        ySr[m][c] = sr;
        ySi[m][c] = si;
    }
    __syncthreads();
    for (int idx = tid; idx < 64 * 32; idx += 256) {
        int kw = idx & 31, c = idx >> 5;
        int k0 = 2 * kw, k1 = 2 * kw + 1;
        float v0 = (k0 < 32) ? ySr[k0][c] : ySi[k0 - 32][c];
        float v1 = (k1 < 32) ? ySr[k1][c] : ySi[k1 - 32][c];
        unsigned int w0v, w1v;
        bfsplit2(v0, v1, w0v, w1v);
        size_t o = (size_t)(b * HQ + c0 + c) * 32 + kw;
        g_Ys0[o] = w0v;
        g_Ys1[o] = w1v;
    }
}

// ---------------- LN row kernel ----------------
__global__ void k_lnrow(const float* __restrict__ cb, const float* __restrict__ gg,
                        const float* __restrict__ bb) {
    int row = blockIdx.x, tid = threadIdx.x;
    int b = row >> 11, s = row & (SQ - 1);
    int j0 = tid * 4;
    float v[4], s1 = 0.f, s2 = 0.f;
#pragma unroll
    for (int i = 0; i < 4; i++) {
        int j = j0 + i;
        float t = g_y[(size_t)row * HQ + j] +
                  g_xfC[(size_t)s * (BQ * HQ) + b * HQ + j] + cb[j];
        v[i] = t; s1 += t; s2 += t * t;
    }
#pragma unroll
    for (int o = 16; o; o >>= 1) {
        s1 += __shfl_xor_sync(0xffffffffu, s1, o);
        s2 += __shfl_xor_sync(0xffffffffu, s2, o);
    }
    __shared__ float red[64];
    int w = tid >> 5;
    if ((tid & 31) == 0) { red[w] = s1; red[32 + w] = s2; }
    __syncthreads();
    float ts  = red[0] + red[1] + red[2] + red[3];
    float ts2 = red[32] + red[33] + red[34] + red[35];
    float mu  = ts * (1.f / HQ);
    float var = ts2 * (1.f / HQ) - mu * mu;
    float rinv = rsqrtf(var + 1e-5f);
    float hv[4];
#pragma unroll
    for (int i = 0; i < 4; i++) {
        int j = j0 + i;
        size_t idx = (size_t)row * HQ + j;
        hv[i] = (v[i] - mu) * rinv * gg[j] + bb[j] + g_h[idx];
        g_h[idx] = hv[i];
    }
    size_t wbase = (size_t)row * (HQ / 2) + tid * 2;
    bfsplit2(hv[0], hv[1], g_A0[wbase], g_A1[wbase]);
    bfsplit2(hv[2], hv[3], g_A0[wbase + 1], g_A1[wbase + 1]);
}

// ---------------- h -> hT transpose ----------------
__global__ void k_hTt() {
    __shared__ float tile[64][33];
    int s0 = blockIdx.x * 64;
    int c0 = blockIdx.y * 32;
    int b  = blockIdx.z;
    int tid = threadIdx.x;
    for (int i = tid; i < 64 * 32; i += 256) {
        int si = i >> 5, ci = i & 31;
        tile[si][ci] = g_h[(size_t)(b * SQ + s0 + si) * HQ + c0 + ci];
    }
    __syncthreads();
    for (int i = tid; i < 32 * 32; i += 256) {
        int ci = i >> 5, spi = i & 31;
        unsigned int w0v, w1v;
        bfsplit2(tile[2 * spi][ci], tile[2 * spi + 1][ci], w0v, w1v);
        size_t o = ((size_t)(b * HQ + c0 + ci) << 10) + (size_t)(s0 >> 1) + spi;
        g_hT0[o] = w0v;
        g_hT1[o] = w1v;
    }
}

// ============ 3xBF16 tensor-core GEMM (hi/lo compensated, gridDim.z K-split) ============
#define STG_WORDS 12288

__device__ __forceinline__ void issue_slab(
    unsigned int smemBase, int stageSel,
    const unsigned int* __restrict__ Amat0, const unsigned int* __restrict__ Amat1,
    const unsigned int* __restrict__ Bmat0, const unsigned int* __restrict__ Bmat1,
    int rowBase, int colBase, int Kw, int kw, int tid)
{
#pragma unroll
    for (int it = 0; it < 4; it++) {
        int idx = tid + it * 256;
        int row = idx >> 3, chk = idx & 7;
        unsigned int woff = (unsigned int)(stageSel * STG_WORDS + row * 32 +
                                           ((chk ^ (row & 7)) << 2));
        size_t gsrc = (size_t)(rowBase + row) * Kw + kw + chk * 4;
        CPASYNC16(smemBase + woff * 4, Amat0 + gsrc);
        CPASYNC16(smemBase + (woff + 4096) * 4, Amat1 + gsrc);
    }
#pragma unroll
    for (int it = 0; it < 2; it++) {
        int idx = tid + it * 256;
        int row = idx >> 3, chk = idx & 7;
        unsigned int woff = (unsigned int)(stageSel * STG_WORDS + 8192 + row * 32 +
                                           ((chk ^ (row & 7)) << 2));
        size_t gsrc = (size_t)(colBase + row) * Kw + kw + chk * 4;
        CPASYNC16(smemBase + woff * 4, Bmat0 + gsrc);
        CPASYNC16(smemBase + (woff + 2048) * 4, Bmat1 + gsrc);
    }
}

__global__ void __launch_bounds__(256, 2)
k_gemm_tc2(const unsigned int* __restrict__ Amat0, const unsigned int* __restrict__ Amat1,
           const unsigned int* __restrict__ Bmat0, const unsigned int* __restrict__ Bmat1,
           float* __restrict__ Cmat, int Mdim, int Ndim, int Kdim,
           const float* __restrict__ biasPtr, int gmode,
           unsigned int* __restrict__ Cout0, unsigned int* __restrict__ Cout1) {
    extern __shared__ unsigned int shMem[];
    const int tid  = threadIdx.x;
    const int lane = tid & 31;
    const int warpIdx = tid >> 5;
    const int wmoff = (warpIdx & 3) * 32;
    const int wnoff = (warpIdx >> 2) * 32;
    const int rowBase = blockIdx.x * 128;
    const int colBase = blockIdx.y * 64;
    const int Kw = Kdim >> 1;
    const int KwSlice = Kw / gridDim.z;
    const int kwBase  = blockIdx.z * KwSlice;
    Cmat += (size_t)blockIdx.z * Mdim * Ndim;

    const unsigned int smemBase = (unsigned int)__cvta_generic_to_shared(shMem);

    const int arowA = wmoff + (lane & 15);
    const int achA  = lane >> 4;
    const int browB = wnoff + ((lane >> 4) << 3) + (lane & 7);
    const int bchB  = (lane >> 3) & 1;

    float acc[2][4][4];
#pragma unroll
    for (int fi = 0; fi < 2; fi++)
#pragma unroll
        for (int ji = 0; ji < 4; ji++)
#pragma unroll
            for (int ci = 0; ci < 4; ci++) acc[fi][ji][ci] = 0.0f;

    const int nSlab = KwSlice >> 5;
    issue_slab(smemBase, 0, Amat0, Amat1, Bmat0, Bmat1, rowBase, colBase, Kw, kwBase, tid);
    CPCOMMIT();

    for (int is = 0; is < nSlab; is++) {
        const int stagec = is & 1;
        if (is + 1 < nSlab) {
            issue_slab(smemBase, (is + 1) & 1, Amat0, Amat1, Bmat0, Bmat1,
                       rowBase, colBase, Kw, kwBase + ((is + 1) << 5), tid);
            CPCOMMIT();
            CPWAIT(1);
        } else {
            CPWAIT(0);
        }
        __syncthreads();

        const unsigned int stW = (unsigned int)(stagec * STG_WORDS);
#pragma unroll
        for (int gi = 0; gi < 4; gi++) {
            unsigned int fragA0[2][4];
            unsigned int fragA1[2][4];
            unsigned int fragB0[4][2];
            unsigned int fragB1[4][2];
#pragma unroll
            for (int fi = 0; fi < 2; fi++) {
                int rr = arowA + fi * 16;
                int chq = 2 * gi + achA;
                unsigned int byoff = (stW + rr * 32 + ((chq ^ (rr & 7)) << 2)) << 2;
                ldsm4(fragA0[fi][0], fragA0[fi][1], fragA0[fi][2], fragA0[fi][3],
                      smemBase + byoff);
                ldsm4(fragA1[fi][0], fragA1[fi][1], fragA1[fi][2], fragA1[fi][3],
                      smemBase + byoff + 4096 * 4);
            }
#pragma unroll
            for (int pj = 0; pj < 2; pj++) {
                int rr = browB + pj * 16;
                int chq = 2 * gi + bchB;
                unsigned int byoff = (stW + 8192 + rr * 32 + ((chq ^ (rr & 7)) << 2)) << 2;
                unsigned int tqa[4];
                ldsm4(tqa[0], tqa[1], tqa[2], tqa[3], smemBase + byoff);
                fragB0[2 * pj + 0][0] = tqa[0];
                fragB0[2 * pj + 0][1] = tqa[1];
                fragB0[2 * pj + 1][0] = tqa[2];
                fragB0[2 * pj + 1][1] = tqa[3];
                unsigned int tqb[4];
                ldsm4(tqb[0], tqb[1], tqb[2], tqb[3], smemBase + byoff + 2048 * 4);
                fragB1[2 * pj + 0][0] = tqb[0];
                fragB1[2 * pj + 0][1] = tqb[1];
                fragB1[2 * pj + 1][0] = tqb[2];
                fragB1[2 * pj + 1][1] = tqb[3];
            }
#pragma unroll
            for (int fi = 0; fi < 2; fi++) {
#pragma unroll
                for (int ji = 0; ji < 4; ji++) {
                    mma_bf16(acc[fi][ji], fragA0[fi], fragB0[ji]);
                    mma_bf16(acc[fi][ji], fragA1[fi], fragB0[ji]);
                    mma_bf16(acc[fi][ji], fragA0[fi], fragB1[ji]);
                }
            }
        }
        __syncthreads();
    }

    const int Ndw = Ndim >> 1;
#pragma unroll
    for (int fi = 0; fi < 2; fi++) {
#pragma unroll
        for (int ji = 0; ji < 4; ji++) {
            int orow = rowBase + wmoff + fi * 16 + (lane >> 2);
            int ocol = colBase + wnoff + ji * 8 + (lane & 3) * 2;
            float outA = acc[fi][ji][0];
            float outB = acc[fi][ji][1];
            float outC = acc[fi][ji][2];
            float outD = acc[fi][ji][3];
            if (gmode != 0) {
                float biasLo = biasPtr[ocol];
                float biasHi = biasPtr[ocol + 1];
                outA = gelu_exact(outA + biasLo);
                outB = gelu_exact(outB + biasHi);
                outC = gelu_exact(outC + biasLo);
                outD = gelu_exact(outD + biasHi);
            }
            if (gmode == 3) {
                size_t widx0 = (size_t)orow * Ndw + (ocol >> 1);
                size_t widx1 = (size_t)(orow + 8) * Ndw + (ocol >> 1);
                bfsplit2(outA, outB, Cout0[widx0], Cout1[widx0]);
                bfsplit2(outC, outD, Cout0[widx1], Cout1[widx1]);
            } else {
                *(float2*)&Cmat[(size_t)orow * Ndim + ocol] = make_float2(outA, outB);
                *(float2*)&Cmat[(size_t)(orow + 8) * Ndim + ocol] = make_float2(outC, outD);
            }
        }
    }
}

// ---------------- final projection to scalar ----------------
__global__ void k_op3(const float* __restrict__ w, const float* __restrict__ b3,
                      float* __restrict__ out) {
    int tid = threadIdx.x;
    int row = blockIdx.x * 4 + (tid >> 5);
    int lane = tid & 31;
    float s = 0.f;
#pragma unroll
    for (int i = 0; i < 4; i++) {
        int j = lane + i * 32;
        s += g_o2[(size_t)row * 128 + j] * w[j];
    }
#pragma unroll
    for (int o = 16; o; o >>= 1) s += __shfl_xor_sync(0xffffffffu, s, o);
    if (lane == 0) out[row] = s + b3[0];
}

// ---------------- mean over s (two-stage) ----------------
__global__ void k_mean1() {
    int part = blockIdx.y;
    int b = blockIdx.x >> 2;
    int c = (blockIdx.x & 3) * 128 + threadIdx.x;
    float s = 0.f;
    int sbeg = part * (SQ / 16);
    for (int ss = sbeg; ss < sbeg + (SQ / 16); ss++)
        s += g_h[(size_t)(b * SQ + ss) * HQ + c];
    g_mred[part * (BQ * HQ) + b * HQ + c] = s;
}

__global__ void k_mean2() {
    int i = blockIdx.x * 256 + threadIdx.x;
    if (i < BQ * HQ) {
        float s = 0.f;
#pragma unroll
        for (int part = 0; part < 16; part++) s += g_mred[part * (BQ * HQ) + i];
        g_gf[i] = s * (1.f / SQ);
    }
}

// ---------------- head kernels ----------------
__global__ void k_head1(const float* __restrict__ w, const float* __restrict__ bias) {
    int b = blockIdx.x, tid = threadIdx.x;
    int j = blockIdx.y * 128 + tid;
    __shared__ float sg[HQ];
    for (int i = tid; i < HQ; i += 128) sg[i] = g_gf[b * HQ + i];
    __syncthreads();
    const float4* w4 = (const float4*)(w + (size_t)j * HQ);
    float acc = 0.f;
    for (int c = 0; c < HQ / 4; c++) {
        float4 wv = w4[c];
        float4 gv = *(const float4*)&sg[c * 4];
        acc = fmaf(wv.x, gv.x, acc); acc = fmaf(wv.y, gv.y, acc);
        acc = fmaf(wv.z, gv.z, acc); acc = fmaf(wv.w, gv.w, acc);
    }
    g_k1[b * HQ + j] = gelu_exact(acc + bias[j]);
}

__global__ void k_head2(const float* __restrict__ w, const float* __restrict__ bias,
                        float* __restrict__ out) {
    int b = blockIdx.x, tid = threadIdx.x;
    int j = blockIdx.y * 128 + tid;
    __shared__ float sk[HQ];
    for (int i = tid; i < HQ; i += 128) sk[i] = g_k1[b * HQ + i];
    __syncthreads();
    const float4* w4 = (const float4*)(w + (size_t)j * HQ);
    float acc = 0.f;
    for (int c = 0; c < HQ / 4; c++) {
        float4 wv = w4[c];
        float4 kv = *(const float4*)&sk[c * 4];
        acc = fmaf(wv.x, kv.x, acc); acc = fmaf(wv.y, kv.y, acc);
        acc = fmaf(wv.z, kv.z, acc); acc = fmaf(wv.w, kv.w, acc);
    }
    float t = acc + bias[j];
    out[BQ * SQ + b * KBQ + j] = 1.f / (1.f + expf(-t));
}

// ---------------- launch ----------------
extern "C" void kernel_launch(void* const* d_in, const int* in_sizes, int n_in,
                              void* d_out, int out_size) {
    const float* x      = (const float*)d_in[0];
    const float* in_w   = (const float*)d_in[1];
    const float* in_b   = (const float*)d_in[2];
    const float* fw_r   = (const float*)d_in[3];
    const float* fw_i   = (const float*)d_in[4];
    const float* conv_w = (const float*)d_in[5];
    const float* conv_b = (const float*)d_in[6];
    const float* ln_g   = (const float*)d_in[7];
    const float* ln_b   = (const float*)d_in[8];
    const float* op1_w  = (const float*)d_in[9];
    const float* op1_b  = (const float*)d_in[10];
    const float* op2_w  = (const float*)d_in[11];
    const float* op2_b  = (const float*)d_in[12];
    const float* op3_w  = (const float*)d_in[13];
    const float* op3_b  = (const float*)d_in[14];
    const float* h1_w   = (const float*)d_in[15];
    const float* h1_b   = (const float*)d_in[16];
    const float* h2_w   = (const float*)d_in[17];
    const float* h2_b   = (const float*)d_in[18];
    float* out = (float*)d_out;

    float *yp, *o2p, *xcp, *xfp;
    unsigned int *a0p, *a1p, *w0p, *w1p, *o10p, *o11p;
    unsigned int *t0p, *t1p, *ti0p, *ti1p, *ht0p, *ht1p, *ys0p, *ys1p;
    cudaGetSymbolAddress((void**)&yp,  g_y);
    cudaGetSymbolAddress((void**)&o2p, g_o2);
    cudaGetSymbolAddress((void**)&xcp, g_Xc);
    cudaGetSymbolAddress((void**)&xfp, g_xfC);
    cudaGetSymbolAddress((void**)&a0p, g_A0);
    cudaGetSymbolAddress((void**)&a1p, g_A1);
    cudaGetSymbolAddress((void**)&w0p, g_W0);
    cudaGetSymbolAddress((void**)&w1p, g_W1);
    cudaGetSymbolAddress((void**)&o10p, g_o10);
    cudaGetSymbolAddress((void**)&o11p, g_o11);
    cudaGetSymbolAddress((void**)&t0p, g_T0);
    cudaGetSymbolAddress((void**)&t1p, g_T1);
    cudaGetSymbolAddress((void**)&ti0p, g_Ti0);
    cudaGetSymbolAddress((void**)&ti1p, g_Ti1);
    cudaGetSymbolAddress((void**)&ht0p, g_hT0);
    cudaGetSymbolAddress((void**)&ht1p, g_hT1);
    cudaGetSymbolAddress((void**)&ys0p, g_Ys0);
    cudaGetSymbolAddress((void**)&ys1p, g_Ys1);

    // one-time setup on first (non-captured) call
    static cudaStream_t sideStream = 0;
    static cudaEvent_t evFork = 0, evDone = 0, evTail = 0;
    if (!sideStream) {
        cudaFuncSetAttribute(k_gemm_tc2, cudaFuncAttributeMaxDynamicSharedMemorySize,
                             2 * STG_WORDS * 4);
        cudaStreamCreateWithFlags(&sideStream, cudaStreamNonBlocking);
        cudaEventCreateWithFlags(&evFork, cudaEventDisableTiming);
        cudaEventCreateWithFlags(&evDone, cudaEventDisableTiming);
        cudaEventCreateWithFlags(&evTail, cudaEventDisableTiming);
    }
    const int dynSmem = 2 * STG_WORDS * 4;

    const int convWPairs = LQ * HQ * HQ / 2;
    const int op1WOff    = convWPairs;
    const int op1WPairs  = (HQ / 2) * HQ / 2;
    const int op2WOff    = convWPairs + op1WPairs;
    const int op2WPairs  = (HQ / 4) * (HQ / 2) / 2;
    const int hPairs     = BQ * SQ * HQ / 2;
    const int htWords    = BQ * HQ * SQ / 2;

    // prologue (main = legacy stream)
    k_tabT<<<(128 * SQ / 2 + 255) / 256, 256>>>();
    k_initT<<<(htWords + 255) / 256, 256>>>(x, in_w, in_b);
    k_tabI<<<(SQ * 32 + 255) / 256, 256>>>();
    k_init<<<(hPairs + 255) / 256, 256>>>(x, in_w, in_b);
    k_cvt<<<(convWPairs + 255) / 256, 256>>>(conv_w, w0p, w1p, convWPairs);
    k_cvt<<<(op1WPairs + 255) / 256, 256>>>(op1_w, w0p + op1WOff, w1p + op1WOff, op1WPairs);
    k_cvt<<<(op2WPairs + 255) / 256, 256>>>(op2_w, w0p + op2WOff, w1p + op2WOff, op2WPairs);

    for (int l = 0; l < LQ; l++) {
        // fork: conv GEMM on side stream
        cudaEventRecord(evFork, 0);
        cudaStreamWaitEvent(sideStream, evFork, 0);
        k_gemm_tc2<<<dim3(BQ * SQ / 128, HQ / 64), 256, dynSmem, sideStream>>>(
            a0p, a1p, w0p + (size_t)l * HQ * HQ / 2, w1p + (size_t)l * HQ * HQ / 2,
            yp, BQ * SQ, HQ, HQ, (const float*)0, 0,
            (unsigned int*)0, (unsigned int*)0);
        cudaEventRecord(evDone, sideStream);

        // main: fourier chain
        k_gemm_tc2<<<dim3(BQ * HQ / 128, 1, 4), 256, dynSmem>>>(
            ht0p, ht1p, t0p, t1p, xcp, BQ * HQ, 64, SQ,
            (const float*)0, 0, (unsigned int*)0, (unsigned int*)0);
        k_spec2<<<dim3(MQ, 2, 8), 256>>>(fw_r + (size_t)l * MQ * HQ * HQ,
                                         fw_i + (size_t)l * MQ * HQ * HQ);
        k_specred<<<dim3(HQ / 64, BQ), 256>>>();
        k_gemm_tc2<<<dim3(SQ / 128, BQ * HQ / 64), 256, dynSmem>>>(
            ti0p, ti1p, ys0p, ys1p, xfp, SQ, BQ * HQ, 64,
            (const float*)0, 0, (unsigned int*)0, (unsigned int*)0);

        // join: lnrow needs conv output g_y
        cudaStreamWaitEvent(0, evDone, 0);
        k_lnrow<<<BQ * SQ, 128>>>(conv_b + l * HQ, ln_g + l * HQ, ln_b + l * HQ);
        if (l < LQ - 1)
            k_hTt<<<dim3(SQ / 64, HQ / 32, BQ), 256>>>();
    }

    // tail fork: head chain (side) parallel with output projection (main)
    cudaEventRecord(evFork, 0);
    cudaStreamWaitEvent(sideStream, evFork, 0);
    k_mean1<<<dim3(BQ * 4, 16), 128, 0, sideStream>>>();
    k_mean2<<<(BQ * HQ + 255) / 256, 256, 0, sideStream>>>();
    k_head1<<<dim3(BQ, HQ / 128), 128, 0, sideStream>>>(h1_w, h1_b);
    k_head2<<<dim3(BQ, KBQ / 128), 128, 0, sideStream>>>(h2_w, h2_b, out);
    cudaEventRecord(evTail, sideStream);

    // main: output projection H -> H/2 -> H/4 -> 1
    k_gemm_tc2<<<dim3(BQ * SQ / 128, (HQ / 2) / 64), 256, dynSmem>>>(
        a0p, a1p, w0p + op1WOff, w1p + op1WOff, yp, BQ * SQ, HQ / 2, HQ,
        op1_b, 3, o10p, o11p);
    k_gemm_tc2<<<dim3(BQ * SQ / 128, (HQ / 4) / 64), 256, dynSmem>>>(
        o10p, o11p, w0p + op2WOff, w1p + op2WOff, o2p, BQ * SQ, HQ / 4, HQ / 2,
        op2_b, 1, (unsigned int*)0, (unsigned int*)0);
    k_op3<<<BQ * SQ / 4, 128>>>(op3_w, op3_b, out);

    // final join
    cudaStreamWaitEvent(0, evTail, 0);
}